// round 7
// baseline (speedup 1.0000x reference)
#include <cuda_runtime.h>
#include <cuda_bf16.h>
#include <math.h>
#include <stdint.h>

#define DIM   1024
#define NH    16
#define NKV   4
#define HD    64
#define WIN   512
#define BB    2
#define SS    2048
#define TT    (BB*SS)
#define QKVW  1536   // 1024 q | 256 k | 256 v per token
#define GK    1024   // K dim of every GEMM
#define LOG2E 1.4426950408889634f

// ---------------- scratch (no allocs allowed) ----------------
__device__ float g_xqkv[(size_t)TT * QKVW];          // fp32 qkv projections
__device__ __nv_bfloat16 g_ah[(size_t)TT * DIM];     // activation hi (x, then attn out)
__device__ __nv_bfloat16 g_al[(size_t)TT * DIM];     // activation lo
__device__ __nv_bfloat16 g_wh[(size_t)2560 * DIM];   // weights hi: wq|wk|wv|wo
__device__ __nv_bfloat16 g_wl[(size_t)2560 * DIM];
__device__ __nv_bfloat16 g_qh[(size_t)TT * DIM];     // per-head Q hi  [(b*NH+h)*SS+s][64]
__device__ __nv_bfloat16 g_ql[(size_t)TT * DIM];
__device__ __nv_bfloat16 g_kh[(size_t)TT * 256];     // per-kvhead K hi [(b*NKV+kv)*SS+s][64]
__device__ __nv_bfloat16 g_kl[(size_t)TT * 256];
__device__ __nv_bfloat16 g_vh[(size_t)TT * 256];
__device__ __nv_bfloat16 g_vl[(size_t)TT * 256];
#define WO_ROW 1536

// ---------------- small PTX helpers ----------------
__device__ __forceinline__ uint32_t smem_u32(const void* p) {
    uint32_t a;
    asm("{ .reg .u64 t; cvta.to.shared.u64 t, %1; cvt.u32.u64 %0, t; }" : "=r"(a) : "l"(p));
    return a;
}
__device__ __forceinline__ void cp16(uint32_t s, const void* g) {
    asm volatile("{ .reg .u64 gg; cvta.to.global.u64 gg, %1; cp.async.cg.shared.global [%0], [gg], 16; }"
                 :: "r"(s), "l"(g) : "memory");
}
__device__ __forceinline__ void cp_commit() { asm volatile("cp.async.commit_group;" ::: "memory"); }
template <int N>
__device__ __forceinline__ void cp_wait() { asm volatile("cp.async.wait_group %0;" :: "n"(N) : "memory"); }

__device__ __forceinline__ uint32_t packbf(float lo, float hi) {
    uint32_t r;
    asm("cvt.rn.bf16x2.f32 %0, %1, %2;" : "=r"(r) : "f"(hi), "f"(lo));
    return r;
}

#define MMA_BF16(c0,c1,c2,c3, a0,a1,a2,a3, b0,b1) \
    asm volatile("mma.sync.aligned.m16n8k16.row.col.f32.bf16.bf16.f32 " \
                 "{%0,%1,%2,%3}, {%4,%5,%6,%7}, {%8,%9}, {%0,%1,%2,%3};" \
                 : "+f"(c0), "+f"(c1), "+f"(c2), "+f"(c3) \
                 : "r"(a0), "r"(a1), "r"(a2), "r"(a3), "r"(b0), "r"(b1))

#define LDMX4(r0,r1,r2,r3, addr) \
    asm volatile("ldmatrix.sync.aligned.m8n8.x4.shared.b16 {%0,%1,%2,%3}, [%4];" \
                 : "=r"(r0), "=r"(r1), "=r"(r2), "=r"(r3) : "r"(addr))
#define LDMX4T(r0,r1,r2,r3, addr) \
    asm volatile("ldmatrix.sync.aligned.m8n8.x4.trans.shared.b16 {%0,%1,%2,%3}, [%4];" \
                 : "=r"(r0), "=r"(r1), "=r"(r2), "=r"(r3) : "r"(addr))

// ---------------- fp32 -> bf16 hi/lo split (x) ----------------
__global__ __launch_bounds__(256) void split_bf16(
    const float* __restrict__ in, __nv_bfloat16* __restrict__ hi,
    __nv_bfloat16* __restrict__ lo, int n4)
{
    int i = blockIdx.x * 256 + threadIdx.x;
    if (i >= n4) return;
    float4 v = ((const float4*)in)[i];
    float f[4] = {v.x, v.y, v.z, v.w};
    union { __nv_bfloat16 b[4]; uint2 u; } H, L;
#pragma unroll
    for (int k = 0; k < 4; k++) {
        __nv_bfloat16 h = __float2bfloat16(f[k]);
        H.b[k] = h;
        L.b[k] = __float2bfloat16(f[k] - __bfloat162float(h));
    }
    ((uint2*)hi)[i] = H.u;
    ((uint2*)lo)[i] = L.u;
}

// ---------------- all weights -> stacked bf16 hi/lo, one kernel ----------------
__global__ __launch_bounds__(256) void wsplit_all(
    const float* __restrict__ wq, const float* __restrict__ wk,
    const float* __restrict__ wv, const float* __restrict__ wo)
{
    int i = blockIdx.x * 256 + threadIdx.x;   // float4 index
    const float* src;
    int local;
    if (i < 262144)      { src = wq; local = i; }
    else if (i < 327680) { src = wk; local = i - 262144; }
    else if (i < 393216) { src = wv; local = i - 327680; }
    else                 { src = wo; local = i - 393216; }
    float4 v = ((const float4*)src)[local];
    float f[4] = {v.x, v.y, v.z, v.w};
    union { __nv_bfloat16 b[4]; uint2 u; } H, L;
#pragma unroll
    for (int k = 0; k < 4; k++) {
        __nv_bfloat16 h = __float2bfloat16(f[k]);
        H.b[k] = h;
        L.b[k] = __float2bfloat16(f[k] - __bfloat162float(h));
    }
    ((uint2*)g_wh)[i] = H.u;
    ((uint2*)g_wl)[i] = L.u;
}

// ---------------- HMMA split-bf16 GEMM: BK=64, 3-stage cp.async, pass-major MMAs ----------------
#define BKC 64
#define NCHG (GK / BKC)          // 16
#define SROWG 72                 // halves per row (64 data + 8 pad -> 144B)
#define TILEG (128 * SROWG)      // halves per tile
#define STAGEG (4 * TILEG)
#define GEMM_SMEM (3 * STAGEG * 2)   // 221184 bytes

__global__ __launch_bounds__(256, 1) void hmma_gemm(
    const __nv_bfloat16* __restrict__ ah, const __nv_bfloat16* __restrict__ al,
    const __nv_bfloat16* __restrict__ bh, const __nv_bfloat16* __restrict__ bl,
    float* __restrict__ C, int ldc, int coff)
{
    extern __shared__ char smraw[];
    const uint32_t smb = smem_u32(smraw);

    const int tid = threadIdx.x;
    const int wid = tid >> 5;
    const int lid = tid & 31;
    const int wm = wid & 1;
    const int wn = wid >> 1;
    const int m0 = blockIdx.y * 128;
    const int n0 = blockIdx.x * 128;

    const __nv_bfloat16* gbase[4];
    gbase[0] = ah + (size_t)m0 * GK;
    gbase[1] = al + (size_t)m0 * GK;
    gbase[2] = bh + (size_t)n0 * GK;
    gbase[3] = bl + (size_t)n0 * GK;

    auto load_stage = [&](int kc, int stg) {
        const uint32_t base = smb + (uint32_t)stg * (STAGEG * 2);
#pragma unroll
        for (int i = 0; i < 4; i++) {
            int id = tid + 256 * i;
            int row = id >> 3, seg = id & 7;
            uint32_t soff = (uint32_t)(row * SROWG + seg * 8) * 2;
#pragma unroll
            for (int t = 0; t < 4; t++) {
                const __nv_bfloat16* src = gbase[t] + (size_t)row * GK + kc + seg * 8;
                cp16(base + (uint32_t)t * (TILEG * 2) + soff, src);
            }
        }
        cp_commit();
    };

    float acc[4][4][4];
#pragma unroll
    for (int i = 0; i < 4; i++)
#pragma unroll
        for (int j = 0; j < 4; j++)
#pragma unroll
            for (int k = 0; k < 4; k++) acc[i][j][k] = 0.f;

    const uint32_t frag_off =
        (uint32_t)((((lid & 7) + ((lid >> 3) & 1) * 8) * SROWG + (lid >> 4) * 8) * 2);

    load_stage(0, 0);
    load_stage(BKC, 1);
    load_stage(2 * BKC, 2);

    for (int c = 0; c < NCHG; c++) {
        if (c <= NCHG - 3)      cp_wait<2>();
        else if (c == NCHG - 2) cp_wait<1>();
        else                    cp_wait<0>();
        __syncthreads();

        const uint32_t sbase = smb + (uint32_t)(c % 3) * (STAGEG * 2);

#pragma unroll
        for (int ks = 0; ks < 4; ks++) {
            // load ALL fragments for this k-step first
            uint32_t Ah[4][4], Al[4][4], Bh[2][4], Bl[2][4];
#pragma unroll
            for (int mf = 0; mf < 4; mf++) {
                uint32_t aaddr = sbase +
                    (uint32_t)(((wm * 64 + mf * 16) * SROWG + ks * 16) * 2) + frag_off;
                LDMX4(Ah[mf][0], Ah[mf][1], Ah[mf][2], Ah[mf][3], aaddr);
                LDMX4(Al[mf][0], Al[mf][1], Al[mf][2], Al[mf][3], aaddr + TILEG * 2);
            }
#pragma unroll
            for (int nfp = 0; nfp < 2; nfp++) {
                uint32_t baddr = sbase + 2u * (TILEG * 2) +
                    (uint32_t)(((wn * 32 + nfp * 16) * SROWG + ks * 16) * 2) + frag_off;
                LDMX4(Bh[nfp][0], Bh[nfp][1], Bh[nfp][2], Bh[nfp][3], baddr);
                LDMX4(Bl[nfp][0], Bl[nfp][1], Bl[nfp][2], Bl[nfp][3], baddr + TILEG * 2);
            }

            // pass 1: Ah*Bh  (each acc touched once per pass -> re-touch distance 16 MMAs)
#pragma unroll
            for (int nfp = 0; nfp < 2; nfp++)
#pragma unroll
                for (int mf = 0; mf < 4; mf++) {
                    MMA_BF16(acc[mf][2*nfp][0], acc[mf][2*nfp][1], acc[mf][2*nfp][2], acc[mf][2*nfp][3],
                             Ah[mf][0], Ah[mf][1], Ah[mf][2], Ah[mf][3], Bh[nfp][0], Bh[nfp][2]);
                    MMA_BF16(acc[mf][2*nfp+1][0], acc[mf][2*nfp+1][1], acc[mf][2*nfp+1][2], acc[mf][2*nfp+1][3],
                             Ah[mf][0], Ah[mf][1], Ah[mf][2], Ah[mf][3], Bh[nfp][1], Bh[nfp][3]);
                }
            // pass 2: Ah*Bl
#pragma unroll
            for (int nfp = 0; nfp < 2; nfp++)
#pragma unroll
                for (int mf = 0; mf < 4; mf++) {
                    MMA_BF16(acc[mf][2*nfp][0], acc[mf][2*nfp][1], acc[mf][2*nfp][2], acc[mf][2*nfp][3],
                             Ah[mf][0], Ah[mf][1], Ah[mf][2], Ah[mf][3], Bl[nfp][0], Bl[nfp][2]);
                    MMA_BF16(acc[mf][2*nfp+1][0], acc[mf][2*nfp+1][1], acc[mf][2*nfp+1][2], acc[mf][2*nfp+1][3],
                             Ah[mf][0], Ah[mf][1], Ah[mf][2], Ah[mf][3], Bl[nfp][1], Bl[nfp][3]);
                }
            // pass 3: Al*Bh
#pragma unroll
            for (int nfp = 0; nfp < 2; nfp++)
#pragma unroll
                for (int mf = 0; mf < 4; mf++) {
                    MMA_BF16(acc[mf][2*nfp][0], acc[mf][2*nfp][1], acc[mf][2*nfp][2], acc[mf][2*nfp][3],
                             Al[mf][0], Al[mf][1], Al[mf][2], Al[mf][3], Bh[nfp][0], Bh[nfp][2]);
                    MMA_BF16(acc[mf][2*nfp+1][0], acc[mf][2*nfp+1][1], acc[mf][2*nfp+1][2], acc[mf][2*nfp+1][3],
                             Al[mf][0], Al[mf][1], Al[mf][2], Al[mf][3], Bh[nfp][1], Bh[nfp][3]);
                }
        }

        __syncthreads();
        if (c + 3 < NCHG) load_stage((c + 3) * BKC, c % 3);
    }

    const int r2 = lid >> 2;
    const int c2 = (lid & 3) * 2;
#pragma unroll
    for (int mf = 0; mf < 4; mf++) {
        const int row = m0 + wm * 64 + mf * 16 + r2;
#pragma unroll
        for (int nf = 0; nf < 4; nf++) {
            float* cp0 = C + (size_t)row * ldc + coff + n0 + wn * 32 + nf * 8 + c2;
            *(float2*)cp0 = make_float2(acc[mf][nf][0], acc[mf][nf][1]);
            *(float2*)(cp0 + 8 * (size_t)ldc) = make_float2(acc[mf][nf][2], acc[mf][nf][3]);
        }
    }
}

// ---------------- fused q-rms + k-rms + v split ----------------
__global__ __launch_bounds__(256) void prep_qkv(
    const float* __restrict__ qw, const float* __restrict__ kw)
{
    const int t = blockIdx.x;
    const int b = t >> 11, s = t & (SS - 1);
    const float* row = g_xqkv + (size_t)t * QKVW;
    const int tid = threadIdx.x;

    float v[4];
    float ssq = 0.f;
#pragma unroll
    for (int i = 0; i < 4; i++) {
        v[i] = row[tid + 256 * i];
        ssq = fmaf(v[i], v[i], ssq);
    }
    float kvl = row[1024 + tid];
    float ssk = kvl * kvl;
    float vv = row[1280 + tid];

#pragma unroll
    for (int o = 16; o > 0; o >>= 1) {
        ssq += __shfl_xor_sync(0xffffffffu, ssq, o);
        ssk += __shfl_xor_sync(0xffffffffu, ssk, o);
    }

    __shared__ float redq[8], redk[8];
    __shared__ float sclq_s, sclk_s;
    if ((tid & 31) == 0) { redq[tid >> 5] = ssq; redk[tid >> 5] = ssk; }
    __syncthreads();
    if (tid == 0) {
        float tq = 0.f, tk = 0.f;
#pragma unroll
        for (int i = 0; i < 8; i++) { tq += redq[i]; tk += redk[i]; }
        sclq_s = rsqrtf(tq * (1.f / 1024.f) + 1e-6f) * (0.125f * LOG2E);
        sclk_s = rsqrtf(tk * (1.f / 256.f) + 1e-6f);
    }
    __syncthreads();
    const float sclq = sclq_s, sclk = sclk_s;

#pragma unroll
    for (int i = 0; i < 4; i++) {
        int idx = tid + 256 * i;
        float val = v[i] * sclq * qw[idx];
        int head = idx >> 6, d = idx & 63;
        size_t off = ((size_t)(b * NH + head) * SS + s) * 64 + d;
        __nv_bfloat16 h = __float2bfloat16(val);
        g_qh[off] = h;
        g_ql[off] = __float2bfloat16(val - __bfloat162float(h));
    }

    const int kv = tid >> 6, d = tid & 63;
    const size_t off = ((size_t)(b * NKV + kv) * SS + s) * 64 + d;
    float kn = kvl * sclk * kw[tid];
    __nv_bfloat16 kh = __float2bfloat16(kn);
    g_kh[off] = kh;
    g_kl[off] = __float2bfloat16(kn - __bfloat162float(kh));
    __nv_bfloat16 vh = __float2bfloat16(vv);
    g_vh[off] = vh;
    g_vl[off] = __float2bfloat16(vv - __bfloat162float(vh));
}

// ---------------- tensor-core attention (log2 domain, pass-grouped MMAs) ----------------
#define TILEB 9216                    // 64*144
#define ATT_SMEM (2 * 4 * TILEB)      // 73728

__global__ __launch_bounds__(256, 2) void attn_tc()
{
    extern __shared__ char asm_[];
    const uint32_t smb = smem_u32(asm_);

    const int tid = threadIdx.x;
    const int wid = tid >> 5;
    const int lid = tid & 31;
    const int qstart = blockIdx.x * 128;
    const int head = blockIdx.y;
    const int b = blockIdx.z;
    const int kvh = head >> 2;

    const int r = lid >> 2;
    const int c2 = (lid & 3) * 2;
    const int qpos0 = qstart + wid * 16 + r;
    const int wqmin = qstart + wid * 16;
    const int wqmax = wqmin + 15;
    const float slope = exp2f(-0.5f * (float)(head + 1)) * LOG2E;

    const __nv_bfloat16* qbh = g_qh + ((size_t)(b * NH + head) * SS + qstart + wid * 16) * 64;
    const __nv_bfloat16* qbl = g_ql + ((size_t)(b * NH + head) * SS + qstart + wid * 16) * 64;
    uint32_t Qh[4][4];
#pragma unroll
    for (int ks = 0; ks < 4; ks++) {
        Qh[ks][0] = *(const uint32_t*)(qbh + r * 64 + ks * 16 + c2);
        Qh[ks][1] = *(const uint32_t*)(qbh + (r + 8) * 64 + ks * 16 + c2);
        Qh[ks][2] = *(const uint32_t*)(qbh + r * 64 + ks * 16 + 8 + c2);
        Qh[ks][3] = *(const uint32_t*)(qbh + (r + 8) * 64 + ks * 16 + 8 + c2);
    }

    float O[8][4];
#pragma unroll
    for (int i = 0; i < 8; i++)
#pragma unroll
        for (int j = 0; j < 4; j++) O[i][j] = 0.f;
    float m0 = -INFINITY, m1 = -INFINITY, l0 = 0.f, l1 = 0.f;

    const int kc0 = (qstart >= WIN) ? qstart - WIN : 0;
    const int nch = (qstart + 128 - kc0) >> 6;

    const int key_ld = tid >> 2;
    const int seg = tid & 3;
    const __nv_bfloat16* src_base[4];
    {
        size_t kvb = ((size_t)(b * NKV + kvh) * SS) * 64;
        src_base[0] = g_kh + kvb; src_base[1] = g_kl + kvb;
        src_base[2] = g_vh + kvb; src_base[3] = g_vl + kvb;
    }
    auto load_chunk = [&](int kc, int stg) {
        uint32_t sb = smb + stg * 4 * TILEB + key_ld * 144 + seg * 16;
#pragma unroll
        for (int t = 0; t < 4; t++) {
            const __nv_bfloat16* src = src_base[t] + (size_t)(kc + key_ld) * 64 + seg * 8;
            cp16(sb + t * TILEB, src);
            cp16(sb + t * TILEB + 64, src + 32);
        }
        cp_commit();
    };

    load_chunk(kc0, 0);
    if (nch > 1) load_chunk(kc0 + 64, 1);

    const uint32_t lane_off = (uint32_t)(((lid >> 4) * 8 + (lid & 7)) * 144 + ((lid >> 3) & 1) * 16);

    for (int c = 0; c < nch; c++) {
        if (c < nch - 1) cp_wait<1>(); else cp_wait<0>();
        __syncthreads();

        const uint32_t sb = smb + (c & 1) * 4 * TILEB;
        const int kc = kc0 + c * 64;

        const bool active = (kc <= wqmax) && (kc + 63 >= wqmin - WIN);
        if (active) {

        // ---- scores: S = Qh*Kh + Qh*Kl + Ql*Kh ----
        float S[8][4];
#pragma unroll
        for (int i = 0; i < 8; i++)
#pragma unroll
            for (int j = 0; j < 4; j++) S[i][j] = 0.f;

#pragma unroll
        for (int ks = 0; ks < 4; ks++) {
            uint32_t Qlr[4];
            Qlr[0] = *(const uint32_t*)(qbl + r * 64 + ks * 16 + c2);
            Qlr[1] = *(const uint32_t*)(qbl + (r + 8) * 64 + ks * 16 + c2);
            Qlr[2] = *(const uint32_t*)(qbl + r * 64 + ks * 16 + 8 + c2);
            Qlr[3] = *(const uint32_t*)(qbl + (r + 8) * 64 + ks * 16 + 8 + c2);
#pragma unroll
            for (int g = 0; g < 2; g++) {      // nfp pairs {0,1}, {2,3}
                uint32_t kh[2][4], kl[2][4];
#pragma unroll
                for (int j = 0; j < 2; j++) {
                    int nfp = g * 2 + j;
                    LDMX4(kh[j][0], kh[j][1], kh[j][2], kh[j][3],
                          sb + nfp * 2304 + ks * 32 + lane_off);
                    LDMX4(kl[j][0], kl[j][1], kl[j][2], kl[j][3],
                          sb + TILEB + nfp * 2304 + ks * 32 + lane_off);
                }
                // pass 1: Qh*Kh
#pragma unroll
                for (int j = 0; j < 2; j++) {
                    int nf = (g * 2 + j) * 2;
                    MMA_BF16(S[nf][0], S[nf][1], S[nf][2], S[nf][3],
                             Qh[ks][0], Qh[ks][1], Qh[ks][2], Qh[ks][3], kh[j][0], kh[j][1]);
                    MMA_BF16(S[nf+1][0], S[nf+1][1], S[nf+1][2], S[nf+1][3],
                             Qh[ks][0], Qh[ks][1], Qh[ks][2], Qh[ks][3], kh[j][2], kh[j][3]);
                }
                // pass 2: Qh*Kl
#pragma unroll
                for (int j = 0; j < 2; j++) {
                    int nf = (g * 2 + j) * 2;
                    MMA_BF16(S[nf][0], S[nf][1], S[nf][2], S[nf][3],
                             Qh[ks][0], Qh[ks][1], Qh[ks][2], Qh[ks][3], kl[j][0], kl[j][1]);
                    MMA_BF16(S[nf+1][0], S[nf+1][1], S[nf+1][2], S[nf+1][3],
                             Qh[ks][0], Qh[ks][1], Qh[ks][2], Qh[ks][3], kl[j][2], kl[j][3]);
                }
                // pass 3: Ql*Kh
#pragma unroll
                for (int j = 0; j < 2; j++) {
                    int nf = (g * 2 + j) * 2;
                    MMA_BF16(S[nf][0], S[nf][1], S[nf][2], S[nf][3],
                             Qlr[0], Qlr[1], Qlr[2], Qlr[3], kh[j][0], kh[j][1]);
                    MMA_BF16(S[nf+1][0], S[nf+1][1], S[nf+1][2], S[nf+1][3],
                             Qlr[0], Qlr[1], Qlr[2], Qlr[3], kh[j][2], kh[j][3]);
                }
            }
        }

        // ---- bias + mask ----
#pragma unroll
        for (int nf = 0; nf < 8; nf++) {
            int rel0 = kc + nf * 8 + c2 - qpos0;
            int rel2 = rel0 - 8;
            S[nf][0] = (rel0     <= 0 && rel0     >= -WIN) ? fmaf(slope, (float)rel0,     S[nf][0]) : -INFINITY;
            S[nf][1] = (rel0 + 1 <= 0 && rel0 + 1 >= -WIN) ? fmaf(slope, (float)(rel0+1), S[nf][1]) : -INFINITY;
            S[nf][2] = (rel2     <= 0 && rel2     >= -WIN) ? fmaf(slope, (float)rel2,     S[nf][2]) : -INFINITY;
            S[nf][3] = (rel2 + 1 <= 0 && rel2 + 1 >= -WIN) ? fmaf(slope, (float)(rel2+1), S[nf][3]) : -INFINITY;
        }

        // ---- online softmax (exp2) ----
        float mx0 = -INFINITY, mx1 = -INFINITY;
#pragma unroll
        for (int nf = 0; nf < 8; nf++) {
            mx0 = fmaxf(mx0, fmaxf(S[nf][0], S[nf][1]));
            mx1 = fmaxf(mx1, fmaxf(S[nf][2], S[nf][3]));
        }
        mx0 = fmaxf(mx0, __shfl_xor_sync(0xffffffffu, mx0, 1));
        mx0 = fmaxf(mx0, __shfl_xor_sync(0xffffffffu, mx0, 2));
        mx1 = fmaxf(mx1, __shfl_xor_sync(0xffffffffu, mx1, 1));
        mx1 = fmaxf(mx1, __shfl_xor_sync(0xffffffffu, mx1, 2));

        float mn0 = fmaxf(fmaxf(m0, mx0), -1e30f);
        float mn1 = fmaxf(fmaxf(m1, mx1), -1e30f);
        float a0 = exp2f(m0 - mn0);
        float a1 = exp2f(m1 - mn1);
        m0 = mn0; m1 = mn1;
        l0 *= a0; l1 *= a1;
#pragma unroll
        for (int nf = 0; nf < 8; nf++) {
            O[nf][0] *= a0; O[nf][1] *= a0;
            O[nf][2] *= a1; O[nf][3] *= a1;
        }
#pragma unroll
        for (int nf = 0; nf < 8; nf++) {
            S[nf][0] = exp2f(S[nf][0] - m0);
            S[nf][1] = exp2f(S[nf][1] - m0);
            S[nf][2] = exp2f(S[nf][2] - m1);
            S[nf][3] = exp2f(S[nf][3] - m1);
            l0 += S[nf][0] + S[nf][1];
            l1 += S[nf][2] + S[nf][3];
        }

        // ---- PV: O += Ph*Vh + Ph*Vl + Pl*Vh ----
#pragma unroll
        for (int ks = 0; ks < 4; ks++) {
            float x00 = S[2*ks][0],   x01 = S[2*ks][1],   x02 = S[2*ks][2],   x03 = S[2*ks][3];
            float x10 = S[2*ks+1][0], x11 = S[2*ks+1][1], x12 = S[2*ks+1][2], x13 = S[2*ks+1][3];
            float h00 = __bfloat162float(__float2bfloat16(x00));
            float h01 = __bfloat162float(__float2bfloat16(x01));
            float h02 = __bfloat162float(__float2bfloat16(x02));
            float h03 = __bfloat162float(__float2bfloat16(x03));
            float h10 = __bfloat162float(__float2bfloat16(x10));
            float h11 = __bfloat162float(__float2bfloat16(x11));
            float h12 = __bfloat162float(__float2bfloat16(x12));
            float h13 = __bfloat162float(__float2bfloat16(x13));
            uint32_t ph0 = packbf(x00, x01), ph1 = packbf(x02, x03);
            uint32_t ph2 = packbf(x10, x11), ph3 = packbf(x12, x13);
            uint32_t pl0 = packbf(x00 - h00, x01 - h01), pl1 = packbf(x02 - h02, x03 - h03);
            uint32_t pl2 = packbf(x10 - h10, x11 - h11), pl3 = packbf(x12 - h12, x13 - h13);
#pragma unroll
            for (int g = 0; g < 2; g++) {
                uint32_t v[2][4], w[2][4];
#pragma unroll
                for (int j = 0; j < 2; j++) {
                    int nfp = g * 2 + j;
                    LDMX4T(v[j][0], v[j][1], v[j][2], v[j][3],
                           sb + 2 * TILEB + ks * 2304 + nfp * 32 + lane_off);
                    LDMX4T(w[j][0], w[j][1], w[j][2], w[j][3],
                           sb + 3 * TILEB + ks * 2304 + nfp * 32 + lane_off);
                }
                // pass 1: Ph*Vh
#pragma unroll
                for (int j = 0; j < 2; j++) {
                    int nf = (g * 2 + j) * 2;
                    MMA_BF16(O[nf][0], O[nf][1], O[nf][2], O[nf][3],
                             ph0, ph1, ph2, ph3, v[j][0], v[j][2]);
                    MMA_BF16(O[nf+1][0], O[nf+1][1], O[nf+1][2], O[nf+1][3],
                             ph0, ph1, ph2, ph3, v[j][1], v[j][3]);
                }
                // pass 2: Ph*Vl
#pragma unroll
                for (int j = 0; j < 2; j++) {
                    int nf = (g * 2 + j) * 2;
                    MMA_BF16(O[nf][0], O[nf][1], O[nf][2], O[nf][3],
                             ph0, ph1, ph2, ph3, w[j][0], w[j][2]);
                    MMA_BF16(O[nf+1][0], O[nf+1][1], O[nf+1][2], O[nf+1][3],
                             ph0, ph1, ph2, ph3, w[j][1], w[j][3]);
                }
                // pass 3: Pl*Vh
#pragma unroll
                for (int j = 0; j < 2; j++) {
                    int nf = (g * 2 + j) * 2;
                    MMA_BF16(O[nf][0], O[nf][1], O[nf][2], O[nf][3],
                             pl0, pl1, pl2, pl3, v[j][0], v[j][2]);
                    MMA_BF16(O[nf+1][0], O[nf+1][1], O[nf+1][2], O[nf+1][3],
                             pl0, pl1, pl2, pl3, v[j][1], v[j][3]);
                }
            }
        }

        }  // active

        __syncthreads();
        if (c + 2 < nch) load_chunk(kc0 + (c + 2) * 64, c & 1);
    }

    // ---- epilogue ----
    l0 += __shfl_xor_sync(0xffffffffu, l0, 1);
    l0 += __shfl_xor_sync(0xffffffffu, l0, 2);
    l1 += __shfl_xor_sync(0xffffffffu, l1, 1);
    l1 += __shfl_xor_sync(0xffffffffu, l1, 2);
    float inv0 = 1.f / l0, inv1 = 1.f / l1;

    size_t out0 = ((size_t)(b * SS + qpos0) * DIM) + head * 64;
    size_t out1 = out0 + (size_t)8 * DIM;
#pragma unroll
    for (int nf = 0; nf < 8; nf++) {
        float y0 = O[nf][0] * inv0, y1 = O[nf][1] * inv0;
        float y2 = O[nf][2] * inv1, y3 = O[nf][3] * inv1;
        int col = nf * 8 + c2;
        float h0 = __bfloat162float(__float2bfloat16(y0));
        float h1 = __bfloat162float(__float2bfloat16(y1));
        float h2 = __bfloat162float(__float2bfloat16(y2));
        float h3 = __bfloat162float(__float2bfloat16(y3));
        *(uint32_t*)(g_ah + out0 + col) = packbf(y0, y1);
        *(uint32_t*)(g_al + out0 + col) = packbf(y0 - h0, y1 - h1);
        *(uint32_t*)(g_ah + out1 + col) = packbf(y2, y3);
        *(uint32_t*)(g_al + out1 + col) = packbf(y2 - h2, y3 - h3);
    }
}

// ---------------- launch ----------------
extern "C" void kernel_launch(void* const* d_in, const int* in_sizes, int n_in,
                              void* d_out, int out_size)
{
    const float* x  = (const float*)d_in[0];
    const float* wq = (const float*)d_in[1];
    const float* wk = (const float*)d_in[2];
    const float* wv = (const float*)d_in[3];
    const float* wo = (const float*)d_in[4];
    const float* qw = (const float*)d_in[5];
    const float* kw = (const float*)d_in[6];
    float* out = (float*)d_out;

    float* xqkv = nullptr;
    __nv_bfloat16 *ah = nullptr, *al = nullptr, *wh = nullptr, *wl = nullptr;
    cudaGetSymbolAddress((void**)&xqkv, g_xqkv);
    cudaGetSymbolAddress((void**)&ah, g_ah);
    cudaGetSymbolAddress((void**)&al, g_al);
    cudaGetSymbolAddress((void**)&wh, g_wh);
    cudaGetSymbolAddress((void**)&wl, g_wl);

    static bool attr_done = false;
    if (!attr_done) {
        cudaFuncSetAttribute(hmma_gemm, cudaFuncAttributeMaxDynamicSharedMemorySize, GEMM_SMEM);
        cudaFuncSetAttribute(attn_tc, cudaFuncAttributeMaxDynamicSharedMemorySize, ATT_SMEM);
        attr_done = true;
    }

    split_bf16<<<(TT * DIM / 4) / 256, 256>>>(x, ah, al, TT * DIM / 4);
    wsplit_all<<<2560, 256>>>(wq, wk, wv, wo);
    hmma_gemm<<<dim3(QKVW / 128, TT / 128), 256, GEMM_SMEM>>>(ah, al, wh, wl, xqkv, QKVW, 0);
    prep_qkv<<<TT, 256>>>(qw, kw);
    attn_tc<<<dim3(SS / 128, NH, BB), 256, ATT_SMEM>>>();
    hmma_gemm<<<dim3(DIM / 128, TT / 128), 256, GEMM_SMEM>>>(
        ah, al, wh + (size_t)WO_ROW * DIM, wl + (size_t)WO_ROW * DIM, out, DIM, 0);
}

// round 8
// speedup vs baseline: 1.3684x; 1.3684x over previous
#include <cuda_runtime.h>
#include <cuda_fp16.h>
#include <math.h>
#include <stdint.h>

#define DIM   1024
#define NH    16
#define NKV   4
#define HD    64
#define WIN   512
#define BB    2
#define SS    2048
#define TT    (BB*SS)
#define QKVW  1536   // 1024 q | 256 k | 256 v per token
#define GK    1024   // K dim of every GEMM
#define LOG2E 1.4426950408889634f

// ---------------- scratch (no allocs allowed) ----------------
__device__ float g_xqkv[(size_t)TT * QKVW];        // fp32 qkv projections
__device__ __half g_ah[(size_t)TT * DIM];          // activation hi (x, then attn out)
__device__ __half g_al[(size_t)TT * DIM];          // activation lo
__device__ __half g_wh[(size_t)2560 * DIM];        // weights fp16 (single): wq|wk|wv|wo
__device__ __half g_qh[(size_t)TT * DIM];          // per-head Q hi  [(b*NH+h)*SS+s][64]
__device__ __half g_ql[(size_t)TT * DIM];          // per-head Q lo
__device__ __half g_kh[(size_t)TT * 256];          // per-kvhead K fp16 (single)
__device__ __half g_vh[(size_t)TT * 256];          // per-kvhead V fp16 (single)
#define WO_ROW 1536

// ---------------- small PTX helpers ----------------
__device__ __forceinline__ uint32_t smem_u32(const void* p) {
    uint32_t a;
    asm("{ .reg .u64 t; cvta.to.shared.u64 t, %1; cvt.u32.u64 %0, t; }" : "=r"(a) : "l"(p));
    return a;
}
__device__ __forceinline__ void cp16(uint32_t s, const void* g) {
    asm volatile("{ .reg .u64 gg; cvta.to.global.u64 gg, %1; cp.async.cg.shared.global [%0], [gg], 16; }"
                 :: "r"(s), "l"(g) : "memory");
}
__device__ __forceinline__ void cp_commit() { asm volatile("cp.async.commit_group;" ::: "memory"); }
template <int N>
__device__ __forceinline__ void cp_wait() { asm volatile("cp.async.wait_group %0;" :: "n"(N) : "memory"); }

__device__ __forceinline__ uint32_t packh(float lo, float hi) {
    uint32_t r;
    asm("cvt.rn.f16x2.f32 %0, %1, %2;" : "=r"(r) : "f"(hi), "f"(lo));
    return r;
}

#define MMA_F16(c0,c1,c2,c3, a0,a1,a2,a3, b0,b1) \
    asm volatile("mma.sync.aligned.m16n8k16.row.col.f32.f16.f16.f32 " \
                 "{%0,%1,%2,%3}, {%4,%5,%6,%7}, {%8,%9}, {%0,%1,%2,%3};" \
                 : "+f"(c0), "+f"(c1), "+f"(c2), "+f"(c3) \
                 : "r"(a0), "r"(a1), "r"(a2), "r"(a3), "r"(b0), "r"(b1))

#define LDMX4(r0,r1,r2,r3, addr) \
    asm volatile("ldmatrix.sync.aligned.m8n8.x4.shared.b16 {%0,%1,%2,%3}, [%4];" \
                 : "=r"(r0), "=r"(r1), "=r"(r2), "=r"(r3) : "r"(addr))
#define LDMX4T(r0,r1,r2,r3, addr) \
    asm volatile("ldmatrix.sync.aligned.m8n8.x4.trans.shared.b16 {%0,%1,%2,%3}, [%4];" \
                 : "=r"(r0), "=r"(r1), "=r"(r2), "=r"(r3) : "r"(addr))

// ---------------- fp32 -> fp16 hi/lo split (x / attention out stays in-kernel) ----------------
__global__ __launch_bounds__(256) void split_f16(
    const float* __restrict__ in, __half* __restrict__ hi,
    __half* __restrict__ lo, int n4)
{
    int i = blockIdx.x * 256 + threadIdx.x;
    if (i >= n4) return;
    float4 v = ((const float4*)in)[i];
    float f[4] = {v.x, v.y, v.z, v.w};
    union { __half b[4]; uint2 u; } H, L;
#pragma unroll
    for (int k = 0; k < 4; k++) {
        __half h = __float2half(f[k]);
        H.b[k] = h;
        L.b[k] = __float2half(f[k] - __half2float(h));
    }
    ((uint2*)hi)[i] = H.u;
    ((uint2*)lo)[i] = L.u;
}

// ---------------- all weights -> stacked fp16 (single precision weight side) ----------------
__global__ __launch_bounds__(256) void wsplit_all(
    const float* __restrict__ wq, const float* __restrict__ wk,
    const float* __restrict__ wv, const float* __restrict__ wo)
{
    int i = blockIdx.x * 256 + threadIdx.x;   // float4 index
    const float* src;
    int local;
    if (i < 262144)      { src = wq; local = i; }
    else if (i < 327680) { src = wk; local = i - 262144; }
    else if (i < 393216) { src = wv; local = i - 327680; }
    else                 { src = wo; local = i - 393216; }
    float4 v = ((const float4*)src)[local];
    union { __half b[4]; uint2 u; } H;
    H.b[0] = __float2half(v.x); H.b[1] = __float2half(v.y);
    H.b[2] = __float2half(v.z); H.b[3] = __float2half(v.w);
    ((uint2*)g_wh)[i] = H.u;
}

// ---------------- HMMA fp16 2-pass GEMM: BK=64, 3-stage cp.async ----------------
// C = (Ah + Al) * Bh  (A split fp16 hi/lo, B single fp16), K-major both sides.
#define BKC 64
#define NCHG (GK / BKC)          // 16
#define SROWG 72                 // halves per row (64 data + 8 pad -> 144B)
#define TILEG (128 * SROWG)      // halves per tile
#define STAGEG (3 * TILEG)       // Ah, Al, Bh
#define GEMM_SMEM (3 * STAGEG * 2)   // 165888 bytes

__global__ __launch_bounds__(256, 1) void hmma_gemm(
    const __half* __restrict__ ah, const __half* __restrict__ al,
    const __half* __restrict__ bh,
    float* __restrict__ C, int ldc, int coff)
{
    extern __shared__ char smraw[];
    const uint32_t smb = smem_u32(smraw);

    const int tid = threadIdx.x;
    const int wid = tid >> 5;
    const int lid = tid & 31;
    const int wm = wid & 1;
    const int wn = wid >> 1;
    const int m0 = blockIdx.y * 128;
    const int n0 = blockIdx.x * 128;

    const __half* gbase[3];
    gbase[0] = ah + (size_t)m0 * GK;
    gbase[1] = al + (size_t)m0 * GK;
    gbase[2] = bh + (size_t)n0 * GK;

    auto load_stage = [&](int kc, int stg) {
        const uint32_t base = smb + (uint32_t)stg * (STAGEG * 2);
#pragma unroll
        for (int i = 0; i < 4; i++) {
            int id = tid + 256 * i;
            int row = id >> 3, seg = id & 7;
            uint32_t soff = (uint32_t)(row * SROWG + seg * 8) * 2;
#pragma unroll
            for (int t = 0; t < 3; t++) {
                const __half* src = gbase[t] + (size_t)row * GK + kc + seg * 8;
                cp16(base + (uint32_t)t * (TILEG * 2) + soff, src);
            }
        }
        cp_commit();
    };

    float acc[4][4][4];
#pragma unroll
    for (int i = 0; i < 4; i++)
#pragma unroll
        for (int j = 0; j < 4; j++)
#pragma unroll
            for (int k = 0; k < 4; k++) acc[i][j][k] = 0.f;

    const uint32_t frag_off =
        (uint32_t)((((lid & 7) + ((lid >> 3) & 1) * 8) * SROWG + (lid >> 4) * 8) * 2);

    load_stage(0, 0);
    load_stage(BKC, 1);
    load_stage(2 * BKC, 2);

    for (int c = 0; c < NCHG; c++) {
        if (c <= NCHG - 3)      cp_wait<2>();
        else if (c == NCHG - 2) cp_wait<1>();
        else                    cp_wait<0>();
        __syncthreads();

        const uint32_t sbase = smb + (uint32_t)(c % 3) * (STAGEG * 2);

#pragma unroll
        for (int ks = 0; ks < 4; ks++) {
            uint32_t Ah[4][4], Al[4][4], Bh[2][4];
#pragma unroll
            for (int mf = 0; mf < 4; mf++) {
                uint32_t aaddr = sbase +
                    (uint32_t)(((wm * 64 + mf * 16) * SROWG + ks * 16) * 2) + frag_off;
                LDMX4(Ah[mf][0], Ah[mf][1], Ah[mf][2], Ah[mf][3], aaddr);
                LDMX4(Al[mf][0], Al[mf][1], Al[mf][2], Al[mf][3], aaddr + TILEG * 2);
            }
#pragma unroll
            for (int nfp = 0; nfp < 2; nfp++) {
                uint32_t baddr = sbase + 2u * (TILEG * 2) +
                    (uint32_t)(((wn * 32 + nfp * 16) * SROWG + ks * 16) * 2) + frag_off;
                LDMX4(Bh[nfp][0], Bh[nfp][1], Bh[nfp][2], Bh[nfp][3], baddr);
            }

            // pass 1: Ah*Bh
#pragma unroll
            for (int nfp = 0; nfp < 2; nfp++)
#pragma unroll
                for (int mf = 0; mf < 4; mf++) {
                    MMA_F16(acc[mf][2*nfp][0], acc[mf][2*nfp][1], acc[mf][2*nfp][2], acc[mf][2*nfp][3],
                            Ah[mf][0], Ah[mf][1], Ah[mf][2], Ah[mf][3], Bh[nfp][0], Bh[nfp][2]);
                    MMA_F16(acc[mf][2*nfp+1][0], acc[mf][2*nfp+1][1], acc[mf][2*nfp+1][2], acc[mf][2*nfp+1][3],
                            Ah[mf][0], Ah[mf][1], Ah[mf][2], Ah[mf][3], Bh[nfp][1], Bh[nfp][3]);
                }
            // pass 2: Al*Bh
#pragma unroll
            for (int nfp = 0; nfp < 2; nfp++)
#pragma unroll
                for (int mf = 0; mf < 4; mf++) {
                    MMA_F16(acc[mf][2*nfp][0], acc[mf][2*nfp][1], acc[mf][2*nfp][2], acc[mf][2*nfp][3],
                            Al[mf][0], Al[mf][1], Al[mf][2], Al[mf][3], Bh[nfp][0], Bh[nfp][2]);
                    MMA_F16(acc[mf][2*nfp+1][0], acc[mf][2*nfp+1][1], acc[mf][2*nfp+1][2], acc[mf][2*nfp+1][3],
                            Al[mf][0], Al[mf][1], Al[mf][2], Al[mf][3], Bh[nfp][1], Bh[nfp][3]);
                }
        }

        __syncthreads();
        if (c + 3 < NCHG) load_stage((c + 3) * BKC, c % 3);
    }

    const int r2 = lid >> 2;
    const int c2 = (lid & 3) * 2;
#pragma unroll
    for (int mf = 0; mf < 4; mf++) {
        const int row = m0 + wm * 64 + mf * 16 + r2;
#pragma unroll
        for (int nf = 0; nf < 4; nf++) {
            float* cp0 = C + (size_t)row * ldc + coff + n0 + wn * 32 + nf * 8 + c2;
            *(float2*)cp0 = make_float2(acc[mf][nf][0], acc[mf][nf][1]);
            *(float2*)(cp0 + 8 * (size_t)ldc) = make_float2(acc[mf][nf][2], acc[mf][nf][3]);
        }
    }
}

// ---------------- fused q-rms + k-rms + v: fp16 outputs ----------------
__global__ __launch_bounds__(256) void prep_qkv(
    const float* __restrict__ qw, const float* __restrict__ kw)
{
    const int t = blockIdx.x;
    const int b = t >> 11, s = t & (SS - 1);
    const float* row = g_xqkv + (size_t)t * QKVW;
    const int tid = threadIdx.x;

    float v[4];
    float ssq = 0.f;
#pragma unroll
    for (int i = 0; i < 4; i++) {
        v[i] = row[tid + 256 * i];
        ssq = fmaf(v[i], v[i], ssq);
    }
    float kvl = row[1024 + tid];
    float ssk = kvl * kvl;
    float vv = row[1280 + tid];

#pragma unroll
    for (int o = 16; o > 0; o >>= 1) {
        ssq += __shfl_xor_sync(0xffffffffu, ssq, o);
        ssk += __shfl_xor_sync(0xffffffffu, ssk, o);
    }

    __shared__ float redq[8], redk[8];
    __shared__ float sclq_s, sclk_s;
    if ((tid & 31) == 0) { redq[tid >> 5] = ssq; redk[tid >> 5] = ssk; }
    __syncthreads();
    if (tid == 0) {
        float tq = 0.f, tk = 0.f;
#pragma unroll
        for (int i = 0; i < 8; i++) { tq += redq[i]; tk += redk[i]; }
        sclq_s = rsqrtf(tq * (1.f / 1024.f) + 1e-6f) * (0.125f * LOG2E);
        sclk_s = rsqrtf(tk * (1.f / 256.f) + 1e-6f);
    }
    __syncthreads();
    const float sclq = sclq_s, sclk = sclk_s;

#pragma unroll
    for (int i = 0; i < 4; i++) {
        int idx = tid + 256 * i;
        float val = v[i] * sclq * qw[idx];
        int head = idx >> 6, d = idx & 63;
        size_t off = ((size_t)(b * NH + head) * SS + s) * 64 + d;
        __half h = __float2half(val);
        g_qh[off] = h;
        g_ql[off] = __float2half(val - __half2float(h));
    }

    const int kv = tid >> 6, d = tid & 63;
    const size_t off = ((size_t)(b * NKV + kv) * SS + s) * 64 + d;
    g_kh[off] = __float2half(kvl * sclk * kw[tid]);
    g_vh[off] = __float2half(vv);
}

// ---------------- tensor-core attention (log2 domain, fp16 2-pass) ----------------
#define TILEB 9216                    // 64*144
#define ATT_SMEM (2 * 2 * TILEB)      // 2 stages x (Kh, Vh) = 36864

__global__ __launch_bounds__(256, 2) void attn_tc()
{
    extern __shared__ char asm_[];
    const uint32_t smb = smem_u32(asm_);

    const int tid = threadIdx.x;
    const int wid = tid >> 5;
    const int lid = tid & 31;
    const int qstart = blockIdx.x * 128;
    const int head = blockIdx.y;
    const int b = blockIdx.z;
    const int kvh = head >> 2;

    const int r = lid >> 2;
    const int c2 = (lid & 3) * 2;
    const int qpos0 = qstart + wid * 16 + r;
    const int wqmin = qstart + wid * 16;
    const int wqmax = wqmin + 15;
    const float slope = exp2f(-0.5f * (float)(head + 1)) * LOG2E;

    const __half* qbh = g_qh + ((size_t)(b * NH + head) * SS + qstart + wid * 16) * 64;
    const __half* qbl = g_ql + ((size_t)(b * NH + head) * SS + qstart + wid * 16) * 64;
    uint32_t Qh[4][4];
#pragma unroll
    for (int ks = 0; ks < 4; ks++) {
        Qh[ks][0] = *(const uint32_t*)(qbh + r * 64 + ks * 16 + c2);
        Qh[ks][1] = *(const uint32_t*)(qbh + (r + 8) * 64 + ks * 16 + c2);
        Qh[ks][2] = *(const uint32_t*)(qbh + r * 64 + ks * 16 + 8 + c2);
        Qh[ks][3] = *(const uint32_t*)(qbh + (r + 8) * 64 + ks * 16 + 8 + c2);
    }

    float O[8][4];
#pragma unroll
    for (int i = 0; i < 8; i++)
#pragma unroll
        for (int j = 0; j < 4; j++) O[i][j] = 0.f;
    float m0 = -INFINITY, m1 = -INFINITY, l0 = 0.f, l1 = 0.f;

    const int kc0 = (qstart >= WIN) ? qstart - WIN : 0;
    const int nch = (qstart + 128 - kc0) >> 6;

    const int key_ld = tid >> 2;
    const int seg = tid & 3;
    const __half* src_base[2];
    {
        size_t kvb = ((size_t)(b * NKV + kvh) * SS) * 64;
        src_base[0] = g_kh + kvb;
        src_base[1] = g_vh + kvb;
    }
    auto load_chunk = [&](int kc, int stg) {
        uint32_t sb = smb + stg * 2 * TILEB + key_ld * 144 + seg * 16;
#pragma unroll
        for (int t = 0; t < 2; t++) {
            const __half* src = src_base[t] + (size_t)(kc + key_ld) * 64 + seg * 8;
            cp16(sb + t * TILEB, src);
            cp16(sb + t * TILEB + 64, src + 32);
        }
        cp_commit();
    };

    load_chunk(kc0, 0);
    if (nch > 1) load_chunk(kc0 + 64, 1);

    const uint32_t lane_off = (uint32_t)(((lid >> 4) * 8 + (lid & 7)) * 144 + ((lid >> 3) & 1) * 16);

    for (int c = 0; c < nch; c++) {
        if (c < nch - 1) cp_wait<1>(); else cp_wait<0>();
        __syncthreads();

        const uint32_t sb = smb + (c & 1) * 2 * TILEB;
        const int kc = kc0 + c * 64;

        const bool active = (kc <= wqmax) && (kc + 63 >= wqmin - WIN);
        if (active) {

        // ---- scores: S = Qh*Kh + Ql*Kh (K single fp16) ----
        float S[8][4];
#pragma unroll
        for (int i = 0; i < 8; i++)
#pragma unroll
            for (int j = 0; j < 4; j++) S[i][j] = 0.f;

#pragma unroll
        for (int ks = 0; ks < 4; ks++) {
            uint32_t Qlr[4];
            Qlr[0] = *(const uint32_t*)(qbl + r * 64 + ks * 16 + c2);
            Qlr[1] = *(const uint32_t*)(qbl + (r + 8) * 64 + ks * 16 + c2);
            Qlr[2] = *(const uint32_t*)(qbl + r * 64 + ks * 16 + 8 + c2);
            Qlr[3] = *(const uint32_t*)(qbl + (r + 8) * 64 + ks * 16 + 8 + c2);
#pragma unroll
            for (int g = 0; g < 2; g++) {
                uint32_t kh[2][4];
#pragma unroll
                for (int j = 0; j < 2; j++) {
                    int nfp = g * 2 + j;
                    LDMX4(kh[j][0], kh[j][1], kh[j][2], kh[j][3],
                          sb + nfp * 2304 + ks * 32 + lane_off);
                }
                // pass 1: Qh*Kh
#pragma unroll
                for (int j = 0; j < 2; j++) {
                    int nf = (g * 2 + j) * 2;
                    MMA_F16(S[nf][0], S[nf][1], S[nf][2], S[nf][3],
                            Qh[ks][0], Qh[ks][1], Qh[ks][2], Qh[ks][3], kh[j][0], kh[j][1]);
                    MMA_F16(S[nf+1][0], S[nf+1][1], S[nf+1][2], S[nf+1][3],
                            Qh[ks][0], Qh[ks][1], Qh[ks][2], Qh[ks][3], kh[j][2], kh[j][3]);
                }
                // pass 2: Ql*Kh
#pragma unroll
                for (int j = 0; j < 2; j++) {
                    int nf = (g * 2 + j) * 2;
                    MMA_F16(S[nf][0], S[nf][1], S[nf][2], S[nf][3],
                            Qlr[0], Qlr[1], Qlr[2], Qlr[3], kh[j][0], kh[j][1]);
                    MMA_F16(S[nf+1][0], S[nf+1][1], S[nf+1][2], S[nf+1][3],
                            Qlr[0], Qlr[1], Qlr[2], Qlr[3], kh[j][2], kh[j][3]);
                }
            }
        }

        // ---- bias + mask ----
#pragma unroll
        for (int nf = 0; nf < 8; nf++) {
            int rel0 = kc + nf * 8 + c2 - qpos0;
            int rel2 = rel0 - 8;
            S[nf][0] = (rel0     <= 0 && rel0     >= -WIN) ? fmaf(slope, (float)rel0,     S[nf][0]) : -INFINITY;
            S[nf][1] = (rel0 + 1 <= 0 && rel0 + 1 >= -WIN) ? fmaf(slope, (float)(rel0+1), S[nf][1]) : -INFINITY;
            S[nf][2] = (rel2     <= 0 && rel2     >= -WIN) ? fmaf(slope, (float)rel2,     S[nf][2]) : -INFINITY;
            S[nf][3] = (rel2 + 1 <= 0 && rel2 + 1 >= -WIN) ? fmaf(slope, (float)(rel2+1), S[nf][3]) : -INFINITY;
        }

        // ---- online softmax (exp2) ----
        float mx0 = -INFINITY, mx1 = -INFINITY;
#pragma unroll
        for (int nf = 0; nf < 8; nf++) {
            mx0 = fmaxf(mx0, fmaxf(S[nf][0], S[nf][1]));
            mx1 = fmaxf(mx1, fmaxf(S[nf][2], S[nf][3]));
        }
        mx0 = fmaxf(mx0, __shfl_xor_sync(0xffffffffu, mx0, 1));
        mx0 = fmaxf(mx0, __shfl_xor_sync(0xffffffffu, mx0, 2));
        mx1 = fmaxf(mx1, __shfl_xor_sync(0xffffffffu, mx1, 1));
        mx1 = fmaxf(mx1, __shfl_xor_sync(0xffffffffu, mx1, 2));

        float mn0 = fmaxf(fmaxf(m0, mx0), -1e30f);
        float mn1 = fmaxf(fmaxf(m1, mx1), -1e30f);
        float a0 = exp2f(m0 - mn0);
        float a1 = exp2f(m1 - mn1);
        m0 = mn0; m1 = mn1;
        l0 *= a0; l1 *= a1;
#pragma unroll
        for (int nf = 0; nf < 8; nf++) {
            O[nf][0] *= a0; O[nf][1] *= a0;
            O[nf][2] *= a1; O[nf][3] *= a1;
        }
#pragma unroll
        for (int nf = 0; nf < 8; nf++) {
            S[nf][0] = exp2f(S[nf][0] - m0);
            S[nf][1] = exp2f(S[nf][1] - m0);
            S[nf][2] = exp2f(S[nf][2] - m1);
            S[nf][3] = exp2f(S[nf][3] - m1);
            l0 += S[nf][0] + S[nf][1];
            l1 += S[nf][2] + S[nf][3];
        }

        // ---- PV: O += Ph*Vh + Pl*Vh (V single fp16) ----
#pragma unroll
        for (int ks = 0; ks < 4; ks++) {
            float x00 = S[2*ks][0],   x01 = S[2*ks][1],   x02 = S[2*ks][2],   x03 = S[2*ks][3];
            float x10 = S[2*ks+1][0], x11 = S[2*ks+1][1], x12 = S[2*ks+1][2], x13 = S[2*ks+1][3];
            float h00 = __half2float(__float2half(x00));
            float h01 = __half2float(__float2half(x01));
            float h02 = __half2float(__float2half(x02));
            float h03 = __half2float(__float2half(x03));
            float h10 = __half2float(__float2half(x10));
            float h11 = __half2float(__float2half(x11));
            float h12 = __half2float(__float2half(x12));
            float h13 = __half2float(__float2half(x13));
            uint32_t ph0 = packh(x00, x01), ph1 = packh(x02, x03);
            uint32_t ph2 = packh(x10, x11), ph3 = packh(x12, x13);
            uint32_t pl0 = packh(x00 - h00, x01 - h01), pl1 = packh(x02 - h02, x03 - h03);
            uint32_t pl2 = packh(x10 - h10, x11 - h11), pl3 = packh(x12 - h12, x13 - h13);
#pragma unroll
            for (int g = 0; g < 2; g++) {
                uint32_t v[2][4];
#pragma unroll
                for (int j = 0; j < 2; j++) {
                    int nfp = g * 2 + j;
                    LDMX4T(v[j][0], v[j][1], v[j][2], v[j][3],
                           sb + TILEB + ks * 2304 + nfp * 32 + lane_off);
                }
                // pass 1: Ph*Vh
#pragma unroll
                for (int j = 0; j < 2; j++) {
                    int nf = (g * 2 + j) * 2;
                    MMA_F16(O[nf][0], O[nf][1], O[nf][2], O[nf][3],
                            ph0, ph1, ph2, ph3, v[j][0], v[j][2]);
                    MMA_F16(O[nf+1][0], O[nf+1][1], O[nf+1][2], O[nf+1][3],
                            ph0, ph1, ph2, ph3, v[j][1], v[j][3]);
                }
                // pass 2: Pl*Vh
#pragma unroll
                for (int j = 0; j < 2; j++) {
                    int nf = (g * 2 + j) * 2;
                    MMA_F16(O[nf][0], O[nf][1], O[nf][2], O[nf][3],
                            pl0, pl1, pl2, pl3, v[j][0], v[j][2]);
                    MMA_F16(O[nf+1][0], O[nf+1][1], O[nf+1][2], O[nf+1][3],
                            pl0, pl1, pl2, pl3, v[j][1], v[j][3]);
                }
            }
        }

        }  // active

        __syncthreads();
        if (c + 2 < nch) load_chunk(kc0 + (c + 2) * 64, c & 1);
    }

    // ---- epilogue: write y as fp16 hi/lo for the O-projection ----
    l0 += __shfl_xor_sync(0xffffffffu, l0, 1);
    l0 += __shfl_xor_sync(0xffffffffu, l0, 2);
    l1 += __shfl_xor_sync(0xffffffffu, l1, 1);
    l1 += __shfl_xor_sync(0xffffffffu, l1, 2);
    float inv0 = 1.f / l0, inv1 = 1.f / l1;

    size_t out0 = ((size_t)(b * SS + qpos0) * DIM) + head * 64;
    size_t out1 = out0 + (size_t)8 * DIM;
#pragma unroll
    for (int nf = 0; nf < 8; nf++) {
        float y0 = O[nf][0] * inv0, y1 = O[nf][1] * inv0;
        float y2 = O[nf][2] * inv1, y3 = O[nf][3] * inv1;
        int col = nf * 8 + c2;
        float h0 = __half2float(__float2half(y0));
        float h1 = __half2float(__float2half(y1));
        float h2 = __half2float(__float2half(y2));
        float h3 = __half2float(__float2half(y3));
        *(uint32_t*)(g_ah + out0 + col) = packh(y0, y1);
        *(uint32_t*)(g_al + out0 + col) = packh(y0 - h0, y1 - h1);
        *(uint32_t*)(g_ah + out1 + col) = packh(y2, y3);
        *(uint32_t*)(g_al + out1 + col) = packh(y2 - h2, y3 - h3);
    }
}

// ---------------- launch ----------------
extern "C" void kernel_launch(void* const* d_in, const int* in_sizes, int n_in,
                              void* d_out, int out_size)
{
    const float* x  = (const float*)d_in[0];
    const float* wq = (const float*)d_in[1];
    const float* wk = (const float*)d_in[2];
    const float* wv = (const float*)d_in[3];
    const float* wo = (const float*)d_in[4];
    const float* qw = (const float*)d_in[5];
    const float* kw = (const float*)d_in[6];
    float* out = (float*)d_out;

    float* xqkv = nullptr;
    __half *ah = nullptr, *al = nullptr, *wh = nullptr;
    cudaGetSymbolAddress((void**)&xqkv, g_xqkv);
    cudaGetSymbolAddress((void**)&ah, g_ah);
    cudaGetSymbolAddress((void**)&al, g_al);
    cudaGetSymbolAddress((void**)&wh, g_wh);

    static bool attr_done = false;
    if (!attr_done) {
        cudaFuncSetAttribute(hmma_gemm, cudaFuncAttributeMaxDynamicSharedMemorySize, GEMM_SMEM);
        cudaFuncSetAttribute(attn_tc, cudaFuncAttributeMaxDynamicSharedMemorySize, ATT_SMEM);
        attr_done = true;
    }

    split_f16<<<(TT * DIM / 4) / 256, 256>>>(x, ah, al, TT * DIM / 4);
    wsplit_all<<<2560, 256>>>(wq, wk, wv, wo);
    hmma_gemm<<<dim3(QKVW / 128, TT / 128), 256, GEMM_SMEM>>>(ah, al, wh, xqkv, QKVW, 0);
    prep_qkv<<<TT, 256>>>(qw, kw);
    attn_tc<<<dim3(SS / 128, NH, BB), 256, ATT_SMEM>>>();
    hmma_gemm<<<dim3(DIM / 128, TT / 128), 256, GEMM_SMEM>>>(
        ah, al, wh + (size_t)WO_ROW * DIM, out, DIM, 0);
}

// round 9
// speedup vs baseline: 1.4534x; 1.0621x over previous
#include <cuda_runtime.h>
#include <cuda_fp16.h>
#include <math.h>
#include <stdint.h>

#define DIM   1024
#define NH    16
#define NKV   4
#define HD    64
#define WIN   512
#define BB    2
#define SS    2048
#define TT    (BB*SS)
#define QKVW  1536   // 1024 q | 256 k | 256 v per token
#define GK    1024   // K dim of every GEMM
#define LOG2E 1.4426950408889634f

// ---------------- scratch (no allocs allowed) ----------------
__device__ float g_xqkv[(size_t)TT * QKVW];        // fp32 qkv projections
__device__ __half g_ah[(size_t)TT * DIM];          // activation hi (x, then attn out)
__device__ __half g_al[(size_t)TT * DIM];          // activation lo
__device__ __half g_wh[(size_t)2560 * DIM];        // weights fp16 (single): wq|wk|wv|wo
__device__ __half g_qh[(size_t)TT * DIM];          // per-head Q hi  [(b*NH+h)*SS+s][64]
__device__ __half g_ql[(size_t)TT * DIM];          // per-head Q lo
__device__ __half g_kh[(size_t)TT * 256];          // per-kvhead K fp16 (single)
__device__ __half g_vh[(size_t)TT * 256];          // per-kvhead V fp16 (single)
#define WO_ROW 1536

// ---------------- small PTX helpers ----------------
__device__ __forceinline__ uint32_t smem_u32(const void* p) {
    uint32_t a;
    asm("{ .reg .u64 t; cvta.to.shared.u64 t, %1; cvt.u32.u64 %0, t; }" : "=r"(a) : "l"(p));
    return a;
}
__device__ __forceinline__ void cp16(uint32_t s, const void* g) {
    asm volatile("{ .reg .u64 gg; cvta.to.global.u64 gg, %1; cp.async.cg.shared.global [%0], [gg], 16; }"
                 :: "r"(s), "l"(g) : "memory");
}
__device__ __forceinline__ void cp_commit() { asm volatile("cp.async.commit_group;" ::: "memory"); }
template <int N>
__device__ __forceinline__ void cp_wait() { asm volatile("cp.async.wait_group %0;" :: "n"(N) : "memory"); }

__device__ __forceinline__ uint32_t packh(float lo, float hi) {
    uint32_t r;
    asm("cvt.rn.f16x2.f32 %0, %1, %2;" : "=r"(r) : "f"(hi), "f"(lo));
    return r;
}

#define MMA_F16(c0,c1,c2,c3, a0,a1,a2,a3, b0,b1) \
    asm volatile("mma.sync.aligned.m16n8k16.row.col.f32.f16.f16.f32 " \
                 "{%0,%1,%2,%3}, {%4,%5,%6,%7}, {%8,%9}, {%0,%1,%2,%3};" \
                 : "+f"(c0), "+f"(c1), "+f"(c2), "+f"(c3) \
                 : "r"(a0), "r"(a1), "r"(a2), "r"(a3), "r"(b0), "r"(b1))

#define LDMX4(r0,r1,r2,r3, addr) \
    asm volatile("ldmatrix.sync.aligned.m8n8.x4.shared.b16 {%0,%1,%2,%3}, [%4];" \
                 : "=r"(r0), "=r"(r1), "=r"(r2), "=r"(r3) : "r"(addr))
#define LDMX4T(r0,r1,r2,r3, addr) \
    asm volatile("ldmatrix.sync.aligned.m8n8.x4.trans.shared.b16 {%0,%1,%2,%3}, [%4];" \
                 : "=r"(r0), "=r"(r1), "=r"(r2), "=r"(r3) : "r"(addr))

// ---------------- fp32 -> fp16 hi/lo split (x) ----------------
__global__ __launch_bounds__(256) void split_f16(
    const float* __restrict__ in, __half* __restrict__ hi,
    __half* __restrict__ lo, int n4)
{
    int i = blockIdx.x * 256 + threadIdx.x;
    if (i >= n4) return;
    float4 v = ((const float4*)in)[i];
    float f[4] = {v.x, v.y, v.z, v.w};
    union { __half b[4]; uint2 u; } H, L;
#pragma unroll
    for (int k = 0; k < 4; k++) {
        __half h = __float2half(f[k]);
        H.b[k] = h;
        L.b[k] = __float2half(f[k] - __half2float(h));
    }
    ((uint2*)hi)[i] = H.u;
    ((uint2*)lo)[i] = L.u;
}

// ---------------- all weights -> stacked fp16 ----------------
__global__ __launch_bounds__(256) void wsplit_all(
    const float* __restrict__ wq, const float* __restrict__ wk,
    const float* __restrict__ wv, const float* __restrict__ wo)
{
    int i = blockIdx.x * 256 + threadIdx.x;   // float4 index
    const float* src;
    int local;
    if (i < 262144)      { src = wq; local = i; }
    else if (i < 327680) { src = wk; local = i - 262144; }
    else if (i < 393216) { src = wv; local = i - 327680; }
    else                 { src = wo; local = i - 393216; }
    float4 v = ((const float4*)src)[local];
    union { __half b[4]; uint2 u; } H;
    H.b[0] = __float2half(v.x); H.b[1] = __float2half(v.y);
    H.b[2] = __float2half(v.z); H.b[3] = __float2half(v.w);
    ((uint2*)g_wh)[i] = H.u;
}

// ---------------- HMMA fp16 2-pass GEMM: BK=64, 2-stage cp.async, 2 CTAs/SM ----------------
// C = (Ah + Al) * Bh  (A split fp16 hi/lo, B single fp16), K-major both sides.
#define BKC 64
#define NCHG (GK / BKC)          // 16
#define SROWG 72                 // halves per row (64 data + 8 pad -> 144B)
#define TILEG (128 * SROWG)      // halves per tile
#define STAGEG (3 * TILEG)       // Ah, Al, Bh
#define GEMM_SMEM (2 * STAGEG * 2)   // 110592 bytes -> 2 CTAs/SM

__global__ __launch_bounds__(256, 2) void hmma_gemm(
    const __half* __restrict__ ah, const __half* __restrict__ al,
    const __half* __restrict__ bh,
    float* __restrict__ C, int ldc, int coff)
{
    extern __shared__ char smraw[];
    const uint32_t smb = smem_u32(smraw);

    const int tid = threadIdx.x;
    const int wid = tid >> 5;
    const int lid = tid & 31;
    const int wm = wid & 1;
    const int wn = wid >> 1;
    const int m0 = blockIdx.y * 128;
    const int n0 = blockIdx.x * 128;

    const __half* gbase[3];
    gbase[0] = ah + (size_t)m0 * GK;
    gbase[1] = al + (size_t)m0 * GK;
    gbase[2] = bh + (size_t)n0 * GK;

    auto load_stage = [&](int kc, int stg) {
        const uint32_t base = smb + (uint32_t)stg * (STAGEG * 2);
#pragma unroll
        for (int i = 0; i < 4; i++) {
            int id = tid + 256 * i;
            int row = id >> 3, seg = id & 7;
            uint32_t soff = (uint32_t)(row * SROWG + seg * 8) * 2;
#pragma unroll
            for (int t = 0; t < 3; t++) {
                const __half* src = gbase[t] + (size_t)row * GK + kc + seg * 8;
                cp16(base + (uint32_t)t * (TILEG * 2) + soff, src);
            }
        }
        cp_commit();
    };

    float acc[4][4][4];
#pragma unroll
    for (int i = 0; i < 4; i++)
#pragma unroll
        for (int j = 0; j < 4; j++)
#pragma unroll
            for (int k = 0; k < 4; k++) acc[i][j][k] = 0.f;

    const uint32_t frag_off =
        (uint32_t)((((lid & 7) + ((lid >> 3) & 1) * 8) * SROWG + (lid >> 4) * 8) * 2);

    load_stage(0, 0);
    load_stage(BKC, 1);

    for (int c = 0; c < NCHG; c++) {
        if (c < NCHG - 1) cp_wait<1>(); else cp_wait<0>();
        __syncthreads();

        const uint32_t sbase = smb + (uint32_t)(c & 1) * (STAGEG * 2);

#pragma unroll
        for (int ks = 0; ks < 4; ks++) {
            uint32_t Ah[4][4], Al[4][4], Bh[2][4];
#pragma unroll
            for (int mf = 0; mf < 4; mf++) {
                uint32_t aaddr = sbase +
                    (uint32_t)(((wm * 64 + mf * 16) * SROWG + ks * 16) * 2) + frag_off;
                LDMX4(Ah[mf][0], Ah[mf][1], Ah[mf][2], Ah[mf][3], aaddr);
                LDMX4(Al[mf][0], Al[mf][1], Al[mf][2], Al[mf][3], aaddr + TILEG * 2);
            }
#pragma unroll
            for (int nfp = 0; nfp < 2; nfp++) {
                uint32_t baddr = sbase + 2u * (TILEG * 2) +
                    (uint32_t)(((wn * 32 + nfp * 16) * SROWG + ks * 16) * 2) + frag_off;
                LDMX4(Bh[nfp][0], Bh[nfp][1], Bh[nfp][2], Bh[nfp][3], baddr);
            }

            // pass 1: Ah*Bh
#pragma unroll
            for (int nfp = 0; nfp < 2; nfp++)
#pragma unroll
                for (int mf = 0; mf < 4; mf++) {
                    MMA_F16(acc[mf][2*nfp][0], acc[mf][2*nfp][1], acc[mf][2*nfp][2], acc[mf][2*nfp][3],
                            Ah[mf][0], Ah[mf][1], Ah[mf][2], Ah[mf][3], Bh[nfp][0], Bh[nfp][2]);
                    MMA_F16(acc[mf][2*nfp+1][0], acc[mf][2*nfp+1][1], acc[mf][2*nfp+1][2], acc[mf][2*nfp+1][3],
                            Ah[mf][0], Ah[mf][1], Ah[mf][2], Ah[mf][3], Bh[nfp][1], Bh[nfp][3]);
                }
            // pass 2: Al*Bh
#pragma unroll
            for (int nfp = 0; nfp < 2; nfp++)
#pragma unroll
                for (int mf = 0; mf < 4; mf++) {
                    MMA_F16(acc[mf][2*nfp][0], acc[mf][2*nfp][1], acc[mf][2*nfp][2], acc[mf][2*nfp][3],
                            Al[mf][0], Al[mf][1], Al[mf][2], Al[mf][3], Bh[nfp][0], Bh[nfp][2]);
                    MMA_F16(acc[mf][2*nfp+1][0], acc[mf][2*nfp+1][1], acc[mf][2*nfp+1][2], acc[mf][2*nfp+1][3],
                            Al[mf][0], Al[mf][1], Al[mf][2], Al[mf][3], Bh[nfp][1], Bh[nfp][3]);
                }
        }

        __syncthreads();
        if (c + 2 < NCHG) load_stage((c + 2) * BKC, c & 1);
    }

    const int r2 = lid >> 2;
    const int c2 = (lid & 3) * 2;
#pragma unroll
    for (int mf = 0; mf < 4; mf++) {
        const int row = m0 + wm * 64 + mf * 16 + r2;
#pragma unroll
        for (int nf = 0; nf < 4; nf++) {
            float* cp0 = C + (size_t)row * ldc + coff + n0 + wn * 32 + nf * 8 + c2;
            *(float2*)cp0 = make_float2(acc[mf][nf][0], acc[mf][nf][1]);
            *(float2*)(cp0 + 8 * (size_t)ldc) = make_float2(acc[mf][nf][2], acc[mf][nf][3]);
        }
    }
}

// ---------------- fused q-rms + k-rms + v: fp16 outputs ----------------
__global__ __launch_bounds__(256) void prep_qkv(
    const float* __restrict__ qw, const float* __restrict__ kw)
{
    const int t = blockIdx.x;
    const int b = t >> 11, s = t & (SS - 1);
    const float* row = g_xqkv + (size_t)t * QKVW;
    const int tid = threadIdx.x;

    float v[4];
    float ssq = 0.f;
#pragma unroll
    for (int i = 0; i < 4; i++) {
        v[i] = row[tid + 256 * i];
        ssq = fmaf(v[i], v[i], ssq);
    }
    float kvl = row[1024 + tid];
    float ssk = kvl * kvl;
    float vv = row[1280 + tid];

#pragma unroll
    for (int o = 16; o > 0; o >>= 1) {
        ssq += __shfl_xor_sync(0xffffffffu, ssq, o);
        ssk += __shfl_xor_sync(0xffffffffu, ssk, o);
    }

    __shared__ float redq[8], redk[8];
    __shared__ float sclq_s, sclk_s;
    if ((tid & 31) == 0) { redq[tid >> 5] = ssq; redk[tid >> 5] = ssk; }
    __syncthreads();
    if (tid == 0) {
        float tq = 0.f, tk = 0.f;
#pragma unroll
        for (int i = 0; i < 8; i++) { tq += redq[i]; tk += redk[i]; }
        sclq_s = rsqrtf(tq * (1.f / 1024.f) + 1e-6f) * (0.125f * LOG2E);
        sclk_s = rsqrtf(tk * (1.f / 256.f) + 1e-6f);
    }
    __syncthreads();
    const float sclq = sclq_s, sclk = sclk_s;

#pragma unroll
    for (int i = 0; i < 4; i++) {
        int idx = tid + 256 * i;
        float val = v[i] * sclq * qw[idx];
        int head = idx >> 6, d = idx & 63;
        size_t off = ((size_t)(b * NH + head) * SS + s) * 64 + d;
        __half h = __float2half(val);
        g_qh[off] = h;
        g_ql[off] = __float2half(val - __half2float(h));
    }

    const int kv = tid >> 6, d = tid & 63;
    const size_t off = ((size_t)(b * NKV + kv) * SS + s) * 64 + d;
    g_kh[off] = __float2half(kvl * sclk * kw[tid]);
    g_vh[off] = __float2half(vv);
}

// ---------------- tensor-core attention (log2 domain, fp16 2-pass) ----------------
#define TILEB 9216                    // 64*144
#define ATT_SMEM (2 * 2 * TILEB)      // 2 stages x (Kh, Vh) = 36864

__global__ __launch_bounds__(256, 2) void attn_tc()
{
    extern __shared__ char asm_[];
    const uint32_t smb = smem_u32(asm_);

    const int tid = threadIdx.x;
    const int wid = tid >> 5;
    const int lid = tid & 31;
    const int qstart = blockIdx.x * 128;
    const int head = blockIdx.y;
    const int b = blockIdx.z;
    const int kvh = head >> 2;

    const int r = lid >> 2;
    const int c2 = (lid & 3) * 2;
    const int qpos0 = qstart + wid * 16 + r;
    const int wqmin = qstart + wid * 16;
    const int wqmax = wqmin + 15;
    const float slope = exp2f(-0.5f * (float)(head + 1)) * LOG2E;

    const __half* qbh = g_qh + ((size_t)(b * NH + head) * SS + qstart + wid * 16) * 64;
    const __half* qbl = g_ql + ((size_t)(b * NH + head) * SS + qstart + wid * 16) * 64;
    uint32_t Qh[4][4];
#pragma unroll
    for (int ks = 0; ks < 4; ks++) {
        Qh[ks][0] = *(const uint32_t*)(qbh + r * 64 + ks * 16 + c2);
        Qh[ks][1] = *(const uint32_t*)(qbh + (r + 8) * 64 + ks * 16 + c2);
        Qh[ks][2] = *(const uint32_t*)(qbh + r * 64 + ks * 16 + 8 + c2);
        Qh[ks][3] = *(const uint32_t*)(qbh + (r + 8) * 64 + ks * 16 + 8 + c2);
    }

    float O[8][4];
#pragma unroll
    for (int i = 0; i < 8; i++)
#pragma unroll
        for (int j = 0; j < 4; j++) O[i][j] = 0.f;
    float m0 = -INFINITY, m1 = -INFINITY, l0 = 0.f, l1 = 0.f;

    const int kc0 = (qstart >= WIN) ? qstart - WIN : 0;
    const int nch = (qstart + 128 - kc0) >> 6;

    const int key_ld = tid >> 2;
    const int seg = tid & 3;
    const __half* src_base[2];
    {
        size_t kvb = ((size_t)(b * NKV + kvh) * SS) * 64;
        src_base[0] = g_kh + kvb;
        src_base[1] = g_vh + kvb;
    }
    auto load_chunk = [&](int kc, int stg) {
        uint32_t sb = smb + stg * 2 * TILEB + key_ld * 144 + seg * 16;
#pragma unroll
        for (int t = 0; t < 2; t++) {
            const __half* src = src_base[t] + (size_t)(kc + key_ld) * 64 + seg * 8;
            cp16(sb + t * TILEB, src);
            cp16(sb + t * TILEB + 64, src + 32);
        }
        cp_commit();
    };

    load_chunk(kc0, 0);
    if (nch > 1) load_chunk(kc0 + 64, 1);

    const uint32_t lane_off = (uint32_t)(((lid >> 4) * 8 + (lid & 7)) * 144 + ((lid >> 3) & 1) * 16);

    for (int c = 0; c < nch; c++) {
        if (c < nch - 1) cp_wait<1>(); else cp_wait<0>();
        __syncthreads();

        const uint32_t sb = smb + (c & 1) * 2 * TILEB;
        const int kc = kc0 + c * 64;

        const bool active = (kc <= wqmax) && (kc + 63 >= wqmin - WIN);
        if (active) {

        // ---- scores: S = Qh*Kh + Ql*Kh ----
        float S[8][4];
#pragma unroll
        for (int i = 0; i < 8; i++)
#pragma unroll
            for (int j = 0; j < 4; j++) S[i][j] = 0.f;

#pragma unroll
        for (int ks = 0; ks < 4; ks++) {
            uint32_t Qlr[4];
            Qlr[0] = *(const uint32_t*)(qbl + r * 64 + ks * 16 + c2);
            Qlr[1] = *(const uint32_t*)(qbl + (r + 8) * 64 + ks * 16 + c2);
            Qlr[2] = *(const uint32_t*)(qbl + r * 64 + ks * 16 + 8 + c2);
            Qlr[3] = *(const uint32_t*)(qbl + (r + 8) * 64 + ks * 16 + 8 + c2);
#pragma unroll
            for (int g = 0; g < 2; g++) {
                uint32_t kh[2][4];
#pragma unroll
                for (int j = 0; j < 2; j++) {
                    int nfp = g * 2 + j;
                    LDMX4(kh[j][0], kh[j][1], kh[j][2], kh[j][3],
                          sb + nfp * 2304 + ks * 32 + lane_off);
                }
#pragma unroll
                for (int j = 0; j < 2; j++) {
                    int nf = (g * 2 + j) * 2;
                    MMA_F16(S[nf][0], S[nf][1], S[nf][2], S[nf][3],
                            Qh[ks][0], Qh[ks][1], Qh[ks][2], Qh[ks][3], kh[j][0], kh[j][1]);
                    MMA_F16(S[nf+1][0], S[nf+1][1], S[nf+1][2], S[nf+1][3],
                            Qh[ks][0], Qh[ks][1], Qh[ks][2], Qh[ks][3], kh[j][2], kh[j][3]);
                }
#pragma unroll
                for (int j = 0; j < 2; j++) {
                    int nf = (g * 2 + j) * 2;
                    MMA_F16(S[nf][0], S[nf][1], S[nf][2], S[nf][3],
                            Qlr[0], Qlr[1], Qlr[2], Qlr[3], kh[j][0], kh[j][1]);
                    MMA_F16(S[nf+1][0], S[nf+1][1], S[nf+1][2], S[nf+1][3],
                            Qlr[0], Qlr[1], Qlr[2], Qlr[3], kh[j][2], kh[j][3]);
                }
            }
        }

        // ---- bias + mask ----
#pragma unroll
        for (int nf = 0; nf < 8; nf++) {
            int rel0 = kc + nf * 8 + c2 - qpos0;
            int rel2 = rel0 - 8;
            S[nf][0] = (rel0     <= 0 && rel0     >= -WIN) ? fmaf(slope, (float)rel0,     S[nf][0]) : -INFINITY;
            S[nf][1] = (rel0 + 1 <= 0 && rel0 + 1 >= -WIN) ? fmaf(slope, (float)(rel0+1), S[nf][1]) : -INFINITY;
            S[nf][2] = (rel2     <= 0 && rel2     >= -WIN) ? fmaf(slope, (float)rel2,     S[nf][2]) : -INFINITY;
            S[nf][3] = (rel2 + 1 <= 0 && rel2 + 1 >= -WIN) ? fmaf(slope, (float)(rel2+1), S[nf][3]) : -INFINITY;
        }

        // ---- online softmax (exp2) ----
        float mx0 = -INFINITY, mx1 = -INFINITY;
#pragma unroll
        for (int nf = 0; nf < 8; nf++) {
            mx0 = fmaxf(mx0, fmaxf(S[nf][0], S[nf][1]));
            mx1 = fmaxf(mx1, fmaxf(S[nf][2], S[nf][3]));
        }
        mx0 = fmaxf(mx0, __shfl_xor_sync(0xffffffffu, mx0, 1));
        mx0 = fmaxf(mx0, __shfl_xor_sync(0xffffffffu, mx0, 2));
        mx1 = fmaxf(mx1, __shfl_xor_sync(0xffffffffu, mx1, 1));
        mx1 = fmaxf(mx1, __shfl_xor_sync(0xffffffffu, mx1, 2));

        float mn0 = fmaxf(fmaxf(m0, mx0), -1e30f);
        float mn1 = fmaxf(fmaxf(m1, mx1), -1e30f);
        float a0 = exp2f(m0 - mn0);
        float a1 = exp2f(m1 - mn1);
        m0 = mn0; m1 = mn1;
        l0 *= a0; l1 *= a1;
#pragma unroll
        for (int nf = 0; nf < 8; nf++) {
            O[nf][0] *= a0; O[nf][1] *= a0;
            O[nf][2] *= a1; O[nf][3] *= a1;
        }
#pragma unroll
        for (int nf = 0; nf < 8; nf++) {
            S[nf][0] = exp2f(S[nf][0] - m0);
            S[nf][1] = exp2f(S[nf][1] - m0);
            S[nf][2] = exp2f(S[nf][2] - m1);
            S[nf][3] = exp2f(S[nf][3] - m1);
            l0 += S[nf][0] + S[nf][1];
            l1 += S[nf][2] + S[nf][3];
        }

        // ---- PV: O += Ph*Vh + Pl*Vh ----
#pragma unroll
        for (int ks = 0; ks < 4; ks++) {
            float x00 = S[2*ks][0],   x01 = S[2*ks][1],   x02 = S[2*ks][2],   x03 = S[2*ks][3];
            float x10 = S[2*ks+1][0], x11 = S[2*ks+1][1], x12 = S[2*ks+1][2], x13 = S[2*ks+1][3];
            float h00 = __half2float(__float2half(x00));
            float h01 = __half2float(__float2half(x01));
            float h02 = __half2float(__float2half(x02));
            float h03 = __half2float(__float2half(x03));
            float h10 = __half2float(__float2half(x10));
            float h11 = __half2float(__float2half(x11));
            float h12 = __half2float(__float2half(x12));
            float h13 = __half2float(__float2half(x13));
            uint32_t ph0 = packh(x00, x01), ph1 = packh(x02, x03);
            uint32_t ph2 = packh(x10, x11), ph3 = packh(x12, x13);
            uint32_t pl0 = packh(x00 - h00, x01 - h01), pl1 = packh(x02 - h02, x03 - h03);
            uint32_t pl2 = packh(x10 - h10, x11 - h11), pl3 = packh(x12 - h12, x13 - h13);
#pragma unroll
            for (int g = 0; g < 2; g++) {
                uint32_t v[2][4];
#pragma unroll
                for (int j = 0; j < 2; j++) {
                    int nfp = g * 2 + j;
                    LDMX4T(v[j][0], v[j][1], v[j][2], v[j][3],
                           sb + TILEB + ks * 2304 + nfp * 32 + lane_off);
                }
#pragma unroll
                for (int j = 0; j < 2; j++) {
                    int nf = (g * 2 + j) * 2;
                    MMA_F16(O[nf][0], O[nf][1], O[nf][2], O[nf][3],
                            ph0, ph1, ph2, ph3, v[j][0], v[j][2]);
                    MMA_F16(O[nf+1][0], O[nf+1][1], O[nf+1][2], O[nf+1][3],
                            ph0, ph1, ph2, ph3, v[j][1], v[j][3]);
                }
#pragma unroll
                for (int j = 0; j < 2; j++) {
                    int nf = (g * 2 + j) * 2;
                    MMA_F16(O[nf][0], O[nf][1], O[nf][2], O[nf][3],
                            pl0, pl1, pl2, pl3, v[j][0], v[j][2]);
                    MMA_F16(O[nf+1][0], O[nf+1][1], O[nf+1][2], O[nf+1][3],
                            pl0, pl1, pl2, pl3, v[j][1], v[j][3]);
                }
            }
        }

        }  // active

        __syncthreads();
        if (c + 2 < nch) load_chunk(kc0 + (c + 2) * 64, c & 1);
    }

    // ---- epilogue ----
    l0 += __shfl_xor_sync(0xffffffffu, l0, 1);
    l0 += __shfl_xor_sync(0xffffffffu, l0, 2);
    l1 += __shfl_xor_sync(0xffffffffu, l1, 1);
    l1 += __shfl_xor_sync(0xffffffffu, l1, 2);
    float inv0 = 1.f / l0, inv1 = 1.f / l1;

    size_t out0 = ((size_t)(b * SS + qpos0) * DIM) + head * 64;
    size_t out1 = out0 + (size_t)8 * DIM;
#pragma unroll
    for (int nf = 0; nf < 8; nf++) {
        float y0 = O[nf][0] * inv0, y1 = O[nf][1] * inv0;
        float y2 = O[nf][2] * inv1, y3 = O[nf][3] * inv1;
        int col = nf * 8 + c2;
        float h0 = __half2float(__float2half(y0));
        float h1 = __half2float(__float2half(y1));
        float h2 = __half2float(__float2half(y2));
        float h3 = __half2float(__float2half(y3));
        *(uint32_t*)(g_ah + out0 + col) = packh(y0, y1);
        *(uint32_t*)(g_al + out0 + col) = packh(y0 - h0, y1 - h1);
        *(uint32_t*)(g_ah + out1 + col) = packh(y2, y3);
        *(uint32_t*)(g_al + out1 + col) = packh(y2 - h2, y3 - h3);
    }
}

// ---------------- launch ----------------
extern "C" void kernel_launch(void* const* d_in, const int* in_sizes, int n_in,
                              void* d_out, int out_size)
{
    const float* x  = (const float*)d_in[0];
    const float* wq = (const float*)d_in[1];
    const float* wk = (const float*)d_in[2];
    const float* wv = (const float*)d_in[3];
    const float* wo = (const float*)d_in[4];
    const float* qw = (const float*)d_in[5];
    const float* kw = (const float*)d_in[6];
    float* out = (float*)d_out;

    float* xqkv = nullptr;
    __half *ah = nullptr, *al = nullptr, *wh = nullptr;
    cudaGetSymbolAddress((void**)&xqkv, g_xqkv);
    cudaGetSymbolAddress((void**)&ah, g_ah);
    cudaGetSymbolAddress((void**)&al, g_al);
    cudaGetSymbolAddress((void**)&wh, g_wh);

    static bool attr_done = false;
    if (!attr_done) {
        cudaFuncSetAttribute(hmma_gemm, cudaFuncAttributeMaxDynamicSharedMemorySize, GEMM_SMEM);
        cudaFuncSetAttribute(attn_tc, cudaFuncAttributeMaxDynamicSharedMemorySize, ATT_SMEM);
        attr_done = true;
    }

    split_f16<<<(TT * DIM / 4) / 256, 256>>>(x, ah, al, TT * DIM / 4);
    wsplit_all<<<2560, 256>>>(wq, wk, wv, wo);
    hmma_gemm<<<dim3(QKVW / 128, TT / 128), 256, GEMM_SMEM>>>(ah, al, wh, xqkv, QKVW, 0);
    prep_qkv<<<TT, 256>>>(qw, kw);
    attn_tc<<<dim3(SS / 128, NH, BB), 256, ATT_SMEM>>>();
    hmma_gemm<<<dim3(DIM / 128, TT / 128), 256, GEMM_SMEM>>>(
        ah, al, wh + (size_t)WO_ROW * DIM, out, DIM, 0);
}

// round 10
// speedup vs baseline: 1.4565x; 1.0021x over previous
#include <cuda_runtime.h>
#include <cuda_fp16.h>
#include <math.h>
#include <stdint.h>

#define DIM   1024
#define NH    16
#define NKV   4
#define HD    64
#define WIN   512
#define BB    2
#define SS    2048
#define TT    (BB*SS)
#define QKVW  1536   // 1024 q | 256 k | 256 v per token
#define GK    1024   // K dim of every GEMM
#define LOG2E 1.4426950408889634f

// ---------------- scratch (no allocs allowed) ----------------
__device__ float g_xqkv[(size_t)TT * QKVW];        // fp32 qkv projections
__device__ __half g_ah[(size_t)TT * DIM];          // activation hi (x, then attn out)
__device__ __half g_al[(size_t)TT * DIM];          // activation lo
__device__ __half g_wh[(size_t)2560 * DIM];        // weights fp16 (single): wq|wk|wv|wo
__device__ __half g_qh[(size_t)TT * DIM];          // per-head Q hi  [(b*NH+h)*SS+s][64]
__device__ __half g_ql[(size_t)TT * DIM];          // per-head Q lo
__device__ __half g_kh[(size_t)TT * 256];          // per-kvhead K fp16 (single)
__device__ __half g_vh[(size_t)TT * 256];          // per-kvhead V fp16 (single)
#define WO_ROW 1536

// ---------------- small PTX helpers ----------------
__device__ __forceinline__ uint32_t smem_u32(const void* p) {
    uint32_t a;
    asm("{ .reg .u64 t; cvta.to.shared.u64 t, %1; cvt.u32.u64 %0, t; }" : "=r"(a) : "l"(p));
    return a;
}
__device__ __forceinline__ void cp16(uint32_t s, const void* g) {
    asm volatile("{ .reg .u64 gg; cvta.to.global.u64 gg, %1; cp.async.cg.shared.global [%0], [gg], 16; }"
                 :: "r"(s), "l"(g) : "memory");
}
__device__ __forceinline__ void cp_commit() { asm volatile("cp.async.commit_group;" ::: "memory"); }
template <int N>
__device__ __forceinline__ void cp_wait() { asm volatile("cp.async.wait_group %0;" :: "n"(N) : "memory"); }

__device__ __forceinline__ uint32_t packh(float lo, float hi) {
    uint32_t r;
    asm("cvt.rn.f16x2.f32 %0, %1, %2;" : "=r"(r) : "f"(hi), "f"(lo));
    return r;
}

#define MMA_F16(c0,c1,c2,c3, a0,a1,a2,a3, b0,b1) \
    asm volatile("mma.sync.aligned.m16n8k16.row.col.f32.f16.f16.f32 " \
                 "{%0,%1,%2,%3}, {%4,%5,%6,%7}, {%8,%9}, {%0,%1,%2,%3};" \
                 : "+f"(c0), "+f"(c1), "+f"(c2), "+f"(c3) \
                 : "r"(a0), "r"(a1), "r"(a2), "r"(a3), "r"(b0), "r"(b1))

#define LDMX4(r0,r1,r2,r3, addr) \
    asm volatile("ldmatrix.sync.aligned.m8n8.x4.shared.b16 {%0,%1,%2,%3}, [%4];" \
                 : "=r"(r0), "=r"(r1), "=r"(r2), "=r"(r3) : "r"(addr))
#define LDMX4T(r0,r1,r2,r3, addr) \
    asm volatile("ldmatrix.sync.aligned.m8n8.x4.trans.shared.b16 {%0,%1,%2,%3}, [%4];" \
                 : "=r"(r0), "=r"(r1), "=r"(r2), "=r"(r3) : "r"(addr))

// ---------------- fused splits: x -> hi/lo fp16, all weights -> fp16 ----------------
// float4 ids: [0, 1048576) = x, [1048576, 1703936) = weights (wq|wk|wv|wo order)
__global__ __launch_bounds__(256) void split_all(
    const float* __restrict__ x,
    const float* __restrict__ wq, const float* __restrict__ wk,
    const float* __restrict__ wv, const float* __restrict__ wo)
{
    int i = blockIdx.x * 256 + threadIdx.x;
    if (i < 1048576) {
        float4 v = ((const float4*)x)[i];
        float f[4] = {v.x, v.y, v.z, v.w};
        union { __half b[4]; uint2 u; } H, L;
#pragma unroll
        for (int k = 0; k < 4; k++) {
            __half h = __float2half(f[k]);
            H.b[k] = h;
            L.b[k] = __float2half(f[k] - __half2float(h));
        }
        ((uint2*)g_ah)[i] = H.u;
        ((uint2*)g_al)[i] = L.u;
    } else {
        int j = i - 1048576;
        const float* src;
        int local;
        if (j < 262144)      { src = wq; local = j; }
        else if (j < 327680) { src = wk; local = j - 262144; }
        else if (j < 393216) { src = wv; local = j - 327680; }
        else                 { src = wo; local = j - 393216; }
        float4 v = ((const float4*)src)[local];
        union { __half b[4]; uint2 u; } H;
        H.b[0] = __float2half(v.x); H.b[1] = __float2half(v.y);
        H.b[2] = __float2half(v.z); H.b[3] = __float2half(v.w);
        ((uint2*)g_wh)[j] = H.u;
    }
}

// ---------------- HMMA fp16 2-pass GEMM: BK=64, 2-stage cp.async, 2 CTAs/SM ----------------
#define BKC 64
#define NCHG (GK / BKC)          // 16
#define SROWG 72                 // halves per row (64 data + 8 pad -> 144B)
#define TILEG (128 * SROWG)      // halves per tile
#define STAGEG (3 * TILEG)       // Ah, Al, Bh
#define GEMM_SMEM (2 * STAGEG * 2)   // 110592 bytes -> 2 CTAs/SM

__global__ __launch_bounds__(256, 2) void hmma_gemm(
    const __half* __restrict__ ah, const __half* __restrict__ al,
    const __half* __restrict__ bh,
    float* __restrict__ C, int ldc, int coff)
{
    extern __shared__ char smraw[];
    const uint32_t smb = smem_u32(smraw);

    const int tid = threadIdx.x;
    const int wid = tid >> 5;
    const int lid = tid & 31;
    const int wm = wid & 1;
    const int wn = wid >> 1;
    const int m0 = blockIdx.y * 128;
    const int n0 = blockIdx.x * 128;

    const __half* gbase[3];
    gbase[0] = ah + (size_t)m0 * GK;
    gbase[1] = al + (size_t)m0 * GK;
    gbase[2] = bh + (size_t)n0 * GK;

    auto load_stage = [&](int kc, int stg) {
        const uint32_t base = smb + (uint32_t)stg * (STAGEG * 2);
#pragma unroll
        for (int i = 0; i < 4; i++) {
            int id = tid + 256 * i;
            int row = id >> 3, seg = id & 7;
            uint32_t soff = (uint32_t)(row * SROWG + seg * 8) * 2;
#pragma unroll
            for (int t = 0; t < 3; t++) {
                const __half* src = gbase[t] + (size_t)row * GK + kc + seg * 8;
                cp16(base + (uint32_t)t * (TILEG * 2) + soff, src);
            }
        }
        cp_commit();
    };

    float acc[4][4][4];
#pragma unroll
    for (int i = 0; i < 4; i++)
#pragma unroll
        for (int j = 0; j < 4; j++)
#pragma unroll
            for (int k = 0; k < 4; k++) acc[i][j][k] = 0.f;

    const uint32_t frag_off =
        (uint32_t)((((lid & 7) + ((lid >> 3) & 1) * 8) * SROWG + (lid >> 4) * 8) * 2);

    load_stage(0, 0);
    load_stage(BKC, 1);

    for (int c = 0; c < NCHG; c++) {
        if (c < NCHG - 1) cp_wait<1>(); else cp_wait<0>();
        __syncthreads();

        const uint32_t sbase = smb + (uint32_t)(c & 1) * (STAGEG * 2);

#pragma unroll
        for (int ks = 0; ks < 4; ks++) {
            uint32_t Ah[4][4], Al[4][4], Bh[2][4];
#pragma unroll
            for (int mf = 0; mf < 4; mf++) {
                uint32_t aaddr = sbase +
                    (uint32_t)(((wm * 64 + mf * 16) * SROWG + ks * 16) * 2) + frag_off;
                LDMX4(Ah[mf][0], Ah[mf][1], Ah[mf][2], Ah[mf][3], aaddr);
                LDMX4(Al[mf][0], Al[mf][1], Al[mf][2], Al[mf][3], aaddr + TILEG * 2);
            }
#pragma unroll
            for (int nfp = 0; nfp < 2; nfp++) {
                uint32_t baddr = sbase + 2u * (TILEG * 2) +
                    (uint32_t)(((wn * 32 + nfp * 16) * SROWG + ks * 16) * 2) + frag_off;
                LDMX4(Bh[nfp][0], Bh[nfp][1], Bh[nfp][2], Bh[nfp][3], baddr);
            }

            // pass 1: Ah*Bh
#pragma unroll
            for (int nfp = 0; nfp < 2; nfp++)
#pragma unroll
                for (int mf = 0; mf < 4; mf++) {
                    MMA_F16(acc[mf][2*nfp][0], acc[mf][2*nfp][1], acc[mf][2*nfp][2], acc[mf][2*nfp][3],
                            Ah[mf][0], Ah[mf][1], Ah[mf][2], Ah[mf][3], Bh[nfp][0], Bh[nfp][2]);
                    MMA_F16(acc[mf][2*nfp+1][0], acc[mf][2*nfp+1][1], acc[mf][2*nfp+1][2], acc[mf][2*nfp+1][3],
                            Ah[mf][0], Ah[mf][1], Ah[mf][2], Ah[mf][3], Bh[nfp][1], Bh[nfp][3]);
                }
            // pass 2: Al*Bh
#pragma unroll
            for (int nfp = 0; nfp < 2; nfp++)
#pragma unroll
                for (int mf = 0; mf < 4; mf++) {
                    MMA_F16(acc[mf][2*nfp][0], acc[mf][2*nfp][1], acc[mf][2*nfp][2], acc[mf][2*nfp][3],
                            Al[mf][0], Al[mf][1], Al[mf][2], Al[mf][3], Bh[nfp][0], Bh[nfp][2]);
                    MMA_F16(acc[mf][2*nfp+1][0], acc[mf][2*nfp+1][1], acc[mf][2*nfp+1][2], acc[mf][2*nfp+1][3],
                            Al[mf][0], Al[mf][1], Al[mf][2], Al[mf][3], Bh[nfp][1], Bh[nfp][3]);
                }
        }

        __syncthreads();
        if (c + 2 < NCHG) load_stage((c + 2) * BKC, c & 1);
    }

    const int r2 = lid >> 2;
    const int c2 = (lid & 3) * 2;
#pragma unroll
    for (int mf = 0; mf < 4; mf++) {
        const int row = m0 + wm * 64 + mf * 16 + r2;
#pragma unroll
        for (int nf = 0; nf < 4; nf++) {
            float* cp0 = C + (size_t)row * ldc + coff + n0 + wn * 32 + nf * 8 + c2;
            *(float2*)cp0 = make_float2(acc[mf][nf][0], acc[mf][nf][1]);
            *(float2*)(cp0 + 8 * (size_t)ldc) = make_float2(acc[mf][nf][2], acc[mf][nf][3]);
        }
    }
}

// ---------------- fused q-rms + k-rms + v, vectorized float4 ----------------
__global__ __launch_bounds__(256) void prep_qkv(
    const float* __restrict__ qw, const float* __restrict__ kw)
{
    const int t = blockIdx.x;
    const int b = t >> 11, s = t & (SS - 1);
    const float* row = g_xqkv + (size_t)t * QKVW;
    const int tid = threadIdx.x;

    // q: one float4 per thread (256*4 = 1024)
    float4 q4 = *(const float4*)(row + tid * 4);
    float ssq = q4.x * q4.x;
    ssq = fmaf(q4.y, q4.y, ssq);
    ssq = fmaf(q4.z, q4.z, ssq);
    ssq = fmaf(q4.w, q4.w, ssq);

    // k: threads 0..63, v: threads 64..127
    float4 kv4 = make_float4(0.f, 0.f, 0.f, 0.f);
    float ssk = 0.f;
    if (tid < 64) {
        kv4 = *(const float4*)(row + 1024 + tid * 4);
        ssk = kv4.x * kv4.x;
        ssk = fmaf(kv4.y, kv4.y, ssk);
        ssk = fmaf(kv4.z, kv4.z, ssk);
        ssk = fmaf(kv4.w, kv4.w, ssk);
    } else if (tid < 128) {
        kv4 = *(const float4*)(row + 1280 + (tid - 64) * 4);
    }

#pragma unroll
    for (int o = 16; o > 0; o >>= 1) {
        ssq += __shfl_xor_sync(0xffffffffu, ssq, o);
        ssk += __shfl_xor_sync(0xffffffffu, ssk, o);
    }

    __shared__ float redq[8], redk[8];
    __shared__ float sclq_s, sclk_s;
    if ((tid & 31) == 0) { redq[tid >> 5] = ssq; redk[tid >> 5] = ssk; }
    __syncthreads();
    if (tid == 0) {
        float tq = 0.f, tk = 0.f;
#pragma unroll
        for (int i = 0; i < 8; i++) { tq += redq[i]; tk += redk[i]; }
        sclq_s = rsqrtf(tq * (1.f / 1024.f) + 1e-6f) * (0.125f * LOG2E);
        sclk_s = rsqrtf(tk * (1.f / 256.f) + 1e-6f);
    }
    __syncthreads();
    const float sclq = sclq_s, sclk = sclk_s;

    // q write: 4 contiguous dims, same head (64 % 4 == 0)
    {
        float4 qwv = *(const float4*)(qw + tid * 4);
        float v0 = q4.x * sclq * qwv.x;
        float v1 = q4.y * sclq * qwv.y;
        float v2 = q4.z * sclq * qwv.z;
        float v3 = q4.w * sclq * qwv.w;
        float h0 = __half2float(__float2half(v0));
        float h1 = __half2float(__float2half(v1));
        float h2 = __half2float(__float2half(v2));
        float h3 = __half2float(__float2half(v3));
        int idx = tid * 4;
        int head = idx >> 6, d = idx & 63;
        size_t off = ((size_t)(b * NH + head) * SS + s) * 64 + d;
        *(uint2*)(g_qh + off) = make_uint2(packh(v0, v1), packh(v2, v3));
        *(uint2*)(g_ql + off) = make_uint2(packh(v0 - h0, v1 - h1), packh(v2 - h2, v3 - h3));
    }

    if (tid < 64) {
        int idx = tid * 4;
        int kv = idx >> 6, d = idx & 63;
        float4 kwv = *(const float4*)(kw + idx);
        float v0 = kv4.x * sclk * kwv.x;
        float v1 = kv4.y * sclk * kwv.y;
        float v2 = kv4.z * sclk * kwv.z;
        float v3 = kv4.w * sclk * kwv.w;
        size_t off = ((size_t)(b * NKV + kv) * SS + s) * 64 + d;
        *(uint2*)(g_kh + off) = make_uint2(packh(v0, v1), packh(v2, v3));
    } else if (tid < 128) {
        int idx = (tid - 64) * 4;
        int kv = idx >> 6, d = idx & 63;
        size_t off = ((size_t)(b * NKV + kv) * SS + s) * 64 + d;
        *(uint2*)(g_vh + off) = make_uint2(packh(kv4.x, kv4.y), packh(kv4.z, kv4.w));
    }
}

// ---------------- tensor-core attention (log2 domain, fp16 2-pass, g-skip) ----------------
#define TILEB 9216                    // 64*144
#define ATT_SMEM (2 * 2 * TILEB)      // 2 stages x (Kh, Vh) = 36864

__global__ __launch_bounds__(256, 2) void attn_tc()
{
    extern __shared__ char asm_[];
    const uint32_t smb = smem_u32(asm_);

    const int tid = threadIdx.x;
    const int wid = tid >> 5;
    const int lid = tid & 31;
    const int qstart = blockIdx.x * 128;
    const int head = blockIdx.y;
    const int b = blockIdx.z;
    const int kvh = head >> 2;

    const int r = lid >> 2;
    const int c2 = (lid & 3) * 2;
    const int qpos0 = qstart + wid * 16 + r;
    const int wqmin = qstart + wid * 16;
    const int wqmax = wqmin + 15;
    const float slope = exp2f(-0.5f * (float)(head + 1)) * LOG2E;

    const __half* qbh = g_qh + ((size_t)(b * NH + head) * SS + qstart + wid * 16) * 64;
    const __half* qbl = g_ql + ((size_t)(b * NH + head) * SS + qstart + wid * 16) * 64;
    uint32_t Qh[4][4];
#pragma unroll
    for (int ks = 0; ks < 4; ks++) {
        Qh[ks][0] = *(const uint32_t*)(qbh + r * 64 + ks * 16 + c2);
        Qh[ks][1] = *(const uint32_t*)(qbh + (r + 8) * 64 + ks * 16 + c2);
        Qh[ks][2] = *(const uint32_t*)(qbh + r * 64 + ks * 16 + 8 + c2);
        Qh[ks][3] = *(const uint32_t*)(qbh + (r + 8) * 64 + ks * 16 + 8 + c2);
    }

    float O[8][4];
#pragma unroll
    for (int i = 0; i < 8; i++)
#pragma unroll
        for (int j = 0; j < 4; j++) O[i][j] = 0.f;
    float m0 = -INFINITY, m1 = -INFINITY, l0 = 0.f, l1 = 0.f;

    const int kc0 = (qstart >= WIN) ? qstart - WIN : 0;
    const int nch = (qstart + 128 - kc0) >> 6;

    const int key_ld = tid >> 2;
    const int seg = tid & 3;
    const __half* src_base[2];
    {
        size_t kvb = ((size_t)(b * NKV + kvh) * SS) * 64;
        src_base[0] = g_kh + kvb;
        src_base[1] = g_vh + kvb;
    }
    auto load_chunk = [&](int kc, int stg) {
        uint32_t sb = smb + stg * 2 * TILEB + key_ld * 144 + seg * 16;
#pragma unroll
        for (int t = 0; t < 2; t++) {
            const __half* src = src_base[t] + (size_t)(kc + key_ld) * 64 + seg * 8;
            cp16(sb + t * TILEB, src);
            cp16(sb + t * TILEB + 64, src + 32);
        }
        cp_commit();
    };

    load_chunk(kc0, 0);
    if (nch > 1) load_chunk(kc0 + 64, 1);

    const uint32_t lane_off = (uint32_t)(((lid >> 4) * 8 + (lid & 7)) * 144 + ((lid >> 3) & 1) * 16);

    for (int c = 0; c < nch; c++) {
        if (c < nch - 1) cp_wait<1>(); else cp_wait<0>();
        __syncthreads();

        const uint32_t sb = smb + (c & 1) * 2 * TILEB;
        const int kc = kc0 + c * 64;

        const bool active = (kc <= wqmax) && (kc + 63 >= wqmin - WIN);
        if (active) {

        // per-g (32-key group) skip flags: fully causal-masked or fully out of window
        bool gok[2];
#pragma unroll
        for (int g = 0; g < 2; g++) {
            int gk0 = kc + g * 32;
            gok[g] = (gk0 <= wqmax) && (gk0 + 31 >= wqmin - WIN);
        }

        // ---- scores: S = Qh*Kh + Ql*Kh ----
        float S[8][4];
#pragma unroll
        for (int i = 0; i < 8; i++)
#pragma unroll
            for (int j = 0; j < 4; j++) S[i][j] = 0.f;

#pragma unroll
        for (int ks = 0; ks < 4; ks++) {
            uint32_t Qlr[4];
            Qlr[0] = *(const uint32_t*)(qbl + r * 64 + ks * 16 + c2);
            Qlr[1] = *(const uint32_t*)(qbl + (r + 8) * 64 + ks * 16 + c2);
            Qlr[2] = *(const uint32_t*)(qbl + r * 64 + ks * 16 + 8 + c2);
            Qlr[3] = *(const uint32_t*)(qbl + (r + 8) * 64 + ks * 16 + 8 + c2);
#pragma unroll
            for (int g = 0; g < 2; g++) {
                if (!gok[g]) continue;
                uint32_t kh[2][4];
#pragma unroll
                for (int j = 0; j < 2; j++) {
                    int nfp = g * 2 + j;
                    LDMX4(kh[j][0], kh[j][1], kh[j][2], kh[j][3],
                          sb + nfp * 2304 + ks * 32 + lane_off);
                }
#pragma unroll
                for (int j = 0; j < 2; j++) {
                    int nf = (g * 2 + j) * 2;
                    MMA_F16(S[nf][0], S[nf][1], S[nf][2], S[nf][3],
                            Qh[ks][0], Qh[ks][1], Qh[ks][2], Qh[ks][3], kh[j][0], kh[j][1]);
                    MMA_F16(S[nf+1][0], S[nf+1][1], S[nf+1][2], S[nf+1][3],
                            Qh[ks][0], Qh[ks][1], Qh[ks][2], Qh[ks][3], kh[j][2], kh[j][3]);
                }
#pragma unroll
                for (int j = 0; j < 2; j++) {
                    int nf = (g * 2 + j) * 2;
                    MMA_F16(S[nf][0], S[nf][1], S[nf][2], S[nf][3],
                            Qlr[0], Qlr[1], Qlr[2], Qlr[3], kh[j][0], kh[j][1]);
                    MMA_F16(S[nf+1][0], S[nf+1][1], S[nf+1][2], S[nf+1][3],
                            Qlr[0], Qlr[1], Qlr[2], Qlr[3], kh[j][2], kh[j][3]);
                }
            }
        }

        // ---- bias + mask ----
#pragma unroll
        for (int nf = 0; nf < 8; nf++) {
            int rel0 = kc + nf * 8 + c2 - qpos0;
            int rel2 = rel0 - 8;
            S[nf][0] = (rel0     <= 0 && rel0     >= -WIN) ? fmaf(slope, (float)rel0,     S[nf][0]) : -INFINITY;
            S[nf][1] = (rel0 + 1 <= 0 && rel0 + 1 >= -WIN) ? fmaf(slope, (float)(rel0+1), S[nf][1]) : -INFINITY;
            S[nf][2] = (rel2     <= 0 && rel2     >= -WIN) ? fmaf(slope, (float)rel2,     S[nf][2]) : -INFINITY;
            S[nf][3] = (rel2 + 1 <= 0 && rel2 + 1 >= -WIN) ? fmaf(slope, (float)(rel2+1), S[nf][3]) : -INFINITY;
        }

        // ---- online softmax (exp2) ----
        float mx0 = -INFINITY, mx1 = -INFINITY;
#pragma unroll
        for (int nf = 0; nf < 8; nf++) {
            mx0 = fmaxf(mx0, fmaxf(S[nf][0], S[nf][1]));
            mx1 = fmaxf(mx1, fmaxf(S[nf][2], S[nf][3]));
        }
        mx0 = fmaxf(mx0, __shfl_xor_sync(0xffffffffu, mx0, 1));
        mx0 = fmaxf(mx0, __shfl_xor_sync(0xffffffffu, mx0, 2));
        mx1 = fmaxf(mx1, __shfl_xor_sync(0xffffffffu, mx1, 1));
        mx1 = fmaxf(mx1, __shfl_xor_sync(0xffffffffu, mx1, 2));

        float mn0 = fmaxf(fmaxf(m0, mx0), -1e30f);
        float mn1 = fmaxf(fmaxf(m1, mx1), -1e30f);
        float a0 = exp2f(m0 - mn0);
        float a1 = exp2f(m1 - mn1);
        m0 = mn0; m1 = mn1;
        l0 *= a0; l1 *= a1;
#pragma unroll
        for (int nf = 0; nf < 8; nf++) {
            O[nf][0] *= a0; O[nf][1] *= a0;
            O[nf][2] *= a1; O[nf][3] *= a1;
        }
#pragma unroll
        for (int nf = 0; nf < 8; nf++) {
            S[nf][0] = exp2f(S[nf][0] - m0);
            S[nf][1] = exp2f(S[nf][1] - m0);
            S[nf][2] = exp2f(S[nf][2] - m1);
            S[nf][3] = exp2f(S[nf][3] - m1);
            l0 += S[nf][0] + S[nf][1];
            l1 += S[nf][2] + S[nf][3];
        }

        // ---- PV: O += Ph*Vh + Pl*Vh ----
#pragma unroll
        for (int ks = 0; ks < 4; ks++) {
            float x00 = S[2*ks][0],   x01 = S[2*ks][1],   x02 = S[2*ks][2],   x03 = S[2*ks][3];
            float x10 = S[2*ks+1][0], x11 = S[2*ks+1][1], x12 = S[2*ks+1][2], x13 = S[2*ks+1][3];
            // skip whole ks if this 16-key span is fully masked (P==0 there)
            int kk0 = kc + ks * 16;
            if (kk0 > wqmax || kk0 + 15 < wqmin - WIN) continue;
            float h00 = __half2float(__float2half(x00));
            float h01 = __half2float(__float2half(x01));
            float h02 = __half2float(__float2half(x02));
            float h03 = __half2float(__float2half(x03));
            float h10 = __half2float(__float2half(x10));
            float h11 = __half2float(__float2half(x11));
            float h12 = __half2float(__float2half(x12));
            float h13 = __half2float(__float2half(x13));
            uint32_t ph0 = packh(x00, x01), ph1 = packh(x02, x03);
            uint32_t ph2 = packh(x10, x11), ph3 = packh(x12, x13);
            uint32_t pl0 = packh(x00 - h00, x01 - h01), pl1 = packh(x02 - h02, x03 - h03);
            uint32_t pl2 = packh(x10 - h10, x11 - h11), pl3 = packh(x12 - h12, x13 - h13);
#pragma unroll
            for (int g = 0; g < 2; g++) {
                uint32_t v[2][4];
#pragma unroll
                for (int j = 0; j < 2; j++) {
                    int nfp = g * 2 + j;
                    LDMX4T(v[j][0], v[j][1], v[j][2], v[j][3],
                           sb + TILEB + ks * 2304 + nfp * 32 + lane_off);
                }
#pragma unroll
                for (int j = 0; j < 2; j++) {
                    int nf = (g * 2 + j) * 2;
                    MMA_F16(O[nf][0], O[nf][1], O[nf][2], O[nf][3],
                            ph0, ph1, ph2, ph3, v[j][0], v[j][2]);
                    MMA_F16(O[nf+1][0], O[nf+1][1], O[nf+1][2], O[nf+1][3],
                            ph0, ph1, ph2, ph3, v[j][1], v[j][3]);
                }
#pragma unroll
                for (int j = 0; j < 2; j++) {
                    int nf = (g * 2 + j) * 2;
                    MMA_F16(O[nf][0], O[nf][1], O[nf][2], O[nf][3],
                            pl0, pl1, pl2, pl3, v[j][0], v[j][2]);
                    MMA_F16(O[nf+1][0], O[nf+1][1], O[nf+1][2], O[nf+1][3],
                            pl0, pl1, pl2, pl3, v[j][1], v[j][3]);
                }
            }
        }

        }  // active

        __syncthreads();
        if (c + 2 < nch) load_chunk(kc0 + (c + 2) * 64, c & 1);
    }

    // ---- epilogue ----
    l0 += __shfl_xor_sync(0xffffffffu, l0, 1);
    l0 += __shfl_xor_sync(0xffffffffu, l0, 2);
    l1 += __shfl_xor_sync(0xffffffffu, l1, 1);
    l1 += __shfl_xor_sync(0xffffffffu, l1, 2);
    float inv0 = 1.f / l0, inv1 = 1.f / l1;

    size_t out0 = ((size_t)(b * SS + qpos0) * DIM) + head * 64;
    size_t out1 = out0 + (size_t)8 * DIM;
#pragma unroll
    for (int nf = 0; nf < 8; nf++) {
        float y0 = O[nf][0] * inv0, y1 = O[nf][1] * inv0;
        float y2 = O[nf][2] * inv1, y3 = O[nf][3] * inv1;
        int col = nf * 8 + c2;
        float h0 = __half2float(__float2half(y0));
        float h1 = __half2float(__float2half(y1));
        float h2 = __half2float(__float2half(y2));
        float h3 = __half2float(__float2half(y3));
        *(uint32_t*)(g_ah + out0 + col) = packh(y0, y1);
        *(uint32_t*)(g_al + out0 + col) = packh(y0 - h0, y1 - h1);
        *(uint32_t*)(g_ah + out1 + col) = packh(y2, y3);
        *(uint32_t*)(g_al + out1 + col) = packh(y2 - h2, y3 - h3);
    }
}

// ---------------- launch ----------------
extern "C" void kernel_launch(void* const* d_in, const int* in_sizes, int n_in,
                              void* d_out, int out_size)
{
    const float* x  = (const float*)d_in[0];
    const float* wq = (const float*)d_in[1];
    const float* wk = (const float*)d_in[2];
    const float* wv = (const float*)d_in[3];
    const float* wo = (const float*)d_in[4];
    const float* qw = (const float*)d_in[5];
    const float* kw = (const float*)d_in[6];
    float* out = (float*)d_out;

    float* xqkv = nullptr;
    __half *ah = nullptr, *al = nullptr, *wh = nullptr;
    cudaGetSymbolAddress((void**)&xqkv, g_xqkv);
    cudaGetSymbolAddress((void**)&ah, g_ah);
    cudaGetSymbolAddress((void**)&al, g_al);
    cudaGetSymbolAddress((void**)&wh, g_wh);

    static bool attr_done = false;
    if (!attr_done) {
        cudaFuncSetAttribute(hmma_gemm, cudaFuncAttributeMaxDynamicSharedMemorySize, GEMM_SMEM);
        cudaFuncSetAttribute(attn_tc, cudaFuncAttributeMaxDynamicSharedMemorySize, ATT_SMEM);
        attr_done = true;
    }

    split_all<<<(1048576 + 655360) / 256, 256>>>(x, wq, wk, wv, wo);
    hmma_gemm<<<dim3(QKVW / 128, TT / 128), 256, GEMM_SMEM>>>(ah, al, wh, xqkv, QKVW, 0);
    prep_qkv<<<TT, 256>>>(qw, kw);
    attn_tc<<<dim3(SS / 128, NH, BB), 256, ATT_SMEM>>>();
    hmma_gemm<<<dim3(DIM / 128, TT / 128), 256, GEMM_SMEM>>>(
        ah, al, wh + (size_t)WO_ROW * DIM, out, DIM, 0);
}

// round 11
// speedup vs baseline: 1.4574x; 1.0006x over previous
#include <cuda_runtime.h>
#include <cuda_fp16.h>
#include <math.h>
#include <stdint.h>

#define DIM   1024
#define NH    16
#define NKV   4
#define HD    64
#define WIN   512
#define BB    2
#define SS    2048
#define TT    (BB*SS)
#define QKVW  1536   // 1024 q | 256 k | 256 v per token
#define GK    1024   // K dim of every GEMM
#define LOG2E 1.4426950408889634f

// ---------------- scratch (no allocs allowed) ----------------
__device__ float g_xqkv[(size_t)TT * QKVW];        // fp32 qkv projections
__device__ __half g_ah[(size_t)TT * DIM];          // activation hi (x, then attn out)
__device__ __half g_al[(size_t)TT * DIM];          // activation lo
__device__ __half g_wh[(size_t)2560 * DIM];        // weights fp16 (single): wq|wk|wv|wo
__device__ __half g_qh[(size_t)TT * DIM];          // per-head Q hi  [(b*NH+h)*SS+s][64]
__device__ __half g_ql[(size_t)TT * DIM];          // per-head Q lo
__device__ __half g_kh[(size_t)TT * 256];          // per-kvhead K fp16 (single)
__device__ __half g_vh[(size_t)TT * 256];          // per-kvhead V fp16 (single)
#define WO_ROW 1536

// ---------------- small PTX helpers ----------------
__device__ __forceinline__ uint32_t smem_u32(const void* p) {
    uint32_t a;
    asm("{ .reg .u64 t; cvta.to.shared.u64 t, %1; cvt.u32.u64 %0, t; }" : "=r"(a) : "l"(p));
    return a;
}
__device__ __forceinline__ void cp16(uint32_t s, const void* g) {
    asm volatile("{ .reg .u64 gg; cvta.to.global.u64 gg, %1; cp.async.cg.shared.global [%0], [gg], 16; }"
                 :: "r"(s), "l"(g) : "memory");
}
__device__ __forceinline__ void cp_commit() { asm volatile("cp.async.commit_group;" ::: "memory"); }
template <int N>
__device__ __forceinline__ void cp_wait() { asm volatile("cp.async.wait_group %0;" :: "n"(N) : "memory"); }

__device__ __forceinline__ uint32_t packh(float lo, float hi) {
    uint32_t r;
    asm("cvt.rn.f16x2.f32 %0, %1, %2;" : "=r"(r) : "f"(hi), "f"(lo));
    return r;
}
// fast exp2: single MUFU.EX2 (harness builds without fast-math, so exp2f is slow-path)
__device__ __forceinline__ float ex2(float x) {
    float y;
    asm("ex2.approx.ftz.f32 %0, %1;" : "=f"(y) : "f"(x));
    return y;
}

#define MMA_F16(c0,c1,c2,c3, a0,a1,a2,a3, b0,b1) \
    asm volatile("mma.sync.aligned.m16n8k16.row.col.f32.f16.f16.f32 " \
                 "{%0,%1,%2,%3}, {%4,%5,%6,%7}, {%8,%9}, {%0,%1,%2,%3};" \
                 : "+f"(c0), "+f"(c1), "+f"(c2), "+f"(c3) \
                 : "r"(a0), "r"(a1), "r"(a2), "r"(a3), "r"(b0), "r"(b1))

#define LDMX4(r0,r1,r2,r3, addr) \
    asm volatile("ldmatrix.sync.aligned.m8n8.x4.shared.b16 {%0,%1,%2,%3}, [%4];" \
                 : "=r"(r0), "=r"(r1), "=r"(r2), "=r"(r3) : "r"(addr))
#define LDMX4T(r0,r1,r2,r3, addr) \
    asm volatile("ldmatrix.sync.aligned.m8n8.x4.trans.shared.b16 {%0,%1,%2,%3}, [%4];" \
                 : "=r"(r0), "=r"(r1), "=r"(r2), "=r"(r3) : "r"(addr))

// ---------------- fused splits: x -> hi/lo fp16, all weights -> fp16 ----------------
__global__ __launch_bounds__(256) void split_all(
    const float* __restrict__ x,
    const float* __restrict__ wq, const float* __restrict__ wk,
    const float* __restrict__ wv, const float* __restrict__ wo)
{
    int i = blockIdx.x * 256 + threadIdx.x;
    if (i < 1048576) {
        float4 v = ((const float4*)x)[i];
        float f[4] = {v.x, v.y, v.z, v.w};
        union { __half b[4]; uint2 u; } H, L;
#pragma unroll
        for (int k = 0; k < 4; k++) {
            __half h = __float2half(f[k]);
            H.b[k] = h;
            L.b[k] = __float2half(f[k] - __half2float(h));
        }
        ((uint2*)g_ah)[i] = H.u;
        ((uint2*)g_al)[i] = L.u;
    } else {
        int j = i - 1048576;
        const float* src;
        int local;
        if (j < 262144)      { src = wq; local = j; }
        else if (j < 327680) { src = wk; local = j - 262144; }
        else if (j < 393216) { src = wv; local = j - 327680; }
        else                 { src = wo; local = j - 393216; }
        float4 v = ((const float4*)src)[local];
        union { __half b[4]; uint2 u; } H;
        H.b[0] = __float2half(v.x); H.b[1] = __float2half(v.y);
        H.b[2] = __float2half(v.z); H.b[3] = __float2half(v.w);
        ((uint2*)g_wh)[j] = H.u;
    }
}

// ---------------- HMMA fp16 2-pass GEMM: BK=64, 2-stage cp.async, 2 CTAs/SM ----------------
#define BKC 64
#define NCHG (GK / BKC)          // 16
#define SROWG 72                 // halves per row (64 data + 8 pad -> 144B)
#define TILEG (128 * SROWG)      // halves per tile
#define STAGEG (3 * TILEG)       // Ah, Al, Bh
#define GEMM_SMEM (2 * STAGEG * 2)   // 110592 bytes -> 2 CTAs/SM

__global__ __launch_bounds__(256, 2) void hmma_gemm(
    const __half* __restrict__ ah, const __half* __restrict__ al,
    const __half* __restrict__ bh,
    float* __restrict__ C, int ldc, int coff)
{
    extern __shared__ char smraw[];
    const uint32_t smb = smem_u32(smraw);

    const int tid = threadIdx.x;
    const int wid = tid >> 5;
    const int lid = tid & 31;
    const int wm = wid & 1;
    const int wn = wid >> 1;
    const int m0 = blockIdx.y * 128;
    const int n0 = blockIdx.x * 128;

    const __half* gbase[3];
    gbase[0] = ah + (size_t)m0 * GK;
    gbase[1] = al + (size_t)m0 * GK;
    gbase[2] = bh + (size_t)n0 * GK;

    auto load_stage = [&](int kc, int stg) {
        const uint32_t base = smb + (uint32_t)stg * (STAGEG * 2);
#pragma unroll
        for (int i = 0; i < 4; i++) {
            int id = tid + 256 * i;
            int row = id >> 3, seg = id & 7;
            uint32_t soff = (uint32_t)(row * SROWG + seg * 8) * 2;
#pragma unroll
            for (int t = 0; t < 3; t++) {
                const __half* src = gbase[t] + (size_t)row * GK + kc + seg * 8;
                cp16(base + (uint32_t)t * (TILEG * 2) + soff, src);
            }
        }
        cp_commit();
    };

    float acc[4][4][4];
#pragma unroll
    for (int i = 0; i < 4; i++)
#pragma unroll
        for (int j = 0; j < 4; j++)
#pragma unroll
            for (int k = 0; k < 4; k++) acc[i][j][k] = 0.f;

    const uint32_t frag_off =
        (uint32_t)((((lid & 7) + ((lid >> 3) & 1) * 8) * SROWG + (lid >> 4) * 8) * 2);

    load_stage(0, 0);
    load_stage(BKC, 1);

    for (int c = 0; c < NCHG; c++) {
        if (c < NCHG - 1) cp_wait<1>(); else cp_wait<0>();
        __syncthreads();

        const uint32_t sbase = smb + (uint32_t)(c & 1) * (STAGEG * 2);

#pragma unroll
        for (int ks = 0; ks < 4; ks++) {
            uint32_t Ah[4][4], Al[4][4], Bh[2][4];
#pragma unroll
            for (int mf = 0; mf < 4; mf++) {
                uint32_t aaddr = sbase +
                    (uint32_t)(((wm * 64 + mf * 16) * SROWG + ks * 16) * 2) + frag_off;
                LDMX4(Ah[mf][0], Ah[mf][1], Ah[mf][2], Ah[mf][3], aaddr);
                LDMX4(Al[mf][0], Al[mf][1], Al[mf][2], Al[mf][3], aaddr + TILEG * 2);
            }
#pragma unroll
            for (int nfp = 0; nfp < 2; nfp++) {
                uint32_t baddr = sbase + 2u * (TILEG * 2) +
                    (uint32_t)(((wn * 32 + nfp * 16) * SROWG + ks * 16) * 2) + frag_off;
                LDMX4(Bh[nfp][0], Bh[nfp][1], Bh[nfp][2], Bh[nfp][3], baddr);
            }

#pragma unroll
            for (int nfp = 0; nfp < 2; nfp++)
#pragma unroll
                for (int mf = 0; mf < 4; mf++) {
                    MMA_F16(acc[mf][2*nfp][0], acc[mf][2*nfp][1], acc[mf][2*nfp][2], acc[mf][2*nfp][3],
                            Ah[mf][0], Ah[mf][1], Ah[mf][2], Ah[mf][3], Bh[nfp][0], Bh[nfp][2]);
                    MMA_F16(acc[mf][2*nfp+1][0], acc[mf][2*nfp+1][1], acc[mf][2*nfp+1][2], acc[mf][2*nfp+1][3],
                            Ah[mf][0], Ah[mf][1], Ah[mf][2], Ah[mf][3], Bh[nfp][1], Bh[nfp][3]);
                }
#pragma unroll
            for (int nfp = 0; nfp < 2; nfp++)
#pragma unroll
                for (int mf = 0; mf < 4; mf++) {
                    MMA_F16(acc[mf][2*nfp][0], acc[mf][2*nfp][1], acc[mf][2*nfp][2], acc[mf][2*nfp][3],
                            Al[mf][0], Al[mf][1], Al[mf][2], Al[mf][3], Bh[nfp][0], Bh[nfp][2]);
                    MMA_F16(acc[mf][2*nfp+1][0], acc[mf][2*nfp+1][1], acc[mf][2*nfp+1][2], acc[mf][2*nfp+1][3],
                            Al[mf][0], Al[mf][1], Al[mf][2], Al[mf][3], Bh[nfp][1], Bh[nfp][3]);
                }
        }

        __syncthreads();
        if (c + 2 < NCHG) load_stage((c + 2) * BKC, c & 1);
    }

    const int r2 = lid >> 2;
    const int c2 = (lid & 3) * 2;
#pragma unroll
    for (int mf = 0; mf < 4; mf++) {
        const int row = m0 + wm * 64 + mf * 16 + r2;
#pragma unroll
        for (int nf = 0; nf < 4; nf++) {
            float* cp0 = C + (size_t)row * ldc + coff + n0 + wn * 32 + nf * 8 + c2;
            *(float2*)cp0 = make_float2(acc[mf][nf][0], acc[mf][nf][1]);
            *(float2*)(cp0 + 8 * (size_t)ldc) = make_float2(acc[mf][nf][2], acc[mf][nf][3]);
        }
    }
}

// ---------------- fused q-rms + k-rms + v, vectorized float4 ----------------
__global__ __launch_bounds__(256) void prep_qkv(
    const float* __restrict__ qw, const float* __restrict__ kw)
{
    const int t = blockIdx.x;
    const int b = t >> 11, s = t & (SS - 1);
    const float* row = g_xqkv + (size_t)t * QKVW;
    const int tid = threadIdx.x;

    float4 q4 = *(const float4*)(row + tid * 4);
    float ssq = q4.x * q4.x;
    ssq = fmaf(q4.y, q4.y, ssq);
    ssq = fmaf(q4.z, q4.z, ssq);
    ssq = fmaf(q4.w, q4.w, ssq);

    float4 kv4 = make_float4(0.f, 0.f, 0.f, 0.f);
    float ssk = 0.f;
    if (tid < 64) {
        kv4 = *(const float4*)(row + 1024 + tid * 4);
        ssk = kv4.x * kv4.x;
        ssk = fmaf(kv4.y, kv4.y, ssk);
        ssk = fmaf(kv4.z, kv4.z, ssk);
        ssk = fmaf(kv4.w, kv4.w, ssk);
    } else if (tid < 128) {
        kv4 = *(const float4*)(row + 1280 + (tid - 64) * 4);
    }

#pragma unroll
    for (int o = 16; o > 0; o >>= 1) {
        ssq += __shfl_xor_sync(0xffffffffu, ssq, o);
        ssk += __shfl_xor_sync(0xffffffffu, ssk, o);
    }

    __shared__ float redq[8], redk[8];
    __shared__ float sclq_s, sclk_s;
    if ((tid & 31) == 0) { redq[tid >> 5] = ssq; redk[tid >> 5] = ssk; }
    __syncthreads();
    if (tid == 0) {
        float tq = 0.f, tk = 0.f;
#pragma unroll
        for (int i = 0; i < 8; i++) { tq += redq[i]; tk += redk[i]; }
        sclq_s = rsqrtf(tq * (1.f / 1024.f) + 1e-6f) * (0.125f * LOG2E);
        sclk_s = rsqrtf(tk * (1.f / 256.f) + 1e-6f);
    }
    __syncthreads();
    const float sclq = sclq_s, sclk = sclk_s;

    {
        float4 qwv = *(const float4*)(qw + tid * 4);
        float v0 = q4.x * sclq * qwv.x;
        float v1 = q4.y * sclq * qwv.y;
        float v2 = q4.z * sclq * qwv.z;
        float v3 = q4.w * sclq * qwv.w;
        float h0 = __half2float(__float2half(v0));
        float h1 = __half2float(__float2half(v1));
        float h2 = __half2float(__float2half(v2));
        float h3 = __half2float(__float2half(v3));
        int idx = tid * 4;
        int head = idx >> 6, d = idx & 63;
        size_t off = ((size_t)(b * NH + head) * SS + s) * 64 + d;
        *(uint2*)(g_qh + off) = make_uint2(packh(v0, v1), packh(v2, v3));
        *(uint2*)(g_ql + off) = make_uint2(packh(v0 - h0, v1 - h1), packh(v2 - h2, v3 - h3));
    }

    if (tid < 64) {
        int idx = tid * 4;
        int kv = idx >> 6, d = idx & 63;
        float4 kwv = *(const float4*)(kw + idx);
        float v0 = kv4.x * sclk * kwv.x;
        float v1 = kv4.y * sclk * kwv.y;
        float v2 = kv4.z * sclk * kwv.z;
        float v3 = kv4.w * sclk * kwv.w;
        size_t off = ((size_t)(b * NKV + kv) * SS + s) * 64 + d;
        *(uint2*)(g_kh + off) = make_uint2(packh(v0, v1), packh(v2, v3));
    } else if (tid < 128) {
        int idx = (tid - 64) * 4;
        int kv = idx >> 6, d = idx & 63;
        size_t off = ((size_t)(b * NKV + kv) * SS + s) * 64 + d;
        *(uint2*)(g_vh + off) = make_uint2(packh(kv4.x, kv4.y), packh(kv4.z, kv4.w));
    }
}

// ---------------- tensor-core attention (log2 domain, fast ex2, group-skip softmax) ----------------
#define TILEB 9216                    // 64*144
#define ATT_SMEM (2 * 2 * TILEB)      // 36864

__global__ __launch_bounds__(256, 2) void attn_tc()
{
    extern __shared__ char asm_[];
    const uint32_t smb = smem_u32(asm_);

    const int tid = threadIdx.x;
    const int wid = tid >> 5;
    const int lid = tid & 31;
    const int qstart = blockIdx.x * 128;
    const int head = blockIdx.y;
    const int b = blockIdx.z;
    const int kvh = head >> 2;

    const int r = lid >> 2;
    const int c2 = (lid & 3) * 2;
    const int qpos0 = qstart + wid * 16 + r;
    const int wqmin = qstart + wid * 16;
    const int wqmax = wqmin + 15;
    const float slope = exp2f(-0.5f * (float)(head + 1)) * LOG2E;

    const __half* qbh = g_qh + ((size_t)(b * NH + head) * SS + qstart + wid * 16) * 64;
    const __half* qbl = g_ql + ((size_t)(b * NH + head) * SS + qstart + wid * 16) * 64;
    uint32_t Qh[4][4];
#pragma unroll
    for (int ks = 0; ks < 4; ks++) {
        Qh[ks][0] = *(const uint32_t*)(qbh + r * 64 + ks * 16 + c2);
        Qh[ks][1] = *(const uint32_t*)(qbh + (r + 8) * 64 + ks * 16 + c2);
        Qh[ks][2] = *(const uint32_t*)(qbh + r * 64 + ks * 16 + 8 + c2);
        Qh[ks][3] = *(const uint32_t*)(qbh + (r + 8) * 64 + ks * 16 + 8 + c2);
    }

    float O[8][4];
#pragma unroll
    for (int i = 0; i < 8; i++)
#pragma unroll
        for (int j = 0; j < 4; j++) O[i][j] = 0.f;
    float m0 = -INFINITY, m1 = -INFINITY, l0 = 0.f, l1 = 0.f;

    const int kc0 = (qstart >= WIN) ? qstart - WIN : 0;
    const int nch = (qstart + 128 - kc0) >> 6;

    const int key_ld = tid >> 2;
    const int seg = tid & 3;
    const __half* src_base[2];
    {
        size_t kvb = ((size_t)(b * NKV + kvh) * SS) * 64;
        src_base[0] = g_kh + kvb;
        src_base[1] = g_vh + kvb;
    }
    auto load_chunk = [&](int kc, int stg) {
        uint32_t sb = smb + stg * 2 * TILEB + key_ld * 144 + seg * 16;
#pragma unroll
        for (int t = 0; t < 2; t++) {
            const __half* src = src_base[t] + (size_t)(kc + key_ld) * 64 + seg * 8;
            cp16(sb + t * TILEB, src);
            cp16(sb + t * TILEB + 64, src + 32);
        }
        cp_commit();
    };

    load_chunk(kc0, 0);
    if (nch > 1) load_chunk(kc0 + 64, 1);

    const uint32_t lane_off = (uint32_t)(((lid >> 4) * 8 + (lid & 7)) * 144 + ((lid >> 3) & 1) * 16);

    for (int c = 0; c < nch; c++) {
        if (c < nch - 1) cp_wait<1>(); else cp_wait<0>();
        __syncthreads();

        const uint32_t sb = smb + (c & 1) * 2 * TILEB;
        const int kc = kc0 + c * 64;

        const bool active = (kc <= wqmax) && (kc + 63 >= wqmin - WIN);
        if (active) {

        bool gok[2];
#pragma unroll
        for (int g = 0; g < 2; g++) {
            int gk0 = kc + g * 32;
            gok[g] = (gk0 <= wqmax) && (gk0 + 31 >= wqmin - WIN);
        }

        // ---- scores: S = Qh*Kh + Ql*Kh ----
        float S[8][4];
#pragma unroll
        for (int i = 0; i < 8; i++)
#pragma unroll
            for (int j = 0; j < 4; j++) S[i][j] = 0.f;

#pragma unroll
        for (int ks = 0; ks < 4; ks++) {
            uint32_t Qlr[4];
            Qlr[0] = *(const uint32_t*)(qbl + r * 64 + ks * 16 + c2);
            Qlr[1] = *(const uint32_t*)(qbl + (r + 8) * 64 + ks * 16 + c2);
            Qlr[2] = *(const uint32_t*)(qbl + r * 64 + ks * 16 + 8 + c2);
            Qlr[3] = *(const uint32_t*)(qbl + (r + 8) * 64 + ks * 16 + 8 + c2);
#pragma unroll
            for (int g = 0; g < 2; g++) {
                if (!gok[g]) continue;
                uint32_t kh[2][4];
#pragma unroll
                for (int j = 0; j < 2; j++) {
                    int nfp = g * 2 + j;
                    LDMX4(kh[j][0], kh[j][1], kh[j][2], kh[j][3],
                          sb + nfp * 2304 + ks * 32 + lane_off);
                }
#pragma unroll
                for (int j = 0; j < 2; j++) {
                    int nf = (g * 2 + j) * 2;
                    MMA_F16(S[nf][0], S[nf][1], S[nf][2], S[nf][3],
                            Qh[ks][0], Qh[ks][1], Qh[ks][2], Qh[ks][3], kh[j][0], kh[j][1]);
                    MMA_F16(S[nf+1][0], S[nf+1][1], S[nf+1][2], S[nf+1][3],
                            Qh[ks][0], Qh[ks][1], Qh[ks][2], Qh[ks][3], kh[j][2], kh[j][3]);
                }
#pragma unroll
                for (int j = 0; j < 2; j++) {
                    int nf = (g * 2 + j) * 2;
                    MMA_F16(S[nf][0], S[nf][1], S[nf][2], S[nf][3],
                            Qlr[0], Qlr[1], Qlr[2], Qlr[3], kh[j][0], kh[j][1]);
                    MMA_F16(S[nf+1][0], S[nf+1][1], S[nf+1][2], S[nf+1][3],
                            Qlr[0], Qlr[1], Qlr[2], Qlr[3], kh[j][2], kh[j][3]);
                }
            }
        }

        // ---- bias + mask (active groups only) ----
#pragma unroll
        for (int nf = 0; nf < 8; nf++) {
            if (!gok[nf >> 2]) continue;
            int rel0 = kc + nf * 8 + c2 - qpos0;
            int rel2 = rel0 - 8;
            S[nf][0] = (rel0     <= 0 && rel0     >= -WIN) ? fmaf(slope, (float)rel0,     S[nf][0]) : -INFINITY;
            S[nf][1] = (rel0 + 1 <= 0 && rel0 + 1 >= -WIN) ? fmaf(slope, (float)(rel0+1), S[nf][1]) : -INFINITY;
            S[nf][2] = (rel2     <= 0 && rel2     >= -WIN) ? fmaf(slope, (float)rel2,     S[nf][2]) : -INFINITY;
            S[nf][3] = (rel2 + 1 <= 0 && rel2 + 1 >= -WIN) ? fmaf(slope, (float)(rel2+1), S[nf][3]) : -INFINITY;
        }

        // ---- online softmax (fast ex2, active groups only) ----
        float mx0 = -INFINITY, mx1 = -INFINITY;
#pragma unroll
        for (int nf = 0; nf < 8; nf++) {
            if (!gok[nf >> 2]) continue;
            mx0 = fmaxf(mx0, fmaxf(S[nf][0], S[nf][1]));
            mx1 = fmaxf(mx1, fmaxf(S[nf][2], S[nf][3]));
        }
        mx0 = fmaxf(mx0, __shfl_xor_sync(0xffffffffu, mx0, 1));
        mx0 = fmaxf(mx0, __shfl_xor_sync(0xffffffffu, mx0, 2));
        mx1 = fmaxf(mx1, __shfl_xor_sync(0xffffffffu, mx1, 1));
        mx1 = fmaxf(mx1, __shfl_xor_sync(0xffffffffu, mx1, 2));

        float mn0 = fmaxf(fmaxf(m0, mx0), -1e30f);
        float mn1 = fmaxf(fmaxf(m1, mx1), -1e30f);
        float a0 = ex2(m0 - mn0);
        float a1 = ex2(m1 - mn1);
        m0 = mn0; m1 = mn1;
        l0 *= a0; l1 *= a1;
#pragma unroll
        for (int nf = 0; nf < 8; nf++) {
            O[nf][0] *= a0; O[nf][1] *= a0;
            O[nf][2] *= a1; O[nf][3] *= a1;
        }
#pragma unroll
        for (int nf = 0; nf < 8; nf++) {
            if (!gok[nf >> 2]) {
                S[nf][0] = 0.f; S[nf][1] = 0.f; S[nf][2] = 0.f; S[nf][3] = 0.f;
                continue;
            }
            S[nf][0] = ex2(S[nf][0] - m0);
            S[nf][1] = ex2(S[nf][1] - m0);
            S[nf][2] = ex2(S[nf][2] - m1);
            S[nf][3] = ex2(S[nf][3] - m1);
            l0 += S[nf][0] + S[nf][1];
            l1 += S[nf][2] + S[nf][3];
        }

        // ---- PV: O += Ph*Vh + Pl*Vh ----
#pragma unroll
        for (int ks = 0; ks < 4; ks++) {
            int kk0 = kc + ks * 16;
            if (kk0 > wqmax || kk0 + 15 < wqmin - WIN) continue;
            float x00 = S[2*ks][0],   x01 = S[2*ks][1],   x02 = S[2*ks][2],   x03 = S[2*ks][3];
            float x10 = S[2*ks+1][0], x11 = S[2*ks+1][1], x12 = S[2*ks+1][2], x13 = S[2*ks+1][3];
            float h00 = __half2float(__float2half(x00));
            float h01 = __half2float(__float2half(x01));
            float h02 = __half2float(__float2half(x02));
            float h03 = __half2float(__float2half(x03));
            float h10 = __half2float(__float2half(x10));
            float h11 = __half2float(__float2half(x11));
            float h12 = __half2float(__float2half(x12));
            float h13 = __half2float(__float2half(x13));
            uint32_t ph0 = packh(x00, x01), ph1 = packh(x02, x03);
            uint32_t ph2 = packh(x10, x11), ph3 = packh(x12, x13);
            uint32_t pl0 = packh(x00 - h00, x01 - h01), pl1 = packh(x02 - h02, x03 - h03);
            uint32_t pl2 = packh(x10 - h10, x11 - h11), pl3 = packh(x12 - h12, x13 - h13);
#pragma unroll
            for (int g = 0; g < 2; g++) {
                uint32_t v[2][4];
#pragma unroll
                for (int j = 0; j < 2; j++) {
                    int nfp = g * 2 + j;
                    LDMX4T(v[j][0], v[j][1], v[j][2], v[j][3],
                           sb + TILEB + ks * 2304 + nfp * 32 + lane_off);
                }
#pragma unroll
                for (int j = 0; j < 2; j++) {
                    int nf = (g * 2 + j) * 2;
                    MMA_F16(O[nf][0], O[nf][1], O[nf][2], O[nf][3],
                            ph0, ph1, ph2, ph3, v[j][0], v[j][2]);
                    MMA_F16(O[nf+1][0], O[nf+1][1], O[nf+1][2], O[nf+1][3],
                            ph0, ph1, ph2, ph3, v[j][1], v[j][3]);
                }
#pragma unroll
                for (int j = 0; j < 2; j++) {
                    int nf = (g * 2 + j) * 2;
                    MMA_F16(O[nf][0], O[nf][1], O[nf][2], O[nf][3],
                            pl0, pl1, pl2, pl3, v[j][0], v[j][2]);
                    MMA_F16(O[nf+1][0], O[nf+1][1], O[nf+1][2], O[nf+1][3],
                            pl0, pl1, pl2, pl3, v[j][1], v[j][3]);
                }
            }
        }

        }  // active

        __syncthreads();
        if (c + 2 < nch) load_chunk(kc0 + (c + 2) * 64, c & 1);
    }

    // ---- epilogue ----
    l0 += __shfl_xor_sync(0xffffffffu, l0, 1);
    l0 += __shfl_xor_sync(0xffffffffu, l0, 2);
    l1 += __shfl_xor_sync(0xffffffffu, l1, 1);
    l1 += __shfl_xor_sync(0xffffffffu, l1, 2);
    float inv0 = 1.f / l0, inv1 = 1.f / l1;

    size_t out0 = ((size_t)(b * SS + qpos0) * DIM) + head * 64;
    size_t out1 = out0 + (size_t)8 * DIM;
#pragma unroll
    for (int nf = 0; nf < 8; nf++) {
        float y0 = O[nf][0] * inv0, y1 = O[nf][1] * inv0;
        float y2 = O[nf][2] * inv1, y3 = O[nf][3] * inv1;
        int col = nf * 8 + c2;
        float h0 = __half2float(__float2half(y0));
        float h1 = __half2float(__float2half(y1));
        float h2 = __half2float(__float2half(y2));
        float h3 = __half2float(__float2half(y3));
        *(uint32_t*)(g_ah + out0 + col) = packh(y0, y1);
        *(uint32_t*)(g_al + out0 + col) = packh(y0 - h0, y1 - h1);
        *(uint32_t*)(g_ah + out1 + col) = packh(y2, y3);
        *(uint32_t*)(g_al + out1 + col) = packh(y2 - h2, y3 - h3);
    }
}

// ---------------- launch ----------------
extern "C" void kernel_launch(void* const* d_in, const int* in_sizes, int n_in,
                              void* d_out, int out_size)
{
    const float* x  = (const float*)d_in[0];
    const float* wq = (const float*)d_in[1];
    const float* wk = (const float*)d_in[2];
    const float* wv = (const float*)d_in[3];
    const float* wo = (const float*)d_in[4];
    const float* qw = (const float*)d_in[5];
    const float* kw = (const float*)d_in[6];
    float* out = (float*)d_out;

    float* xqkv = nullptr;
    __half *ah = nullptr, *al = nullptr, *wh = nullptr;
    cudaGetSymbolAddress((void**)&xqkv, g_xqkv);
    cudaGetSymbolAddress((void**)&ah, g_ah);
    cudaGetSymbolAddress((void**)&al, g_al);
    cudaGetSymbolAddress((void**)&wh, g_wh);

    static bool attr_done = false;
    if (!attr_done) {
        cudaFuncSetAttribute(hmma_gemm, cudaFuncAttributeMaxDynamicSharedMemorySize, GEMM_SMEM);
        cudaFuncSetAttribute(attn_tc, cudaFuncAttributeMaxDynamicSharedMemorySize, ATT_SMEM);
        attr_done = true;
    }

    split_all<<<(1048576 + 655360) / 256, 256>>>(x, wq, wk, wv, wo);
    hmma_gemm<<<dim3(QKVW / 128, TT / 128), 256, GEMM_SMEM>>>(ah, al, wh, xqkv, QKVW, 0);
    prep_qkv<<<TT, 256>>>(qw, kw);
    attn_tc<<<dim3(SS / 128, NH, BB), 256, ATT_SMEM>>>();
    hmma_gemm<<<dim3(DIM / 128, TT / 128), 256, GEMM_SMEM>>>(
        ah, al, wh + (size_t)WO_ROW * DIM, out, DIM, 0);
}

// round 12
// speedup vs baseline: 1.6634x; 1.1414x over previous
#include <cuda_runtime.h>
#include <cuda_fp16.h>
#include <math.h>
#include <stdint.h>

#define DIM   1024
#define NH    16
#define NKV   4
#define HD    64
#define WIN   512
#define BB    2
#define SS    2048
#define TT    (BB*SS)
#define QKVW  1536   // 1024 q | 256 k | 256 v per token
#define GK    1024   // K dim of every GEMM
#define LOG2E 1.4426950408889634f

// ---------------- scratch (no allocs allowed) ----------------
__device__ float g_xqkv[(size_t)TT * QKVW];        // fp32 qkv projections
__device__ __half g_ah[(size_t)TT * DIM];          // activation hi (x, then attn out)
__device__ __half g_al[(size_t)TT * DIM];          // activation lo (x only)
__device__ __half g_wh[(size_t)2560 * DIM];        // weights fp16: wq|wk|wv|wo
__device__ __half g_qh[(size_t)TT * DIM];          // per-head Q hi  [(b*NH+h)*SS+s][64]
__device__ __half g_ql[(size_t)TT * DIM];          // per-head Q lo
__device__ __half g_kh[(size_t)TT * 256];          // per-kvhead K fp16
__device__ __half g_vh[(size_t)TT * 256];          // per-kvhead V fp16
#define WO_ROW 1536

// ---------------- small PTX helpers ----------------
__device__ __forceinline__ uint32_t smem_u32(const void* p) {
    uint32_t a;
    asm("{ .reg .u64 t; cvta.to.shared.u64 t, %1; cvt.u32.u64 %0, t; }" : "=r"(a) : "l"(p));
    return a;
}
__device__ __forceinline__ void cp16(uint32_t s, const void* g) {
    asm volatile("{ .reg .u64 gg; cvta.to.global.u64 gg, %1; cp.async.cg.shared.global [%0], [gg], 16; }"
                 :: "r"(s), "l"(g) : "memory");
}
__device__ __forceinline__ void cp_commit() { asm volatile("cp.async.commit_group;" ::: "memory"); }
template <int N>
__device__ __forceinline__ void cp_wait() { asm volatile("cp.async.wait_group %0;" :: "n"(N) : "memory"); }

__device__ __forceinline__ uint32_t packh(float lo, float hi) {
    uint32_t r;
    asm("cvt.rn.f16x2.f32 %0, %1, %2;" : "=r"(r) : "f"(hi), "f"(lo));
    return r;
}
__device__ __forceinline__ float ex2(float x) {
    float y;
    asm("ex2.approx.ftz.f32 %0, %1;" : "=f"(y) : "f"(x));
    return y;
}

#define MMA_F16(c0,c1,c2,c3, a0,a1,a2,a3, b0,b1) \
    asm volatile("mma.sync.aligned.m16n8k16.row.col.f32.f16.f16.f32 " \
                 "{%0,%1,%2,%3}, {%4,%5,%6,%7}, {%8,%9}, {%0,%1,%2,%3};" \
                 : "+f"(c0), "+f"(c1), "+f"(c2), "+f"(c3) \
                 : "r"(a0), "r"(a1), "r"(a2), "r"(a3), "r"(b0), "r"(b1))

#define LDMX4(r0,r1,r2,r3, addr) \
    asm volatile("ldmatrix.sync.aligned.m8n8.x4.shared.b16 {%0,%1,%2,%3}, [%4];" \
                 : "=r"(r0), "=r"(r1), "=r"(r2), "=r"(r3) : "r"(addr))
#define LDMX4T(r0,r1,r2,r3, addr) \
    asm volatile("ldmatrix.sync.aligned.m8n8.x4.trans.shared.b16 {%0,%1,%2,%3}, [%4];" \
                 : "=r"(r0), "=r"(r1), "=r"(r2), "=r"(r3) : "r"(addr))

// ---------------- fused splits: x -> hi/lo fp16, all weights -> fp16 ----------------
__global__ __launch_bounds__(256) void split_all(
    const float* __restrict__ x,
    const float* __restrict__ wq, const float* __restrict__ wk,
    const float* __restrict__ wv, const float* __restrict__ wo)
{
    int i = blockIdx.x * 256 + threadIdx.x;
    if (i < 1048576) {
        float4 v = ((const float4*)x)[i];
        float f[4] = {v.x, v.y, v.z, v.w};
        union { __half b[4]; uint2 u; } H, L;
#pragma unroll
        for (int k = 0; k < 4; k++) {
            __half h = __float2half(f[k]);
            H.b[k] = h;
            L.b[k] = __float2half(f[k] - __half2float(h));
        }
        ((uint2*)g_ah)[i] = H.u;
        ((uint2*)g_al)[i] = L.u;
    } else {
        int j = i - 1048576;
        const float* src;
        int local;
        if (j < 262144)      { src = wq; local = j; }
        else if (j < 327680) { src = wk; local = j - 262144; }
        else if (j < 393216) { src = wv; local = j - 327680; }
        else                 { src = wo; local = j - 393216; }
        float4 v = ((const float4*)src)[local];
        union { __half b[4]; uint2 u; } H;
        H.b[0] = __float2half(v.x); H.b[1] = __float2half(v.y);
        H.b[2] = __float2half(v.z); H.b[3] = __float2half(v.w);
        ((uint2*)g_wh)[j] = H.u;
    }
}

// ---------------- HMMA fp16 GEMM: BK=64, 2-stage cp.async, 2 CTAs/SM ----------------
// two_pass=1: C = (Ah+Al)*Bh (QKV).  two_pass=0: C = Ah*Bh (O-projection).
#define BKC 64
#define NCHG (GK / BKC)          // 16
#define SROWG 72                 // halves per row (64 data + 8 pad -> 144B)
#define TILEG (128 * SROWG)      // halves per tile
#define STAGEG (3 * TILEG)       // Ah, Al, Bh
#define GEMM_SMEM (2 * STAGEG * 2)   // 110592 bytes -> 2 CTAs/SM

__global__ __launch_bounds__(256, 2) void hmma_gemm(
    const __half* __restrict__ ah, const __half* __restrict__ al,
    const __half* __restrict__ bh,
    float* __restrict__ C, int ldc, int coff, int two_pass)
{
    extern __shared__ char smraw[];
    const uint32_t smb = smem_u32(smraw);

    const int tid = threadIdx.x;
    const int wid = tid >> 5;
    const int lid = tid & 31;
    const int wm = wid & 1;
    const int wn = wid >> 1;
    const int m0 = blockIdx.y * 128;
    const int n0 = blockIdx.x * 128;

    const __half* gbase[3];
    gbase[0] = ah + (size_t)m0 * GK;
    gbase[1] = al + (size_t)m0 * GK;
    gbase[2] = bh + (size_t)n0 * GK;

    auto load_stage = [&](int kc, int stg) {
        const uint32_t base = smb + (uint32_t)stg * (STAGEG * 2);
#pragma unroll
        for (int i = 0; i < 4; i++) {
            int id = tid + 256 * i;
            int row = id >> 3, seg = id & 7;
            uint32_t soff = (uint32_t)(row * SROWG + seg * 8) * 2;
#pragma unroll
            for (int t = 0; t < 3; t++) {
                if (t == 1 && !two_pass) continue;   // Al tile unused in 1-pass mode
                const __half* src = gbase[t] + (size_t)row * GK + kc + seg * 8;
                cp16(base + (uint32_t)t * (TILEG * 2) + soff, src);
            }
        }
        cp_commit();
    };

    float acc[4][4][4];
#pragma unroll
    for (int i = 0; i < 4; i++)
#pragma unroll
        for (int j = 0; j < 4; j++)
#pragma unroll
            for (int k = 0; k < 4; k++) acc[i][j][k] = 0.f;

    const uint32_t frag_off =
        (uint32_t)((((lid & 7) + ((lid >> 3) & 1) * 8) * SROWG + (lid >> 4) * 8) * 2);

    load_stage(0, 0);
    load_stage(BKC, 1);

    for (int c = 0; c < NCHG; c++) {
        if (c < NCHG - 1) cp_wait<1>(); else cp_wait<0>();
        __syncthreads();

        const uint32_t sbase = smb + (uint32_t)(c & 1) * (STAGEG * 2);

#pragma unroll
        for (int ks = 0; ks < 4; ks++) {
            uint32_t Ah[4][4], Al[4][4], Bh[2][4];
#pragma unroll
            for (int mf = 0; mf < 4; mf++) {
                uint32_t aaddr = sbase +
                    (uint32_t)(((wm * 64 + mf * 16) * SROWG + ks * 16) * 2) + frag_off;
                LDMX4(Ah[mf][0], Ah[mf][1], Ah[mf][2], Ah[mf][3], aaddr);
                if (two_pass)
                    LDMX4(Al[mf][0], Al[mf][1], Al[mf][2], Al[mf][3], aaddr + TILEG * 2);
            }
#pragma unroll
            for (int nfp = 0; nfp < 2; nfp++) {
                uint32_t baddr = sbase + 2u * (TILEG * 2) +
                    (uint32_t)(((wn * 32 + nfp * 16) * SROWG + ks * 16) * 2) + frag_off;
                LDMX4(Bh[nfp][0], Bh[nfp][1], Bh[nfp][2], Bh[nfp][3], baddr);
            }

            // pass 1: Ah*Bh
#pragma unroll
            for (int nfp = 0; nfp < 2; nfp++)
#pragma unroll
                for (int mf = 0; mf < 4; mf++) {
                    MMA_F16(acc[mf][2*nfp][0], acc[mf][2*nfp][1], acc[mf][2*nfp][2], acc[mf][2*nfp][3],
                            Ah[mf][0], Ah[mf][1], Ah[mf][2], Ah[mf][3], Bh[nfp][0], Bh[nfp][2]);
                    MMA_F16(acc[mf][2*nfp+1][0], acc[mf][2*nfp+1][1], acc[mf][2*nfp+1][2], acc[mf][2*nfp+1][3],
                            Ah[mf][0], Ah[mf][1], Ah[mf][2], Ah[mf][3], Bh[nfp][1], Bh[nfp][3]);
                }
            // pass 2: Al*Bh
            if (two_pass) {
#pragma unroll
                for (int nfp = 0; nfp < 2; nfp++)
#pragma unroll
                    for (int mf = 0; mf < 4; mf++) {
                        MMA_F16(acc[mf][2*nfp][0], acc[mf][2*nfp][1], acc[mf][2*nfp][2], acc[mf][2*nfp][3],
                                Al[mf][0], Al[mf][1], Al[mf][2], Al[mf][3], Bh[nfp][0], Bh[nfp][2]);
                        MMA_F16(acc[mf][2*nfp+1][0], acc[mf][2*nfp+1][1], acc[mf][2*nfp+1][2], acc[mf][2*nfp+1][3],
                                Al[mf][0], Al[mf][1], Al[mf][2], Al[mf][3], Bh[nfp][1], Bh[nfp][3]);
                    }
            }
        }

        __syncthreads();
        if (c + 2 < NCHG) load_stage((c + 2) * BKC, c & 1);
    }

    const int r2 = lid >> 2;
    const int c2 = (lid & 3) * 2;
#pragma unroll
    for (int mf = 0; mf < 4; mf++) {
        const int row = m0 + wm * 64 + mf * 16 + r2;
#pragma unroll
        for (int nf = 0; nf < 4; nf++) {
            float* cp0 = C + (size_t)row * ldc + coff + n0 + wn * 32 + nf * 8 + c2;
            *(float2*)cp0 = make_float2(acc[mf][nf][0], acc[mf][nf][1]);
            *(float2*)(cp0 + 8 * (size_t)ldc) = make_float2(acc[mf][nf][2], acc[mf][nf][3]);
        }
    }
}

// ---------------- fused q-rms + k-rms + v, vectorized float4 ----------------
__global__ __launch_bounds__(256) void prep_qkv(
    const float* __restrict__ qw, const float* __restrict__ kw)
{
    const int t = blockIdx.x;
    const int b = t >> 11, s = t & (SS - 1);
    const float* row = g_xqkv + (size_t)t * QKVW;
    const int tid = threadIdx.x;

    float4 q4 = *(const float4*)(row + tid * 4);
    float ssq = q4.x * q4.x;
    ssq = fmaf(q4.y, q4.y, ssq);
    ssq = fmaf(q4.z, q4.z, ssq);
    ssq = fmaf(q4.w, q4.w, ssq);

    float4 kv4 = make_float4(0.f, 0.f, 0.f, 0.f);
    float ssk = 0.f;
    if (tid < 64) {
        kv4 = *(const float4*)(row + 1024 + tid * 4);
        ssk = kv4.x * kv4.x;
        ssk = fmaf(kv4.y, kv4.y, ssk);
        ssk = fmaf(kv4.z, kv4.z, ssk);
        ssk = fmaf(kv4.w, kv4.w, ssk);
    } else if (tid < 128) {
        kv4 = *(const float4*)(row + 1280 + (tid - 64) * 4);
    }

#pragma unroll
    for (int o = 16; o > 0; o >>= 1) {
        ssq += __shfl_xor_sync(0xffffffffu, ssq, o);
        ssk += __shfl_xor_sync(0xffffffffu, ssk, o);
    }

    __shared__ float redq[8], redk[8];
    __shared__ float sclq_s, sclk_s;
    if ((tid & 31) == 0) { redq[tid >> 5] = ssq; redk[tid >> 5] = ssk; }
    __syncthreads();
    if (tid == 0) {
        float tq = 0.f, tk = 0.f;
#pragma unroll
        for (int i = 0; i < 8; i++) { tq += redq[i]; tk += redk[i]; }
        sclq_s = rsqrtf(tq * (1.f / 1024.f) + 1e-6f) * (0.125f * LOG2E);
        sclk_s = rsqrtf(tk * (1.f / 256.f) + 1e-6f);
    }
    __syncthreads();
    const float sclq = sclq_s, sclk = sclk_s;

    {
        float4 qwv = *(const float4*)(qw + tid * 4);
        float v0 = q4.x * sclq * qwv.x;
        float v1 = q4.y * sclq * qwv.y;
        float v2 = q4.z * sclq * qwv.z;
        float v3 = q4.w * sclq * qwv.w;
        float h0 = __half2float(__float2half(v0));
        float h1 = __half2float(__float2half(v1));
        float h2 = __half2float(__float2half(v2));
        float h3 = __half2float(__float2half(v3));
        int idx = tid * 4;
        int head = idx >> 6, d = idx & 63;
        size_t off = ((size_t)(b * NH + head) * SS + s) * 64 + d;
        *(uint2*)(g_qh + off) = make_uint2(packh(v0, v1), packh(v2, v3));
        *(uint2*)(g_ql + off) = make_uint2(packh(v0 - h0, v1 - h1), packh(v2 - h2, v3 - h3));
    }

    if (tid < 64) {
        int idx = tid * 4;
        int kv = idx >> 6, d = idx & 63;
        float4 kwv = *(const float4*)(kw + idx);
        float v0 = kv4.x * sclk * kwv.x;
        float v1 = kv4.y * sclk * kwv.y;
        float v2 = kv4.z * sclk * kwv.z;
        float v3 = kv4.w * sclk * kwv.w;
        size_t off = ((size_t)(b * NKV + kv) * SS + s) * 64 + d;
        *(uint2*)(g_kh + off) = make_uint2(packh(v0, v1), packh(v2, v3));
    } else if (tid < 128) {
        int idx = (tid - 64) * 4;
        int kv = idx >> 6, d = idx & 63;
        size_t off = ((size_t)(b * NKV + kv) * SS + s) * 64 + d;
        *(uint2*)(g_vh + off) = make_uint2(packh(kv4.x, kv4.y), packh(kv4.z, kv4.w));
    }
}

// ---------------- tensor-core attention (log2 domain, 1-pass PV) ----------------
#define TILEB 9216                    // 64*144
#define ATT_SMEM (2 * 2 * TILEB)      // 36864

__global__ __launch_bounds__(256, 2) void attn_tc()
{
    extern __shared__ char asm_[];
    const uint32_t smb = smem_u32(asm_);

    const int tid = threadIdx.x;
    const int wid = tid >> 5;
    const int lid = tid & 31;
    const int qstart = blockIdx.x * 128;
    const int head = blockIdx.y;
    const int b = blockIdx.z;
    const int kvh = head >> 2;

    const int r = lid >> 2;
    const int c2 = (lid & 3) * 2;
    const int qpos0 = qstart + wid * 16 + r;
    const int wqmin = qstart + wid * 16;
    const int wqmax = wqmin + 15;
    const float slope = exp2f(-0.5f * (float)(head + 1)) * LOG2E;

    const __half* qbh = g_qh + ((size_t)(b * NH + head) * SS + qstart + wid * 16) * 64;
    const __half* qbl = g_ql + ((size_t)(b * NH + head) * SS + qstart + wid * 16) * 64;
    uint32_t Qh[4][4];
#pragma unroll
    for (int ks = 0; ks < 4; ks++) {
        Qh[ks][0] = *(const uint32_t*)(qbh + r * 64 + ks * 16 + c2);
        Qh[ks][1] = *(const uint32_t*)(qbh + (r + 8) * 64 + ks * 16 + c2);
        Qh[ks][2] = *(const uint32_t*)(qbh + r * 64 + ks * 16 + 8 + c2);
        Qh[ks][3] = *(const uint32_t*)(qbh + (r + 8) * 64 + ks * 16 + 8 + c2);
    }

    float O[8][4];
#pragma unroll
    for (int i = 0; i < 8; i++)
#pragma unroll
        for (int j = 0; j < 4; j++) O[i][j] = 0.f;
    float m0 = -INFINITY, m1 = -INFINITY, l0 = 0.f, l1 = 0.f;

    const int kc0 = (qstart >= WIN) ? qstart - WIN : 0;
    const int nch = (qstart + 128 - kc0) >> 6;

    const int key_ld = tid >> 2;
    const int seg = tid & 3;
    const __half* src_base[2];
    {
        size_t kvb = ((size_t)(b * NKV + kvh) * SS) * 64;
        src_base[0] = g_kh + kvb;
        src_base[1] = g_vh + kvb;
    }
    auto load_chunk = [&](int kc, int stg) {
        uint32_t sb = smb + stg * 2 * TILEB + key_ld * 144 + seg * 16;
#pragma unroll
        for (int t = 0; t < 2; t++) {
            const __half* src = src_base[t] + (size_t)(kc + key_ld) * 64 + seg * 8;
            cp16(sb + t * TILEB, src);
            cp16(sb + t * TILEB + 64, src + 32);
        }
        cp_commit();
    };

    load_chunk(kc0, 0);
    if (nch > 1) load_chunk(kc0 + 64, 1);

    const uint32_t lane_off = (uint32_t)(((lid >> 4) * 8 + (lid & 7)) * 144 + ((lid >> 3) & 1) * 16);

    for (int c = 0; c < nch; c++) {
        if (c < nch - 1) cp_wait<1>(); else cp_wait<0>();
        __syncthreads();

        const uint32_t sb = smb + (c & 1) * 2 * TILEB;
        const int kc = kc0 + c * 64;

        const bool active = (kc <= wqmax) && (kc + 63 >= wqmin - WIN);
        if (active) {

        bool gok[2];
#pragma unroll
        for (int g = 0; g < 2; g++) {
            int gk0 = kc + g * 32;
            gok[g] = (gk0 <= wqmax) && (gk0 + 31 >= wqmin - WIN);
        }

        // ---- scores: S = Qh*Kh + Ql*Kh ----
        float S[8][4];
#pragma unroll
        for (int i = 0; i < 8; i++)
#pragma unroll
            for (int j = 0; j < 4; j++) S[i][j] = 0.f;

#pragma unroll
        for (int ks = 0; ks < 4; ks++) {
            uint32_t Qlr[4];
            Qlr[0] = *(const uint32_t*)(qbl + r * 64 + ks * 16 + c2);
            Qlr[1] = *(const uint32_t*)(qbl + (r + 8) * 64 + ks * 16 + c2);
            Qlr[2] = *(const uint32_t*)(qbl + r * 64 + ks * 16 + 8 + c2);
            Qlr[3] = *(const uint32_t*)(qbl + (r + 8) * 64 + ks * 16 + 8 + c2);
#pragma unroll
            for (int g = 0; g < 2; g++) {
                if (!gok[g]) continue;
                uint32_t kh[2][4];
#pragma unroll
                for (int j = 0; j < 2; j++) {
                    int nfp = g * 2 + j;
                    LDMX4(kh[j][0], kh[j][1], kh[j][2], kh[j][3],
                          sb + nfp * 2304 + ks * 32 + lane_off);
                }
#pragma unroll
                for (int j = 0; j < 2; j++) {
                    int nf = (g * 2 + j) * 2;
                    MMA_F16(S[nf][0], S[nf][1], S[nf][2], S[nf][3],
                            Qh[ks][0], Qh[ks][1], Qh[ks][2], Qh[ks][3], kh[j][0], kh[j][1]);
                    MMA_F16(S[nf+1][0], S[nf+1][1], S[nf+1][2], S[nf+1][3],
                            Qh[ks][0], Qh[ks][1], Qh[ks][2], Qh[ks][3], kh[j][2], kh[j][3]);
                }
#pragma unroll
                for (int j = 0; j < 2; j++) {
                    int nf = (g * 2 + j) * 2;
                    MMA_F16(S[nf][0], S[nf][1], S[nf][2], S[nf][3],
                            Qlr[0], Qlr[1], Qlr[2], Qlr[3], kh[j][0], kh[j][1]);
                    MMA_F16(S[nf+1][0], S[nf+1][1], S[nf+1][2], S[nf+1][3],
                            Qlr[0], Qlr[1], Qlr[2], Qlr[3], kh[j][2], kh[j][3]);
                }
            }
        }

        // ---- bias + mask ----
#pragma unroll
        for (int nf = 0; nf < 8; nf++) {
            if (!gok[nf >> 2]) continue;
            int rel0 = kc + nf * 8 + c2 - qpos0;
            int rel2 = rel0 - 8;
            S[nf][0] = (rel0     <= 0 && rel0     >= -WIN) ? fmaf(slope, (float)rel0,     S[nf][0]) : -INFINITY;
            S[nf][1] = (rel0 + 1 <= 0 && rel0 + 1 >= -WIN) ? fmaf(slope, (float)(rel0+1), S[nf][1]) : -INFINITY;
            S[nf][2] = (rel2     <= 0 && rel2     >= -WIN) ? fmaf(slope, (float)rel2,     S[nf][2]) : -INFINITY;
            S[nf][3] = (rel2 + 1 <= 0 && rel2 + 1 >= -WIN) ? fmaf(slope, (float)(rel2+1), S[nf][3]) : -INFINITY;
        }

        // ---- online softmax ----
        float mx0 = -INFINITY, mx1 = -INFINITY;
#pragma unroll
        for (int nf = 0; nf < 8; nf++) {
            if (!gok[nf >> 2]) continue;
            mx0 = fmaxf(mx0, fmaxf(S[nf][0], S[nf][1]));
            mx1 = fmaxf(mx1, fmaxf(S[nf][2], S[nf][3]));
        }
        mx0 = fmaxf(mx0, __shfl_xor_sync(0xffffffffu, mx0, 1));
        mx0 = fmaxf(mx0, __shfl_xor_sync(0xffffffffu, mx0, 2));
        mx1 = fmaxf(mx1, __shfl_xor_sync(0xffffffffu, mx1, 1));
        mx1 = fmaxf(mx1, __shfl_xor_sync(0xffffffffu, mx1, 2));

        float mn0 = fmaxf(fmaxf(m0, mx0), -1e30f);
        float mn1 = fmaxf(fmaxf(m1, mx1), -1e30f);
        float a0 = ex2(m0 - mn0);
        float a1 = ex2(m1 - mn1);
        m0 = mn0; m1 = mn1;
        l0 *= a0; l1 *= a1;
#pragma unroll
        for (int nf = 0; nf < 8; nf++) {
            O[nf][0] *= a0; O[nf][1] *= a0;
            O[nf][2] *= a1; O[nf][3] *= a1;
        }
#pragma unroll
        for (int nf = 0; nf < 8; nf++) {
            if (!gok[nf >> 2]) {
                S[nf][0] = 0.f; S[nf][1] = 0.f; S[nf][2] = 0.f; S[nf][3] = 0.f;
                continue;
            }
            S[nf][0] = ex2(S[nf][0] - m0);
            S[nf][1] = ex2(S[nf][1] - m0);
            S[nf][2] = ex2(S[nf][2] - m1);
            S[nf][3] = ex2(S[nf][3] - m1);
            l0 += S[nf][0] + S[nf][1];
            l1 += S[nf][2] + S[nf][3];
        }

        // ---- PV: O += Ph*Vh (single pass; P fp16 quantization ~2^-12) ----
#pragma unroll
        for (int ks = 0; ks < 4; ks++) {
            int kk0 = kc + ks * 16;
            if (kk0 > wqmax || kk0 + 15 < wqmin - WIN) continue;
            uint32_t ph0 = packh(S[2*ks][0],   S[2*ks][1]);
            uint32_t ph1 = packh(S[2*ks][2],   S[2*ks][3]);
            uint32_t ph2 = packh(S[2*ks+1][0], S[2*ks+1][1]);
            uint32_t ph3 = packh(S[2*ks+1][2], S[2*ks+1][3]);
#pragma unroll
            for (int g = 0; g < 2; g++) {
                uint32_t v[2][4];
#pragma unroll
                for (int j = 0; j < 2; j++) {
                    int nfp = g * 2 + j;
                    LDMX4T(v[j][0], v[j][1], v[j][2], v[j][3],
                           sb + TILEB + ks * 2304 + nfp * 32 + lane_off);
                }
#pragma unroll
                for (int j = 0; j < 2; j++) {
                    int nf = (g * 2 + j) * 2;
                    MMA_F16(O[nf][0], O[nf][1], O[nf][2], O[nf][3],
                            ph0, ph1, ph2, ph3, v[j][0], v[j][2]);
                    MMA_F16(O[nf+1][0], O[nf+1][1], O[nf+1][2], O[nf+1][3],
                            ph0, ph1, ph2, ph3, v[j][1], v[j][3]);
                }
            }
        }

        }  // active

        __syncthreads();
        if (c + 2 < nch) load_chunk(kc0 + (c + 2) * 64, c & 1);
    }

    // ---- epilogue: write y as fp16 (hi only — O-projection is 1-pass) ----
    l0 += __shfl_xor_sync(0xffffffffu, l0, 1);
    l0 += __shfl_xor_sync(0xffffffffu, l0, 2);
    l1 += __shfl_xor_sync(0xffffffffu, l1, 1);
    l1 += __shfl_xor_sync(0xffffffffu, l1, 2);
    float inv0 = 1.f / l0, inv1 = 1.f / l1;

    size_t out0 = ((size_t)(b * SS + qpos0) * DIM) + head * 64;
    size_t out1 = out0 + (size_t)8 * DIM;
#pragma unroll
    for (int nf = 0; nf < 8; nf++) {
        float y0 = O[nf][0] * inv0, y1 = O[nf][1] * inv0;
        float y2 = O[nf][2] * inv1, y3 = O[nf][3] * inv1;
        int col = nf * 8 + c2;
        *(uint32_t*)(g_ah + out0 + col) = packh(y0, y1);
        *(uint32_t*)(g_ah + out1 + col) = packh(y2, y3);
    }
}

// ---------------- launch ----------------
extern "C" void kernel_launch(void* const* d_in, const int* in_sizes, int n_in,
                              void* d_out, int out_size)
{
    const float* x  = (const float*)d_in[0];
    const float* wq = (const float*)d_in[1];
    const float* wk = (const float*)d_in[2];
    const float* wv = (const float*)d_in[3];
    const float* wo = (const float*)d_in[4];
    const float* qw = (const float*)d_in[5];
    const float* kw = (const float*)d_in[6];
    float* out = (float*)d_out;

    float* xqkv = nullptr;
    __half *ah = nullptr, *al = nullptr, *wh = nullptr;
    cudaGetSymbolAddress((void**)&xqkv, g_xqkv);
    cudaGetSymbolAddress((void**)&ah, g_ah);
    cudaGetSymbolAddress((void**)&al, g_al);
    cudaGetSymbolAddress((void**)&wh, g_wh);

    static bool attr_done = false;
    if (!attr_done) {
        cudaFuncSetAttribute(hmma_gemm, cudaFuncAttributeMaxDynamicSharedMemorySize, GEMM_SMEM);
        cudaFuncSetAttribute(attn_tc, cudaFuncAttributeMaxDynamicSharedMemorySize, ATT_SMEM);
        attr_done = true;
    }

    split_all<<<(1048576 + 655360) / 256, 256>>>(x, wq, wk, wv, wo);
    hmma_gemm<<<dim3(QKVW / 128, TT / 128), 256, GEMM_SMEM>>>(ah, al, wh, xqkv, QKVW, 0, 1);
    prep_qkv<<<TT, 256>>>(qw, kw);
    attn_tc<<<dim3(SS / 128, NH, BB), 256, ATT_SMEM>>>();
    hmma_gemm<<<dim3(DIM / 128, TT / 128), 256, GEMM_SMEM>>>(
        ah, al, wh + (size_t)WO_ROW * DIM, out, DIM, 0, 0);
}

// round 13
// speedup vs baseline: 2.0888x; 1.2557x over previous
#include <cuda_runtime.h>
#include <cuda_fp16.h>
#include <math.h>
#include <stdint.h>

#define DIM   1024
#define NH    16
#define NKV   4
#define HD    64
#define WIN   512
#define BB    2
#define SS    2048
#define TT    (BB*SS)
#define QKVW  1536   // 1024 q | 256 k | 256 v per token
#define GK    1024   // K dim of every GEMM
#define LOG2E 1.4426950408889634f

// ---------------- scratch (no allocs allowed) ----------------
__device__ float g_xqkv[(size_t)TT * QKVW];        // fp32 qkv projections
__device__ __half g_ah[(size_t)TT * DIM];          // activation fp16 (x, then attn out)
__device__ __half g_wh[(size_t)2560 * DIM];        // weights fp16: wq|wk|wv|wo
__device__ __half g_qh[(size_t)TT * DIM];          // per-head Q hi  [(b*NH+h)*SS+s][64]
__device__ __half g_ql[(size_t)TT * DIM];          // per-head Q lo
__device__ __half g_kh[(size_t)TT * 256];          // per-kvhead K fp16
__device__ __half g_vh[(size_t)TT * 256];          // per-kvhead V fp16
#define WO_ROW 1536

// ---------------- small PTX helpers ----------------
__device__ __forceinline__ uint32_t smem_u32(const void* p) {
    uint32_t a;
    asm("{ .reg .u64 t; cvta.to.shared.u64 t, %1; cvt.u32.u64 %0, t; }" : "=r"(a) : "l"(p));
    return a;
}
__device__ __forceinline__ void cp16(uint32_t s, const void* g) {
    asm volatile("{ .reg .u64 gg; cvta.to.global.u64 gg, %1; cp.async.cg.shared.global [%0], [gg], 16; }"
                 :: "r"(s), "l"(g) : "memory");
}
__device__ __forceinline__ void cp_commit() { asm volatile("cp.async.commit_group;" ::: "memory"); }
template <int N>
__device__ __forceinline__ void cp_wait() { asm volatile("cp.async.wait_group %0;" :: "n"(N) : "memory"); }

__device__ __forceinline__ uint32_t packh(float lo, float hi) {
    uint32_t r;
    asm("cvt.rn.f16x2.f32 %0, %1, %2;" : "=r"(r) : "f"(hi), "f"(lo));
    return r;
}
__device__ __forceinline__ float ex2(float x) {
    float y;
    asm("ex2.approx.ftz.f32 %0, %1;" : "=f"(y) : "f"(x));
    return y;
}

#define MMA_F16(c0,c1,c2,c3, a0,a1,a2,a3, b0,b1) \
    asm volatile("mma.sync.aligned.m16n8k16.row.col.f32.f16.f16.f32 " \
                 "{%0,%1,%2,%3}, {%4,%5,%6,%7}, {%8,%9}, {%0,%1,%2,%3};" \
                 : "+f"(c0), "+f"(c1), "+f"(c2), "+f"(c3) \
                 : "r"(a0), "r"(a1), "r"(a2), "r"(a3), "r"(b0), "r"(b1))

#define LDMX4(r0,r1,r2,r3, addr) \
    asm volatile("ldmatrix.sync.aligned.m8n8.x4.shared.b16 {%0,%1,%2,%3}, [%4];" \
                 : "=r"(r0), "=r"(r1), "=r"(r2), "=r"(r3) : "r"(addr))
#define LDMX4T(r0,r1,r2,r3, addr) \
    asm volatile("ldmatrix.sync.aligned.m8n8.x4.trans.shared.b16 {%0,%1,%2,%3}, [%4];" \
                 : "=r"(r0), "=r"(r1), "=r"(r2), "=r"(r3) : "r"(addr))

// ---------------- fused splits: x -> fp16, all weights -> fp16 ----------------
__global__ __launch_bounds__(256) void split_all(
    const float* __restrict__ x,
    const float* __restrict__ wq, const float* __restrict__ wk,
    const float* __restrict__ wv, const float* __restrict__ wo)
{
    int i = blockIdx.x * 256 + threadIdx.x;
    if (i < 1048576) {
        float4 v = ((const float4*)x)[i];
        union { __half b[4]; uint2 u; } H;
        H.b[0] = __float2half(v.x); H.b[1] = __float2half(v.y);
        H.b[2] = __float2half(v.z); H.b[3] = __float2half(v.w);
        ((uint2*)g_ah)[i] = H.u;
    } else {
        int j = i - 1048576;
        const float* src;
        int local;
        if (j < 262144)      { src = wq; local = j; }
        else if (j < 327680) { src = wk; local = j - 262144; }
        else if (j < 393216) { src = wv; local = j - 327680; }
        else                 { src = wo; local = j - 393216; }
        float4 v = ((const float4*)src)[local];
        union { __half b[4]; uint2 u; } H;
        H.b[0] = __float2half(v.x); H.b[1] = __float2half(v.y);
        H.b[2] = __float2half(v.z); H.b[3] = __float2half(v.w);
        ((uint2*)g_wh)[j] = H.u;
    }
}

// ---------------- HMMA fp16 1-pass GEMM: C = Ah*Bh, BK=64, 2-stage cp.async ----------------
#define BKC 64
#define NCHG (GK / BKC)          // 16
#define SROWG 72                 // halves per row (64 data + 8 pad -> 144B)
#define TILEG (128 * SROWG)      // halves per tile
#define STAGEG (2 * TILEG)       // Ah, Bh
#define GEMM_SMEM (2 * STAGEG * 2)   // 73728 bytes

__global__ __launch_bounds__(256, 2) void hmma_gemm(
    const __half* __restrict__ ah, const __half* __restrict__ bh,
    float* __restrict__ C, int ldc, int coff)
{
    extern __shared__ char smraw[];
    const uint32_t smb = smem_u32(smraw);

    const int tid = threadIdx.x;
    const int wid = tid >> 5;
    const int lid = tid & 31;
    const int wm = wid & 1;
    const int wn = wid >> 1;
    const int m0 = blockIdx.y * 128;
    const int n0 = blockIdx.x * 128;

    const __half* gbase[2];
    gbase[0] = ah + (size_t)m0 * GK;
    gbase[1] = bh + (size_t)n0 * GK;

    auto load_stage = [&](int kc, int stg) {
        const uint32_t base = smb + (uint32_t)stg * (STAGEG * 2);
#pragma unroll
        for (int i = 0; i < 4; i++) {
            int id = tid + 256 * i;
            int row = id >> 3, seg = id & 7;
            uint32_t soff = (uint32_t)(row * SROWG + seg * 8) * 2;
#pragma unroll
            for (int t = 0; t < 2; t++) {
                const __half* src = gbase[t] + (size_t)row * GK + kc + seg * 8;
                cp16(base + (uint32_t)t * (TILEG * 2) + soff, src);
            }
        }
        cp_commit();
    };

    float acc[4][4][4];
#pragma unroll
    for (int i = 0; i < 4; i++)
#pragma unroll
        for (int j = 0; j < 4; j++)
#pragma unroll
            for (int k = 0; k < 4; k++) acc[i][j][k] = 0.f;

    const uint32_t frag_off =
        (uint32_t)((((lid & 7) + ((lid >> 3) & 1) * 8) * SROWG + (lid >> 4) * 8) * 2);

    load_stage(0, 0);
    load_stage(BKC, 1);

    for (int c = 0; c < NCHG; c++) {
        if (c < NCHG - 1) cp_wait<1>(); else cp_wait<0>();
        __syncthreads();

        const uint32_t sbase = smb + (uint32_t)(c & 1) * (STAGEG * 2);

#pragma unroll
        for (int ks = 0; ks < 4; ks++) {
            uint32_t Ah[4][4], Bh[2][4];
#pragma unroll
            for (int mf = 0; mf < 4; mf++) {
                uint32_t aaddr = sbase +
                    (uint32_t)(((wm * 64 + mf * 16) * SROWG + ks * 16) * 2) + frag_off;
                LDMX4(Ah[mf][0], Ah[mf][1], Ah[mf][2], Ah[mf][3], aaddr);
            }
#pragma unroll
            for (int nfp = 0; nfp < 2; nfp++) {
                uint32_t baddr = sbase + (TILEG * 2) +
                    (uint32_t)(((wn * 32 + nfp * 16) * SROWG + ks * 16) * 2) + frag_off;
                LDMX4(Bh[nfp][0], Bh[nfp][1], Bh[nfp][2], Bh[nfp][3], baddr);
            }

#pragma unroll
            for (int nfp = 0; nfp < 2; nfp++)
#pragma unroll
                for (int mf = 0; mf < 4; mf++) {
                    MMA_F16(acc[mf][2*nfp][0], acc[mf][2*nfp][1], acc[mf][2*nfp][2], acc[mf][2*nfp][3],
                            Ah[mf][0], Ah[mf][1], Ah[mf][2], Ah[mf][3], Bh[nfp][0], Bh[nfp][2]);
                    MMA_F16(acc[mf][2*nfp+1][0], acc[mf][2*nfp+1][1], acc[mf][2*nfp+1][2], acc[mf][2*nfp+1][3],
                            Ah[mf][0], Ah[mf][1], Ah[mf][2], Ah[mf][3], Bh[nfp][1], Bh[nfp][3]);
                }
        }

        __syncthreads();
        if (c + 2 < NCHG) load_stage((c + 2) * BKC, c & 1);
    }

    const int r2 = lid >> 2;
    const int c2 = (lid & 3) * 2;
#pragma unroll
    for (int mf = 0; mf < 4; mf++) {
        const int row = m0 + wm * 64 + mf * 16 + r2;
#pragma unroll
        for (int nf = 0; nf < 4; nf++) {
            float* cp0 = C + (size_t)row * ldc + coff + n0 + wn * 32 + nf * 8 + c2;
            *(float2*)cp0 = make_float2(acc[mf][nf][0], acc[mf][nf][1]);
            *(float2*)(cp0 + 8 * (size_t)ldc) = make_float2(acc[mf][nf][2], acc[mf][nf][3]);
        }
    }
}

// ---------------- fused q-rms + k-rms + v, vectorized float4 ----------------
__global__ __launch_bounds__(256) void prep_qkv(
    const float* __restrict__ qw, const float* __restrict__ kw)
{
    const int t = blockIdx.x;
    const int b = t >> 11, s = t & (SS - 1);
    const float* row = g_xqkv + (size_t)t * QKVW;
    const int tid = threadIdx.x;

    float4 q4 = *(const float4*)(row + tid * 4);
    float ssq = q4.x * q4.x;
    ssq = fmaf(q4.y, q4.y, ssq);
    ssq = fmaf(q4.z, q4.z, ssq);
    ssq = fmaf(q4.w, q4.w, ssq);

    float4 kv4 = make_float4(0.f, 0.f, 0.f, 0.f);
    float ssk = 0.f;
    if (tid < 64) {
        kv4 = *(const float4*)(row + 1024 + tid * 4);
        ssk = kv4.x * kv4.x;
        ssk = fmaf(kv4.y, kv4.y, ssk);
        ssk = fmaf(kv4.z, kv4.z, ssk);
        ssk = fmaf(kv4.w, kv4.w, ssk);
    } else if (tid < 128) {
        kv4 = *(const float4*)(row + 1280 + (tid - 64) * 4);
    }

#pragma unroll
    for (int o = 16; o > 0; o >>= 1) {
        ssq += __shfl_xor_sync(0xffffffffu, ssq, o);
        ssk += __shfl_xor_sync(0xffffffffu, ssk, o);
    }

    __shared__ float redq[8], redk[8];
    __shared__ float sclq_s, sclk_s;
    if ((tid & 31) == 0) { redq[tid >> 5] = ssq; redk[tid >> 5] = ssk; }
    __syncthreads();
    if (tid == 0) {
        float tq = 0.f, tk = 0.f;
#pragma unroll
        for (int i = 0; i < 8; i++) { tq += redq[i]; tk += redk[i]; }
        sclq_s = rsqrtf(tq * (1.f / 1024.f) + 1e-6f) * (0.125f * LOG2E);
        sclk_s = rsqrtf(tk * (1.f / 256.f) + 1e-6f);
    }
    __syncthreads();
    const float sclq = sclq_s, sclk = sclk_s;

    {
        float4 qwv = *(const float4*)(qw + tid * 4);
        float v0 = q4.x * sclq * qwv.x;
        float v1 = q4.y * sclq * qwv.y;
        float v2 = q4.z * sclq * qwv.z;
        float v3 = q4.w * sclq * qwv.w;
        float h0 = __half2float(__float2half(v0));
        float h1 = __half2float(__float2half(v1));
        float h2 = __half2float(__float2half(v2));
        float h3 = __half2float(__float2half(v3));
        int idx = tid * 4;
        int head = idx >> 6, d = idx & 63;
        size_t off = ((size_t)(b * NH + head) * SS + s) * 64 + d;
        *(uint2*)(g_qh + off) = make_uint2(packh(v0, v1), packh(v2, v3));
        *(uint2*)(g_ql + off) = make_uint2(packh(v0 - h0, v1 - h1), packh(v2 - h2, v3 - h3));
    }

    if (tid < 64) {
        int idx = tid * 4;
        int kv = idx >> 6, d = idx & 63;
        float4 kwv = *(const float4*)(kw + idx);
        float v0 = kv4.x * sclk * kwv.x;
        float v1 = kv4.y * sclk * kwv.y;
        float v2 = kv4.z * sclk * kwv.z;
        float v3 = kv4.w * sclk * kwv.w;
        size_t off = ((size_t)(b * NKV + kv) * SS + s) * 64 + d;
        *(uint2*)(g_kh + off) = make_uint2(packh(v0, v1), packh(v2, v3));
    } else if (tid < 128) {
        int idx = (tid - 64) * 4;
        int kv = idx >> 6, d = idx & 63;
        size_t off = ((size_t)(b * NKV + kv) * SS + s) * 64 + d;
        *(uint2*)(g_vh + off) = make_uint2(packh(kv4.x, kv4.y), packh(kv4.z, kv4.w));
    }
}

// ---------------- tensor-core attention (log2 domain, 1-pass PV) ----------------
#define TILEB 9216                    // 64*144
#define ATT_SMEM (2 * 2 * TILEB)      // 36864

__global__ __launch_bounds__(256, 2) void attn_tc()
{
    extern __shared__ char asm_[];
    const uint32_t smb = smem_u32(asm_);

    const int tid = threadIdx.x;
    const int wid = tid >> 5;
    const int lid = tid & 31;
    const int qstart = blockIdx.x * 128;
    const int head = blockIdx.y;
    const int b = blockIdx.z;
    const int kvh = head >> 2;

    const int r = lid >> 2;
    const int c2 = (lid & 3) * 2;
    const int qpos0 = qstart + wid * 16 + r;
    const int wqmin = qstart + wid * 16;
    const int wqmax = wqmin + 15;
    const float slope = exp2f(-0.5f * (float)(head + 1)) * LOG2E;

    const __half* qbh = g_qh + ((size_t)(b * NH + head) * SS + qstart + wid * 16) * 64;
    const __half* qbl = g_ql + ((size_t)(b * NH + head) * SS + qstart + wid * 16) * 64;
    uint32_t Qh[4][4];
#pragma unroll
    for (int ks = 0; ks < 4; ks++) {
        Qh[ks][0] = *(const uint32_t*)(qbh + r * 64 + ks * 16 + c2);
        Qh[ks][1] = *(const uint32_t*)(qbh + (r + 8) * 64 + ks * 16 + c2);
        Qh[ks][2] = *(const uint32_t*)(qbh + r * 64 + ks * 16 + 8 + c2);
        Qh[ks][3] = *(const uint32_t*)(qbh + (r + 8) * 64 + ks * 16 + 8 + c2);
    }

    float O[8][4];
#pragma unroll
    for (int i = 0; i < 8; i++)
#pragma unroll
        for (int j = 0; j < 4; j++) O[i][j] = 0.f;
    float m0 = -INFINITY, m1 = -INFINITY, l0 = 0.f, l1 = 0.f;

    const int kc0 = (qstart >= WIN) ? qstart - WIN : 0;
    const int nch = (qstart + 128 - kc0) >> 6;

    const int key_ld = tid >> 2;
    const int seg = tid & 3;
    const __half* src_base[2];
    {
        size_t kvb = ((size_t)(b * NKV + kvh) * SS) * 64;
        src_base[0] = g_kh + kvb;
        src_base[1] = g_vh + kvb;
    }
    auto load_chunk = [&](int kc, int stg) {
        uint32_t sb = smb + stg * 2 * TILEB + key_ld * 144 + seg * 16;
#pragma unroll
        for (int t = 0; t < 2; t++) {
            const __half* src = src_base[t] + (size_t)(kc + key_ld) * 64 + seg * 8;
            cp16(sb + t * TILEB, src);
            cp16(sb + t * TILEB + 64, src + 32);
        }
        cp_commit();
    };

    load_chunk(kc0, 0);
    if (nch > 1) load_chunk(kc0 + 64, 1);

    const uint32_t lane_off = (uint32_t)(((lid >> 4) * 8 + (lid & 7)) * 144 + ((lid >> 3) & 1) * 16);

    for (int c = 0; c < nch; c++) {
        if (c < nch - 1) cp_wait<1>(); else cp_wait<0>();
        __syncthreads();

        const uint32_t sb = smb + (c & 1) * 2 * TILEB;
        const int kc = kc0 + c * 64;

        const bool active = (kc <= wqmax) && (kc + 63 >= wqmin - WIN);
        if (active) {

        bool gok[2];
#pragma unroll
        for (int g = 0; g < 2; g++) {
            int gk0 = kc + g * 32;
            gok[g] = (gk0 <= wqmax) && (gk0 + 31 >= wqmin - WIN);
        }

        // ---- scores: S = Qh*Kh + Ql*Kh ----
        float S[8][4];
#pragma unroll
        for (int i = 0; i < 8; i++)
#pragma unroll
            for (int j = 0; j < 4; j++) S[i][j] = 0.f;

#pragma unroll
        for (int ks = 0; ks < 4; ks++) {
            uint32_t Qlr[4];
            Qlr[0] = *(const uint32_t*)(qbl + r * 64 + ks * 16 + c2);
            Qlr[1] = *(const uint32_t*)(qbl + (r + 8) * 64 + ks * 16 + c2);
            Qlr[2] = *(const uint32_t*)(qbl + r * 64 + ks * 16 + 8 + c2);
            Qlr[3] = *(const uint32_t*)(qbl + (r + 8) * 64 + ks * 16 + 8 + c2);
#pragma unroll
            for (int g = 0; g < 2; g++) {
                if (!gok[g]) continue;
                uint32_t kh[2][4];
#pragma unroll
                for (int j = 0; j < 2; j++) {
                    int nfp = g * 2 + j;
                    LDMX4(kh[j][0], kh[j][1], kh[j][2], kh[j][3],
                          sb + nfp * 2304 + ks * 32 + lane_off);
                }
#pragma unroll
                for (int j = 0; j < 2; j++) {
                    int nf = (g * 2 + j) * 2;
                    MMA_F16(S[nf][0], S[nf][1], S[nf][2], S[nf][3],
                            Qh[ks][0], Qh[ks][1], Qh[ks][2], Qh[ks][3], kh[j][0], kh[j][1]);
                    MMA_F16(S[nf+1][0], S[nf+1][1], S[nf+1][2], S[nf+1][3],
                            Qh[ks][0], Qh[ks][1], Qh[ks][2], Qh[ks][3], kh[j][2], kh[j][3]);
                }
#pragma unroll
                for (int j = 0; j < 2; j++) {
                    int nf = (g * 2 + j) * 2;
                    MMA_F16(S[nf][0], S[nf][1], S[nf][2], S[nf][3],
                            Qlr[0], Qlr[1], Qlr[2], Qlr[3], kh[j][0], kh[j][1]);
                    MMA_F16(S[nf+1][0], S[nf+1][1], S[nf+1][2], S[nf+1][3],
                            Qlr[0], Qlr[1], Qlr[2], Qlr[3], kh[j][2], kh[j][3]);
                }
            }
        }

        // ---- bias + mask ----
#pragma unroll
        for (int nf = 0; nf < 8; nf++) {
            if (!gok[nf >> 2]) continue;
            int rel0 = kc + nf * 8 + c2 - qpos0;
            int rel2 = rel0 - 8;
            S[nf][0] = (rel0     <= 0 && rel0     >= -WIN) ? fmaf(slope, (float)rel0,     S[nf][0]) : -INFINITY;
            S[nf][1] = (rel0 + 1 <= 0 && rel0 + 1 >= -WIN) ? fmaf(slope, (float)(rel0+1), S[nf][1]) : -INFINITY;
            S[nf][2] = (rel2     <= 0 && rel2     >= -WIN) ? fmaf(slope, (float)rel2,     S[nf][2]) : -INFINITY;
            S[nf][3] = (rel2 + 1 <= 0 && rel2 + 1 >= -WIN) ? fmaf(slope, (float)(rel2+1), S[nf][3]) : -INFINITY;
        }

        // ---- online softmax ----
        float mx0 = -INFINITY, mx1 = -INFINITY;
#pragma unroll
        for (int nf = 0; nf < 8; nf++) {
            if (!gok[nf >> 2]) continue;
            mx0 = fmaxf(mx0, fmaxf(S[nf][0], S[nf][1]));
            mx1 = fmaxf(mx1, fmaxf(S[nf][2], S[nf][3]));
        }
        mx0 = fmaxf(mx0, __shfl_xor_sync(0xffffffffu, mx0, 1));
        mx0 = fmaxf(mx0, __shfl_xor_sync(0xffffffffu, mx0, 2));
        mx1 = fmaxf(mx1, __shfl_xor_sync(0xffffffffu, mx1, 1));
        mx1 = fmaxf(mx1, __shfl_xor_sync(0xffffffffu, mx1, 2));

        float mn0 = fmaxf(fmaxf(m0, mx0), -1e30f);
        float mn1 = fmaxf(fmaxf(m1, mx1), -1e30f);
        float a0 = ex2(m0 - mn0);
        float a1 = ex2(m1 - mn1);
        m0 = mn0; m1 = mn1;
        l0 *= a0; l1 *= a1;
#pragma unroll
        for (int nf = 0; nf < 8; nf++) {
            O[nf][0] *= a0; O[nf][1] *= a0;
            O[nf][2] *= a1; O[nf][3] *= a1;
        }
#pragma unroll
        for (int nf = 0; nf < 8; nf++) {
            if (!gok[nf >> 2]) {
                S[nf][0] = 0.f; S[nf][1] = 0.f; S[nf][2] = 0.f; S[nf][3] = 0.f;
                continue;
            }
            S[nf][0] = ex2(S[nf][0] - m0);
            S[nf][1] = ex2(S[nf][1] - m0);
            S[nf][2] = ex2(S[nf][2] - m1);
            S[nf][3] = ex2(S[nf][3] - m1);
            l0 += S[nf][0] + S[nf][1];
            l1 += S[nf][2] + S[nf][3];
        }

        // ---- PV: O += Ph*Vh ----
#pragma unroll
        for (int ks = 0; ks < 4; ks++) {
            int kk0 = kc + ks * 16;
            if (kk0 > wqmax || kk0 + 15 < wqmin - WIN) continue;
            uint32_t ph0 = packh(S[2*ks][0],   S[2*ks][1]);
            uint32_t ph1 = packh(S[2*ks][2],   S[2*ks][3]);
            uint32_t ph2 = packh(S[2*ks+1][0], S[2*ks+1][1]);
            uint32_t ph3 = packh(S[2*ks+1][2], S[2*ks+1][3]);
#pragma unroll
            for (int g = 0; g < 2; g++) {
                uint32_t v[2][4];
#pragma unroll
                for (int j = 0; j < 2; j++) {
                    int nfp = g * 2 + j;
                    LDMX4T(v[j][0], v[j][1], v[j][2], v[j][3],
                           sb + TILEB + ks * 2304 + nfp * 32 + lane_off);
                }
#pragma unroll
                for (int j = 0; j < 2; j++) {
                    int nf = (g * 2 + j) * 2;
                    MMA_F16(O[nf][0], O[nf][1], O[nf][2], O[nf][3],
                            ph0, ph1, ph2, ph3, v[j][0], v[j][2]);
                    MMA_F16(O[nf+1][0], O[nf+1][1], O[nf+1][2], O[nf+1][3],
                            ph0, ph1, ph2, ph3, v[j][1], v[j][3]);
                }
            }
        }

        }  // active

        __syncthreads();
        if (c + 2 < nch) load_chunk(kc0 + (c + 2) * 64, c & 1);
    }

    // ---- epilogue: write y as fp16 ----
    l0 += __shfl_xor_sync(0xffffffffu, l0, 1);
    l0 += __shfl_xor_sync(0xffffffffu, l0, 2);
    l1 += __shfl_xor_sync(0xffffffffu, l1, 1);
    l1 += __shfl_xor_sync(0xffffffffu, l1, 2);
    float inv0 = 1.f / l0, inv1 = 1.f / l1;

    size_t out0 = ((size_t)(b * SS + qpos0) * DIM) + head * 64;
    size_t out1 = out0 + (size_t)8 * DIM;
#pragma unroll
    for (int nf = 0; nf < 8; nf++) {
        float y0 = O[nf][0] * inv0, y1 = O[nf][1] * inv0;
        float y2 = O[nf][2] * inv1, y3 = O[nf][3] * inv1;
        int col = nf * 8 + c2;
        *(uint32_t*)(g_ah + out0 + col) = packh(y0, y1);
        *(uint32_t*)(g_ah + out1 + col) = packh(y2, y3);
    }
}

// ---------------- launch ----------------
extern "C" void kernel_launch(void* const* d_in, const int* in_sizes, int n_in,
                              void* d_out, int out_size)
{
    const float* x  = (const float*)d_in[0];
    const float* wq = (const float*)d_in[1];
    const float* wk = (const float*)d_in[2];
    const float* wv = (const float*)d_in[3];
    const float* wo = (const float*)d_in[4];
    const float* qw = (const float*)d_in[5];
    const float* kw = (const float*)d_in[6];
    float* out = (float*)d_out;

    float* xqkv = nullptr;
    __half *ah = nullptr, *wh = nullptr;
    cudaGetSymbolAddress((void**)&xqkv, g_xqkv);
    cudaGetSymbolAddress((void**)&ah, g_ah);
    cudaGetSymbolAddress((void**)&wh, g_wh);

    static bool attr_done = false;
    if (!attr_done) {
        cudaFuncSetAttribute(hmma_gemm, cudaFuncAttributeMaxDynamicSharedMemorySize, GEMM_SMEM);
        cudaFuncSetAttribute(attn_tc, cudaFuncAttributeMaxDynamicSharedMemorySize, ATT_SMEM);
        attr_done = true;
    }

    split_all<<<(1048576 + 655360) / 256, 256>>>(x, wq, wk, wv, wo);
    hmma_gemm<<<dim3(QKVW / 128, TT / 128), 256, GEMM_SMEM>>>(ah, wh, xqkv, QKVW, 0);
    prep_qkv<<<TT, 256>>>(qw, kw);
    attn_tc<<<dim3(SS / 128, NH, BB), 256, ATT_SMEM>>>();
    hmma_gemm<<<dim3(DIM / 128, TT / 128), 256, GEMM_SMEM>>>(
        ah, wh + (size_t)WO_ROW * DIM, out, DIM, 0);
}

// round 14
// speedup vs baseline: 2.0895x; 1.0004x over previous
#include <cuda_runtime.h>
#include <cuda_fp16.h>
#include <math.h>
#include <stdint.h>

#define DIM   1024
#define NH    16
#define NKV   4
#define HD    64
#define WIN   512
#define BB    2
#define SS    2048
#define TT    (BB*SS)
#define QKVW  1536   // 1024 q | 256 k | 256 v per token
#define GK    1024   // K dim of every GEMM
#define LOG2E 1.4426950408889634f

// ---------------- scratch (no allocs allowed) ----------------
__device__ float g_xqkv[(size_t)TT * QKVW];        // fp32 qkv projections
__device__ __half g_ah[(size_t)TT * DIM];          // activation fp16 (x, then attn out)
__device__ __half g_wh[(size_t)2560 * DIM];        // weights fp16: wq|wk|wv|wo
__device__ __half g_qh[(size_t)TT * DIM];          // per-head Q hi  [(b*NH+h)*SS+s][64]
__device__ __half g_ql[(size_t)TT * DIM];          // per-head Q lo
__device__ __half g_kh[(size_t)TT * 256];          // per-kvhead K fp16
__device__ __half g_vh[(size_t)TT * 256];          // per-kvhead V fp16
#define WO_ROW 1536

// ---------------- small PTX helpers ----------------
__device__ __forceinline__ uint32_t smem_u32(const void* p) {
    uint32_t a;
    asm("{ .reg .u64 t; cvta.to.shared.u64 t, %1; cvt.u32.u64 %0, t; }" : "=r"(a) : "l"(p));
    return a;
}
__device__ __forceinline__ void cp16(uint32_t s, const void* g) {
    asm volatile("{ .reg .u64 gg; cvta.to.global.u64 gg, %1; cp.async.cg.shared.global [%0], [gg], 16; }"
                 :: "r"(s), "l"(g) : "memory");
}
__device__ __forceinline__ void cp_commit() { asm volatile("cp.async.commit_group;" ::: "memory"); }
template <int N>
__device__ __forceinline__ void cp_wait() { asm volatile("cp.async.wait_group %0;" :: "n"(N) : "memory"); }

__device__ __forceinline__ uint32_t packh(float lo, float hi) {
    uint32_t r;
    asm("cvt.rn.f16x2.f32 %0, %1, %2;" : "=r"(r) : "f"(hi), "f"(lo));
    return r;
}
__device__ __forceinline__ float ex2(float x) {
    float y;
    asm("ex2.approx.ftz.f32 %0, %1;" : "=f"(y) : "f"(x));
    return y;
}

#define MMA_F16(c0,c1,c2,c3, a0,a1,a2,a3, b0,b1) \
    asm volatile("mma.sync.aligned.m16n8k16.row.col.f32.f16.f16.f32 " \
                 "{%0,%1,%2,%3}, {%4,%5,%6,%7}, {%8,%9}, {%0,%1,%2,%3};" \
                 : "+f"(c0), "+f"(c1), "+f"(c2), "+f"(c3) \
                 : "r"(a0), "r"(a1), "r"(a2), "r"(a3), "r"(b0), "r"(b1))

#define LDMX4(r0,r1,r2,r3, addr) \
    asm volatile("ldmatrix.sync.aligned.m8n8.x4.shared.b16 {%0,%1,%2,%3}, [%4];" \
                 : "=r"(r0), "=r"(r1), "=r"(r2), "=r"(r3) : "r"(addr))
#define LDMX4T(r0,r1,r2,r3, addr) \
    asm volatile("ldmatrix.sync.aligned.m8n8.x4.trans.shared.b16 {%0,%1,%2,%3}, [%4];" \
                 : "=r"(r0), "=r"(r1), "=r"(r2), "=r"(r3) : "r"(addr))

// ---------------- fused splits: x -> fp16, all weights -> fp16 ----------------
__global__ __launch_bounds__(256) void split_all(
    const float* __restrict__ x,
    const float* __restrict__ wq, const float* __restrict__ wk,
    const float* __restrict__ wv, const float* __restrict__ wo)
{
    int i = blockIdx.x * 256 + threadIdx.x;
    if (i < 1048576) {
        float4 v = ((const float4*)x)[i];
        union { __half b[4]; uint2 u; } H;
        H.b[0] = __float2half(v.x); H.b[1] = __float2half(v.y);
        H.b[2] = __float2half(v.z); H.b[3] = __float2half(v.w);
        ((uint2*)g_ah)[i] = H.u;
    } else {
        int j = i - 1048576;
        const float* src;
        int local;
        if (j < 262144)      { src = wq; local = j; }
        else if (j < 327680) { src = wk; local = j - 262144; }
        else if (j < 393216) { src = wv; local = j - 327680; }
        else                 { src = wo; local = j - 393216; }
        float4 v = ((const float4*)src)[local];
        union { __half b[4]; uint2 u; } H;
        H.b[0] = __float2half(v.x); H.b[1] = __float2half(v.y);
        H.b[2] = __float2half(v.z); H.b[3] = __float2half(v.w);
        ((uint2*)g_wh)[j] = H.u;
    }
}

// ---------------- HMMA fp16 1-pass GEMM: C = Ah*Bh, BK=64, 2-stage cp.async ----------------
#define BKC 64
#define NCHG (GK / BKC)          // 16
#define SROWG 72                 // halves per row (64 data + 8 pad -> 144B)
#define TILEG (128 * SROWG)      // halves per tile
#define STAGEG (2 * TILEG)       // Ah, Bh
#define GEMM_SMEM (2 * STAGEG * 2)   // 73728 bytes

__global__ __launch_bounds__(256, 2) void hmma_gemm(
    const __half* __restrict__ ah, const __half* __restrict__ bh,
    float* __restrict__ C, int ldc, int coff)
{
    extern __shared__ char smraw[];
    const uint32_t smb = smem_u32(smraw);

    const int tid = threadIdx.x;
    const int wid = tid >> 5;
    const int lid = tid & 31;
    const int wm = wid & 1;
    const int wn = wid >> 1;
    const int m0 = blockIdx.y * 128;
    const int n0 = blockIdx.x * 128;

    const __half* gbase[2];
    gbase[0] = ah + (size_t)m0 * GK;
    gbase[1] = bh + (size_t)n0 * GK;

    auto load_stage = [&](int kc, int stg) {
        const uint32_t base = smb + (uint32_t)stg * (STAGEG * 2);
#pragma unroll
        for (int i = 0; i < 4; i++) {
            int id = tid + 256 * i;
            int row = id >> 3, seg = id & 7;
            uint32_t soff = (uint32_t)(row * SROWG + seg * 8) * 2;
#pragma unroll
            for (int t = 0; t < 2; t++) {
                const __half* src = gbase[t] + (size_t)row * GK + kc + seg * 8;
                cp16(base + (uint32_t)t * (TILEG * 2) + soff, src);
            }
        }
        cp_commit();
    };

    float acc[4][4][4];
#pragma unroll
    for (int i = 0; i < 4; i++)
#pragma unroll
        for (int j = 0; j < 4; j++)
#pragma unroll
            for (int k = 0; k < 4; k++) acc[i][j][k] = 0.f;

    const uint32_t frag_off =
        (uint32_t)((((lid & 7) + ((lid >> 3) & 1) * 8) * SROWG + (lid >> 4) * 8) * 2);

    load_stage(0, 0);
    load_stage(BKC, 1);

    for (int c = 0; c < NCHG; c++) {
        if (c < NCHG - 1) cp_wait<1>(); else cp_wait<0>();
        __syncthreads();

        const uint32_t sbase = smb + (uint32_t)(c & 1) * (STAGEG * 2);

#pragma unroll
        for (int ks = 0; ks < 4; ks++) {
            uint32_t Ah[4][4], Bh[2][4];
#pragma unroll
            for (int mf = 0; mf < 4; mf++) {
                uint32_t aaddr = sbase +
                    (uint32_t)(((wm * 64 + mf * 16) * SROWG + ks * 16) * 2) + frag_off;
                LDMX4(Ah[mf][0], Ah[mf][1], Ah[mf][2], Ah[mf][3], aaddr);
            }
#pragma unroll
            for (int nfp = 0; nfp < 2; nfp++) {
                uint32_t baddr = sbase + (TILEG * 2) +
                    (uint32_t)(((wn * 32 + nfp * 16) * SROWG + ks * 16) * 2) + frag_off;
                LDMX4(Bh[nfp][0], Bh[nfp][1], Bh[nfp][2], Bh[nfp][3], baddr);
            }

#pragma unroll
            for (int nfp = 0; nfp < 2; nfp++)
#pragma unroll
                for (int mf = 0; mf < 4; mf++) {
                    MMA_F16(acc[mf][2*nfp][0], acc[mf][2*nfp][1], acc[mf][2*nfp][2], acc[mf][2*nfp][3],
                            Ah[mf][0], Ah[mf][1], Ah[mf][2], Ah[mf][3], Bh[nfp][0], Bh[nfp][2]);
                    MMA_F16(acc[mf][2*nfp+1][0], acc[mf][2*nfp+1][1], acc[mf][2*nfp+1][2], acc[mf][2*nfp+1][3],
                            Ah[mf][0], Ah[mf][1], Ah[mf][2], Ah[mf][3], Bh[nfp][1], Bh[nfp][3]);
                }
        }

        __syncthreads();
        if (c + 2 < NCHG) load_stage((c + 2) * BKC, c & 1);
    }

    const int r2 = lid >> 2;
    const int c2 = (lid & 3) * 2;
#pragma unroll
    for (int mf = 0; mf < 4; mf++) {
        const int row = m0 + wm * 64 + mf * 16 + r2;
#pragma unroll
        for (int nf = 0; nf < 4; nf++) {
            float* cp0 = C + (size_t)row * ldc + coff + n0 + wn * 32 + nf * 8 + c2;
            *(float2*)cp0 = make_float2(acc[mf][nf][0], acc[mf][nf][1]);
            *(float2*)(cp0 + 8 * (size_t)ldc) = make_float2(acc[mf][nf][2], acc[mf][nf][3]);
        }
    }
}

// ---------------- fused q-rms + k-rms + v, vectorized float4 ----------------
__global__ __launch_bounds__(256) void prep_qkv(
    const float* __restrict__ qw, const float* __restrict__ kw)
{
    const int t = blockIdx.x;
    const int b = t >> 11, s = t & (SS - 1);
    const float* row = g_xqkv + (size_t)t * QKVW;
    const int tid = threadIdx.x;

    float4 q4 = *(const float4*)(row + tid * 4);
    float ssq = q4.x * q4.x;
    ssq = fmaf(q4.y, q4.y, ssq);
    ssq = fmaf(q4.z, q4.z, ssq);
    ssq = fmaf(q4.w, q4.w, ssq);

    float4 kv4 = make_float4(0.f, 0.f, 0.f, 0.f);
    float ssk = 0.f;
    if (tid < 64) {
        kv4 = *(const float4*)(row + 1024 + tid * 4);
        ssk = kv4.x * kv4.x;
        ssk = fmaf(kv4.y, kv4.y, ssk);
        ssk = fmaf(kv4.z, kv4.z, ssk);
        ssk = fmaf(kv4.w, kv4.w, ssk);
    } else if (tid < 128) {
        kv4 = *(const float4*)(row + 1280 + (tid - 64) * 4);
    }

#pragma unroll
    for (int o = 16; o > 0; o >>= 1) {
        ssq += __shfl_xor_sync(0xffffffffu, ssq, o);
        ssk += __shfl_xor_sync(0xffffffffu, ssk, o);
    }

    __shared__ float redq[8], redk[8];
    __shared__ float sclq_s, sclk_s;
    if ((tid & 31) == 0) { redq[tid >> 5] = ssq; redk[tid >> 5] = ssk; }
    __syncthreads();
    if (tid == 0) {
        float tq = 0.f, tk = 0.f;
#pragma unroll
        for (int i = 0; i < 8; i++) { tq += redq[i]; tk += redk[i]; }
        sclq_s = rsqrtf(tq * (1.f / 1024.f) + 1e-6f) * (0.125f * LOG2E);
        sclk_s = rsqrtf(tk * (1.f / 256.f) + 1e-6f);
    }
    __syncthreads();
    const float sclq = sclq_s, sclk = sclk_s;

    {
        float4 qwv = *(const float4*)(qw + tid * 4);
        float v0 = q4.x * sclq * qwv.x;
        float v1 = q4.y * sclq * qwv.y;
        float v2 = q4.z * sclq * qwv.z;
        float v3 = q4.w * sclq * qwv.w;
        float h0 = __half2float(__float2half(v0));
        float h1 = __half2float(__float2half(v1));
        float h2 = __half2float(__float2half(v2));
        float h3 = __half2float(__float2half(v3));
        int idx = tid * 4;
        int head = idx >> 6, d = idx & 63;
        size_t off = ((size_t)(b * NH + head) * SS + s) * 64 + d;
        *(uint2*)(g_qh + off) = make_uint2(packh(v0, v1), packh(v2, v3));
        *(uint2*)(g_ql + off) = make_uint2(packh(v0 - h0, v1 - h1), packh(v2 - h2, v3 - h3));
    }

    if (tid < 64) {
        int idx = tid * 4;
        int kv = idx >> 6, d = idx & 63;
        float4 kwv = *(const float4*)(kw + idx);
        float v0 = kv4.x * sclk * kwv.x;
        float v1 = kv4.y * sclk * kwv.y;
        float v2 = kv4.z * sclk * kwv.z;
        float v3 = kv4.w * sclk * kwv.w;
        size_t off = ((size_t)(b * NKV + kv) * SS + s) * 64 + d;
        *(uint2*)(g_kh + off) = make_uint2(packh(v0, v1), packh(v2, v3));
    } else if (tid < 128) {
        int idx = (tid - 64) * 4;
        int kv = idx >> 6, d = idx & 63;
        size_t off = ((size_t)(b * NKV + kv) * SS + s) * 64 + d;
        *(uint2*)(g_vh + off) = make_uint2(packh(kv4.x, kv4.y), packh(kv4.z, kv4.w));
    }
}

// ---------------- tensor-core attention: 128-key sync windows ----------------
// stage = 128 keys x (K,V) tiles; each window processed as two 64-key halves.
#define TILEB 9216                    // 64 keys * 144B
#define VOFF  18432                   // V tile offset within stage (2 * TILEB)
#define STAGEB 36864                  // bytes per stage (K 128 + V 128)
#define ATT_SMEM (2 * STAGEB)         // 73728

__global__ __launch_bounds__(256, 2) void attn_tc()
{
    extern __shared__ char asm_[];
    const uint32_t smb = smem_u32(asm_);

    const int tid = threadIdx.x;
    const int wid = tid >> 5;
    const int lid = tid & 31;
    const int qstart = blockIdx.x * 128;
    const int head = blockIdx.y;
    const int b = blockIdx.z;
    const int kvh = head >> 2;

    const int r = lid >> 2;
    const int c2 = (lid & 3) * 2;
    const int qpos0 = qstart + wid * 16 + r;
    const int wqmin = qstart + wid * 16;
    const int wqmax = wqmin + 15;
    const float slope = exp2f(-0.5f * (float)(head + 1)) * LOG2E;

    const __half* qbh = g_qh + ((size_t)(b * NH + head) * SS + qstart + wid * 16) * 64;
    const __half* qbl = g_ql + ((size_t)(b * NH + head) * SS + qstart + wid * 16) * 64;
    uint32_t Qh[4][4];
#pragma unroll
    for (int ks = 0; ks < 4; ks++) {
        Qh[ks][0] = *(const uint32_t*)(qbh + r * 64 + ks * 16 + c2);
        Qh[ks][1] = *(const uint32_t*)(qbh + (r + 8) * 64 + ks * 16 + c2);
        Qh[ks][2] = *(const uint32_t*)(qbh + r * 64 + ks * 16 + 8 + c2);
        Qh[ks][3] = *(const uint32_t*)(qbh + (r + 8) * 64 + ks * 16 + 8 + c2);
    }

    float O[8][4];
#pragma unroll
    for (int i = 0; i < 8; i++)
#pragma unroll
        for (int j = 0; j < 4; j++) O[i][j] = 0.f;
    float m0 = -INFINITY, m1 = -INFINITY, l0 = 0.f, l1 = 0.f;

    const int kc0 = (qstart >= WIN) ? qstart - WIN : 0;
    const int nwin = (qstart + 128 - kc0) >> 7;   // 128-key windows (span is a multiple of 128)

    const int key_ld = tid >> 2;                  // 0..63
    const int seg = tid & 3;
    const __half* src_base[2];
    {
        size_t kvb = ((size_t)(b * NKV + kvh) * SS) * 64;
        src_base[0] = g_kh + kvb;
        src_base[1] = g_vh + kvb;
    }
    // load 128 keys (two 64-key halves) of K and V into stage stg
    auto load_window = [&](int kc, int stg) {
        uint32_t sb = smb + stg * STAGEB + key_ld * 144 + seg * 16;
#pragma unroll
        for (int h = 0; h < 2; h++) {
#pragma unroll
            for (int t = 0; t < 2; t++) {
                const __half* src = src_base[t] + (size_t)(kc + h * 64 + key_ld) * 64 + seg * 8;
                cp16(sb + t * VOFF + h * TILEB, src);
                cp16(sb + t * VOFF + h * TILEB + 64, src + 32);
            }
        }
        cp_commit();
    };

    load_window(kc0, 0);
    if (nwin > 1) load_window(kc0 + 128, 1);

    const uint32_t lane_off = (uint32_t)(((lid >> 4) * 8 + (lid & 7)) * 144 + ((lid >> 3) & 1) * 16);

    // process one 64-key chunk whose K tile starts at kbase (V at kbase+VOFF)
    auto do_chunk = [&](int kc, uint32_t kbase) {
        const bool active = (kc <= wqmax) && (kc + 63 >= wqmin - WIN);
        if (!active) return;

        bool gok[2];
#pragma unroll
        for (int g = 0; g < 2; g++) {
            int gk0 = kc + g * 32;
            gok[g] = (gk0 <= wqmax) && (gk0 + 31 >= wqmin - WIN);
        }

        float S[8][4];
#pragma unroll
        for (int i = 0; i < 8; i++)
#pragma unroll
            for (int j = 0; j < 4; j++) S[i][j] = 0.f;

#pragma unroll
        for (int ks = 0; ks < 4; ks++) {
            uint32_t Qlr[4];
            Qlr[0] = *(const uint32_t*)(qbl + r * 64 + ks * 16 + c2);
            Qlr[1] = *(const uint32_t*)(qbl + (r + 8) * 64 + ks * 16 + c2);
            Qlr[2] = *(const uint32_t*)(qbl + r * 64 + ks * 16 + 8 + c2);
            Qlr[3] = *(const uint32_t*)(qbl + (r + 8) * 64 + ks * 16 + 8 + c2);
#pragma unroll
            for (int g = 0; g < 2; g++) {
                if (!gok[g]) continue;
                uint32_t kh[2][4];
#pragma unroll
                for (int j = 0; j < 2; j++) {
                    int nfp = g * 2 + j;
                    LDMX4(kh[j][0], kh[j][1], kh[j][2], kh[j][3],
                          kbase + nfp * 2304 + ks * 32 + lane_off);
                }
#pragma unroll
                for (int j = 0; j < 2; j++) {
                    int nf = (g * 2 + j) * 2;
                    MMA_F16(S[nf][0], S[nf][1], S[nf][2], S[nf][3],
                            Qh[ks][0], Qh[ks][1], Qh[ks][2], Qh[ks][3], kh[j][0], kh[j][1]);
                    MMA_F16(S[nf+1][0], S[nf+1][1], S[nf+1][2], S[nf+1][3],
                            Qh[ks][0], Qh[ks][1], Qh[ks][2], Qh[ks][3], kh[j][2], kh[j][3]);
                }
#pragma unroll
                for (int j = 0; j < 2; j++) {
                    int nf = (g * 2 + j) * 2;
                    MMA_F16(S[nf][0], S[nf][1], S[nf][2], S[nf][3],
                            Qlr[0], Qlr[1], Qlr[2], Qlr[3], kh[j][0], kh[j][1]);
                    MMA_F16(S[nf+1][0], S[nf+1][1], S[nf+1][2], S[nf+1][3],
                            Qlr[0], Qlr[1], Qlr[2], Qlr[3], kh[j][2], kh[j][3]);
                }
            }
        }

#pragma unroll
        for (int nf = 0; nf < 8; nf++) {
            if (!gok[nf >> 2]) continue;
            int rel0 = kc + nf * 8 + c2 - qpos0;
            int rel2 = rel0 - 8;
            S[nf][0] = (rel0     <= 0 && rel0     >= -WIN) ? fmaf(slope, (float)rel0,     S[nf][0]) : -INFINITY;
            S[nf][1] = (rel0 + 1 <= 0 && rel0 + 1 >= -WIN) ? fmaf(slope, (float)(rel0+1), S[nf][1]) : -INFINITY;
            S[nf][2] = (rel2     <= 0 && rel2     >= -WIN) ? fmaf(slope, (float)rel2,     S[nf][2]) : -INFINITY;
            S[nf][3] = (rel2 + 1 <= 0 && rel2 + 1 >= -WIN) ? fmaf(slope, (float)(rel2+1), S[nf][3]) : -INFINITY;
        }

        float mx0 = -INFINITY, mx1 = -INFINITY;
#pragma unroll
        for (int nf = 0; nf < 8; nf++) {
            if (!gok[nf >> 2]) continue;
            mx0 = fmaxf(mx0, fmaxf(S[nf][0], S[nf][1]));
            mx1 = fmaxf(mx1, fmaxf(S[nf][2], S[nf][3]));
        }
        mx0 = fmaxf(mx0, __shfl_xor_sync(0xffffffffu, mx0, 1));
        mx0 = fmaxf(mx0, __shfl_xor_sync(0xffffffffu, mx0, 2));
        mx1 = fmaxf(mx1, __shfl_xor_sync(0xffffffffu, mx1, 1));
        mx1 = fmaxf(mx1, __shfl_xor_sync(0xffffffffu, mx1, 2));

        float mn0 = fmaxf(fmaxf(m0, mx0), -1e30f);
        float mn1 = fmaxf(fmaxf(m1, mx1), -1e30f);
        float a0 = ex2(m0 - mn0);
        float a1 = ex2(m1 - mn1);
        m0 = mn0; m1 = mn1;
        l0 *= a0; l1 *= a1;
#pragma unroll
        for (int nf = 0; nf < 8; nf++) {
            O[nf][0] *= a0; O[nf][1] *= a0;
            O[nf][2] *= a1; O[nf][3] *= a1;
        }
#pragma unroll
        for (int nf = 0; nf < 8; nf++) {
            if (!gok[nf >> 2]) {
                S[nf][0] = 0.f; S[nf][1] = 0.f; S[nf][2] = 0.f; S[nf][3] = 0.f;
                continue;
            }
            S[nf][0] = ex2(S[nf][0] - m0);
            S[nf][1] = ex2(S[nf][1] - m0);
            S[nf][2] = ex2(S[nf][2] - m1);
            S[nf][3] = ex2(S[nf][3] - m1);
            l0 += S[nf][0] + S[nf][1];
            l1 += S[nf][2] + S[nf][3];
        }

#pragma unroll
        for (int ks = 0; ks < 4; ks++) {
            int kk0 = kc + ks * 16;
            if (kk0 > wqmax || kk0 + 15 < wqmin - WIN) continue;
            uint32_t ph0 = packh(S[2*ks][0],   S[2*ks][1]);
            uint32_t ph1 = packh(S[2*ks][2],   S[2*ks][3]);
            uint32_t ph2 = packh(S[2*ks+1][0], S[2*ks+1][1]);
            uint32_t ph3 = packh(S[2*ks+1][2], S[2*ks+1][3]);
#pragma unroll
            for (int g = 0; g < 2; g++) {
                uint32_t v[2][4];
#pragma unroll
                for (int j = 0; j < 2; j++) {
                    int nfp = g * 2 + j;
                    LDMX4T(v[j][0], v[j][1], v[j][2], v[j][3],
                           kbase + VOFF + ks * 2304 + nfp * 32 + lane_off);
                }
#pragma unroll
                for (int j = 0; j < 2; j++) {
                    int nf = (g * 2 + j) * 2;
                    MMA_F16(O[nf][0], O[nf][1], O[nf][2], O[nf][3],
                            ph0, ph1, ph2, ph3, v[j][0], v[j][2]);
                    MMA_F16(O[nf+1][0], O[nf+1][1], O[nf+1][2], O[nf+1][3],
                            ph0, ph1, ph2, ph3, v[j][1], v[j][3]);
                }
            }
        }
    };

    for (int w = 0; w < nwin; w++) {
        if (w < nwin - 1) cp_wait<1>(); else cp_wait<0>();
        __syncthreads();

        const uint32_t sb = smb + (w & 1) * STAGEB;
        const int kc = kc0 + w * 128;

        do_chunk(kc, sb);
        do_chunk(kc + 64, sb + TILEB);

        __syncthreads();
        if (w + 2 < nwin) load_window(kc0 + (w + 2) * 128, w & 1);
    }

    // ---- epilogue: write y as fp16 ----
    l0 += __shfl_xor_sync(0xffffffffu, l0, 1);
    l0 += __shfl_xor_sync(0xffffffffu, l0, 2);
    l1 += __shfl_xor_sync(0xffffffffu, l1, 1);
    l1 += __shfl_xor_sync(0xffffffffu, l1, 2);
    float inv0 = 1.f / l0, inv1 = 1.f / l1;

    size_t out0 = ((size_t)(b * SS + qpos0) * DIM) + head * 64;
    size_t out1 = out0 + (size_t)8 * DIM;
#pragma unroll
    for (int nf = 0; nf < 8; nf++) {
        float y0 = O[nf][0] * inv0, y1 = O[nf][1] * inv0;
        float y2 = O[nf][2] * inv1, y3 = O[nf][3] * inv1;
        int col = nf * 8 + c2;
        *(uint32_t*)(g_ah + out0 + col) = packh(y0, y1);
        *(uint32_t*)(g_ah + out1 + col) = packh(y2, y3);
    }
}

// ---------------- launch ----------------
extern "C" void kernel_launch(void* const* d_in, const int* in_sizes, int n_in,
                              void* d_out, int out_size)
{
    const float* x  = (const float*)d_in[0];
    const float* wq = (const float*)d_in[1];
    const float* wk = (const float*)d_in[2];
    const float* wv = (const float*)d_in[3];
    const float* wo = (const float*)d_in[4];
    const float* qw = (const float*)d_in[5];
    const float* kw = (const float*)d_in[6];
    float* out = (float*)d_out;

    float* xqkv = nullptr;
    __half *ah = nullptr, *wh = nullptr;
    cudaGetSymbolAddress((void**)&xqkv, g_xqkv);
    cudaGetSymbolAddress((void**)&ah, g_ah);
    cudaGetSymbolAddress((void**)&wh, g_wh);

    static bool attr_done = false;
    if (!attr_done) {
        cudaFuncSetAttribute(hmma_gemm, cudaFuncAttributeMaxDynamicSharedMemorySize, GEMM_SMEM);
        cudaFuncSetAttribute(attn_tc, cudaFuncAttributeMaxDynamicSharedMemorySize, ATT_SMEM);
        attr_done = true;
    }

    split_all<<<(1048576 + 655360) / 256, 256>>>(x, wq, wk, wv, wo);
    hmma_gemm<<<dim3(QKVW / 128, TT / 128), 256, GEMM_SMEM>>>(ah, wh, xqkv, QKVW, 0);
    prep_qkv<<<TT, 256>>>(qw, kw);
    attn_tc<<<dim3(SS / 128, NH, BB), 256, ATT_SMEM>>>();
    hmma_gemm<<<dim3(DIM / 128, TT / 128), 256, GEMM_SMEM>>>(
        ah, wh + (size_t)WO_ROW * DIM, out, DIM, 0);
}

// round 15
// speedup vs baseline: 2.3629x; 1.1308x over previous
#include <cuda_runtime.h>
#include <cuda_fp16.h>
#include <math.h>
#include <stdint.h>

#define DIM   1024
#define NH    16
#define NKV   4
#define HD    64
#define WIN   512
#define BB    2
#define SS    2048
#define TT    (BB*SS)
#define QKVW  1536   // 1024 q | 256 k | 256 v per token
#define GK    1024   // K dim of every GEMM
#define LOG2E 1.4426950408889634f

// ---------------- scratch (no allocs allowed) ----------------
__device__ float g_xqkv[(size_t)TT * QKVW];        // fp32 qkv projections
__device__ __half g_ah[(size_t)TT * DIM];          // activation fp16 (x, then attn out)
__device__ __half g_wh[(size_t)2560 * DIM];        // weights fp16: wq|wk|wv|wo
__device__ __half g_qh[(size_t)TT * DIM];          // per-head Q fp16 [(b*NH+h)*SS+s][64]
__device__ __half g_kh[(size_t)TT * 256];          // per-kvhead K fp16
__device__ __half g_vh[(size_t)TT * 256];          // per-kvhead V fp16
#define WO_ROW 1536

// ---------------- small PTX helpers ----------------
__device__ __forceinline__ uint32_t smem_u32(const void* p) {
    uint32_t a;
    asm("{ .reg .u64 t; cvta.to.shared.u64 t, %1; cvt.u32.u64 %0, t; }" : "=r"(a) : "l"(p));
    return a;
}
__device__ __forceinline__ void cp16(uint32_t s, const void* g) {
    asm volatile("{ .reg .u64 gg; cvta.to.global.u64 gg, %1; cp.async.cg.shared.global [%0], [gg], 16; }"
                 :: "r"(s), "l"(g) : "memory");
}
__device__ __forceinline__ void cp_commit() { asm volatile("cp.async.commit_group;" ::: "memory"); }
template <int N>
__device__ __forceinline__ void cp_wait() { asm volatile("cp.async.wait_group %0;" :: "n"(N) : "memory"); }

__device__ __forceinline__ uint32_t packh(float lo, float hi) {
    uint32_t r;
    asm("cvt.rn.f16x2.f32 %0, %1, %2;" : "=r"(r) : "f"(hi), "f"(lo));
    return r;
}
__device__ __forceinline__ float ex2(float x) {
    float y;
    asm("ex2.approx.ftz.f32 %0, %1;" : "=f"(y) : "f"(x));
    return y;
}

#define MMA_F16(c0,c1,c2,c3, a0,a1,a2,a3, b0,b1) \
    asm volatile("mma.sync.aligned.m16n8k16.row.col.f32.f16.f16.f32 " \
                 "{%0,%1,%2,%3}, {%4,%5,%6,%7}, {%8,%9}, {%0,%1,%2,%3};" \
                 : "+f"(c0), "+f"(c1), "+f"(c2), "+f"(c3) \
                 : "r"(a0), "r"(a1), "r"(a2), "r"(a3), "r"(b0), "r"(b1))

#define LDMX4(r0,r1,r2,r3, addr) \
    asm volatile("ldmatrix.sync.aligned.m8n8.x4.shared.b16 {%0,%1,%2,%3}, [%4];" \
                 : "=r"(r0), "=r"(r1), "=r"(r2), "=r"(r3) : "r"(addr))
#define LDMX4T(r0,r1,r2,r3, addr) \
    asm volatile("ldmatrix.sync.aligned.m8n8.x4.trans.shared.b16 {%0,%1,%2,%3}, [%4];" \
                 : "=r"(r0), "=r"(r1), "=r"(r2), "=r"(r3) : "r"(addr))

// ---------------- fused splits: x -> fp16, all weights -> fp16 ----------------
__global__ __launch_bounds__(256) void split_all(
    const float* __restrict__ x,
    const float* __restrict__ wq, const float* __restrict__ wk,
    const float* __restrict__ wv, const float* __restrict__ wo)
{
    int i = blockIdx.x * 256 + threadIdx.x;
    if (i < 1048576) {
        float4 v = ((const float4*)x)[i];
        union { __half b[4]; uint2 u; } H;
        H.b[0] = __float2half(v.x); H.b[1] = __float2half(v.y);
        H.b[2] = __float2half(v.z); H.b[3] = __float2half(v.w);
        ((uint2*)g_ah)[i] = H.u;
    } else {
        int j = i - 1048576;
        const float* src;
        int local;
        if (j < 262144)      { src = wq; local = j; }
        else if (j < 327680) { src = wk; local = j - 262144; }
        else if (j < 393216) { src = wv; local = j - 327680; }
        else                 { src = wo; local = j - 393216; }
        float4 v = ((const float4*)src)[local];
        union { __half b[4]; uint2 u; } H;
        H.b[0] = __float2half(v.x); H.b[1] = __float2half(v.y);
        H.b[2] = __float2half(v.z); H.b[3] = __float2half(v.w);
        ((uint2*)g_wh)[j] = H.u;
    }
}

// ---------------- HMMA fp16 1-pass GEMM: C = Ah*Bh, BK=64, 2-stage cp.async ----------------
#define BKC 64
#define NCHG (GK / BKC)          // 16
#define SROWG 72                 // halves per row (64 data + 8 pad -> 144B)
#define TILEG (128 * SROWG)      // halves per tile
#define STAGEG (2 * TILEG)       // Ah, Bh
#define GEMM_SMEM (2 * STAGEG * 2)   // 73728 bytes

__global__ __launch_bounds__(256, 2) void hmma_gemm(
    const __half* __restrict__ ah, const __half* __restrict__ bh,
    float* __restrict__ C, int ldc, int coff)
{
    extern __shared__ char smraw[];
    const uint32_t smb = smem_u32(smraw);

    const int tid = threadIdx.x;
    const int wid = tid >> 5;
    const int lid = tid & 31;
    const int wm = wid & 1;
    const int wn = wid >> 1;
    const int m0 = blockIdx.y * 128;
    const int n0 = blockIdx.x * 128;

    const __half* gbase[2];
    gbase[0] = ah + (size_t)m0 * GK;
    gbase[1] = bh + (size_t)n0 * GK;

    auto load_stage = [&](int kc, int stg) {
        const uint32_t base = smb + (uint32_t)stg * (STAGEG * 2);
#pragma unroll
        for (int i = 0; i < 4; i++) {
            int id = tid + 256 * i;
            int row = id >> 3, seg = id & 7;
            uint32_t soff = (uint32_t)(row * SROWG + seg * 8) * 2;
#pragma unroll
            for (int t = 0; t < 2; t++) {
                const __half* src = gbase[t] + (size_t)row * GK + kc + seg * 8;
                cp16(base + (uint32_t)t * (TILEG * 2) + soff, src);
            }
        }
        cp_commit();
    };

    float acc[4][4][4];
#pragma unroll
    for (int i = 0; i < 4; i++)
#pragma unroll
        for (int j = 0; j < 4; j++)
#pragma unroll
            for (int k = 0; k < 4; k++) acc[i][j][k] = 0.f;

    const uint32_t frag_off =
        (uint32_t)((((lid & 7) + ((lid >> 3) & 1) * 8) * SROWG + (lid >> 4) * 8) * 2);

    load_stage(0, 0);
    load_stage(BKC, 1);

    for (int c = 0; c < NCHG; c++) {
        if (c < NCHG - 1) cp_wait<1>(); else cp_wait<0>();
        __syncthreads();

        const uint32_t sbase = smb + (uint32_t)(c & 1) * (STAGEG * 2);

#pragma unroll
        for (int ks = 0; ks < 4; ks++) {
            uint32_t Ah[4][4], Bh[2][4];
#pragma unroll
            for (int mf = 0; mf < 4; mf++) {
                uint32_t aaddr = sbase +
                    (uint32_t)(((wm * 64 + mf * 16) * SROWG + ks * 16) * 2) + frag_off;
                LDMX4(Ah[mf][0], Ah[mf][1], Ah[mf][2], Ah[mf][3], aaddr);
            }
#pragma unroll
            for (int nfp = 0; nfp < 2; nfp++) {
                uint32_t baddr = sbase + (TILEG * 2) +
                    (uint32_t)(((wn * 32 + nfp * 16) * SROWG + ks * 16) * 2) + frag_off;
                LDMX4(Bh[nfp][0], Bh[nfp][1], Bh[nfp][2], Bh[nfp][3], baddr);
            }

#pragma unroll
            for (int nfp = 0; nfp < 2; nfp++)
#pragma unroll
                for (int mf = 0; mf < 4; mf++) {
                    MMA_F16(acc[mf][2*nfp][0], acc[mf][2*nfp][1], acc[mf][2*nfp][2], acc[mf][2*nfp][3],
                            Ah[mf][0], Ah[mf][1], Ah[mf][2], Ah[mf][3], Bh[nfp][0], Bh[nfp][2]);
                    MMA_F16(acc[mf][2*nfp+1][0], acc[mf][2*nfp+1][1], acc[mf][2*nfp+1][2], acc[mf][2*nfp+1][3],
                            Ah[mf][0], Ah[mf][1], Ah[mf][2], Ah[mf][3], Bh[nfp][1], Bh[nfp][3]);
                }
        }

        __syncthreads();
        if (c + 2 < NCHG) load_stage((c + 2) * BKC, c & 1);
    }

    const int r2 = lid >> 2;
    const int c2 = (lid & 3) * 2;
#pragma unroll
    for (int mf = 0; mf < 4; mf++) {
        const int row = m0 + wm * 64 + mf * 16 + r2;
#pragma unroll
        for (int nf = 0; nf < 4; nf++) {
            float* cp0 = C + (size_t)row * ldc + coff + n0 + wn * 32 + nf * 8 + c2;
            *(float2*)cp0 = make_float2(acc[mf][nf][0], acc[mf][nf][1]);
            *(float2*)(cp0 + 8 * (size_t)ldc) = make_float2(acc[mf][nf][2], acc[mf][nf][3]);
        }
    }
}

// ---------------- fused q-rms + k-rms + v, vectorized float4 ----------------
__global__ __launch_bounds__(256) void prep_qkv(
    const float* __restrict__ qw, const float* __restrict__ kw)
{
    const int t = blockIdx.x;
    const int b = t >> 11, s = t & (SS - 1);
    const float* row = g_xqkv + (size_t)t * QKVW;
    const int tid = threadIdx.x;

    float4 q4 = *(const float4*)(row + tid * 4);
    float ssq = q4.x * q4.x;
    ssq = fmaf(q4.y, q4.y, ssq);
    ssq = fmaf(q4.z, q4.z, ssq);
    ssq = fmaf(q4.w, q4.w, ssq);

    float4 kv4 = make_float4(0.f, 0.f, 0.f, 0.f);
    float ssk = 0.f;
    if (tid < 64) {
        kv4 = *(const float4*)(row + 1024 + tid * 4);
        ssk = kv4.x * kv4.x;
        ssk = fmaf(kv4.y, kv4.y, ssk);
        ssk = fmaf(kv4.z, kv4.z, ssk);
        ssk = fmaf(kv4.w, kv4.w, ssk);
    } else if (tid < 128) {
        kv4 = *(const float4*)(row + 1280 + (tid - 64) * 4);
    }

#pragma unroll
    for (int o = 16; o > 0; o >>= 1) {
        ssq += __shfl_xor_sync(0xffffffffu, ssq, o);
        ssk += __shfl_xor_sync(0xffffffffu, ssk, o);
    }

    __shared__ float redq[8], redk[8];
    __shared__ float sclq_s, sclk_s;
    if ((tid & 31) == 0) { redq[tid >> 5] = ssq; redk[tid >> 5] = ssk; }
    __syncthreads();
    if (tid == 0) {
        float tq = 0.f, tk = 0.f;
#pragma unroll
        for (int i = 0; i < 8; i++) { tq += redq[i]; tk += redk[i]; }
        sclq_s = rsqrtf(tq * (1.f / 1024.f) + 1e-6f) * (0.125f * LOG2E);
        sclk_s = rsqrtf(tk * (1.f / 256.f) + 1e-6f);
    }
    __syncthreads();
    const float sclq = sclq_s, sclk = sclk_s;

    {
        float4 qwv = *(const float4*)(qw + tid * 4);
        float v0 = q4.x * sclq * qwv.x;
        float v1 = q4.y * sclq * qwv.y;
        float v2 = q4.z * sclq * qwv.z;
        float v3 = q4.w * sclq * qwv.w;
        int idx = tid * 4;
        int head = idx >> 6, d = idx & 63;
        size_t off = ((size_t)(b * NH + head) * SS + s) * 64 + d;
        *(uint2*)(g_qh + off) = make_uint2(packh(v0, v1), packh(v2, v3));
    }

    if (tid < 64) {
        int idx = tid * 4;
        int kv = idx >> 6, d = idx & 63;
        float4 kwv = *(const float4*)(kw + idx);
        float v0 = kv4.x * sclk * kwv.x;
        float v1 = kv4.y * sclk * kwv.y;
        float v2 = kv4.z * sclk * kwv.z;
        float v3 = kv4.w * sclk * kwv.w;
        size_t off = ((size_t)(b * NKV + kv) * SS + s) * 64 + d;
        *(uint2*)(g_kh + off) = make_uint2(packh(v0, v1), packh(v2, v3));
    } else if (tid < 128) {
        int idx = (tid - 64) * 4;
        int kv = idx >> 6, d = idx & 63;
        size_t off = ((size_t)(b * NKV + kv) * SS + s) * 64 + d;
        *(uint2*)(g_vh + off) = make_uint2(packh(kv4.x, kv4.y), packh(kv4.z, kv4.w));
    }
}

// ---------------- tensor-core attention: 128-key windows, 1-pass QK & PV ----------------
#define TILEB 9216                    // 64 keys * 144B
#define VOFF  18432                   // V tile offset within stage
#define STAGEB 36864                  // bytes per stage (K 128 + V 128)
#define ATT_SMEM (2 * STAGEB)         // 73728

__global__ __launch_bounds__(256, 2) void attn_tc()
{
    extern __shared__ char asm_[];
    const uint32_t smb = smem_u32(asm_);

    const int tid = threadIdx.x;
    const int wid = tid >> 5;
    const int lid = tid & 31;
    const int qstart = blockIdx.x * 128;
    const int head = blockIdx.y;
    const int b = blockIdx.z;
    const int kvh = head >> 2;

    const int r = lid >> 2;
    const int c2 = (lid & 3) * 2;
    const int qpos0 = qstart + wid * 16 + r;
    const int wqmin = qstart + wid * 16;
    const int wqmax = wqmin + 15;
    const float slope = exp2f(-0.5f * (float)(head + 1)) * LOG2E;

    const __half* qbh = g_qh + ((size_t)(b * NH + head) * SS + qstart + wid * 16) * 64;
    uint32_t Qh[4][4];
#pragma unroll
    for (int ks = 0; ks < 4; ks++) {
        Qh[ks][0] = *(const uint32_t*)(qbh + r * 64 + ks * 16 + c2);
        Qh[ks][1] = *(const uint32_t*)(qbh + (r + 8) * 64 + ks * 16 + c2);
        Qh[ks][2] = *(const uint32_t*)(qbh + r * 64 + ks * 16 + 8 + c2);
        Qh[ks][3] = *(const uint32_t*)(qbh + (r + 8) * 64 + ks * 16 + 8 + c2);
    }

    float O[8][4];
#pragma unroll
    for (int i = 0; i < 8; i++)
#pragma unroll
        for (int j = 0; j < 4; j++) O[i][j] = 0.f;
    float m0 = -INFINITY, m1 = -INFINITY, l0 = 0.f, l1 = 0.f;

    const int kc0 = (qstart >= WIN) ? qstart - WIN : 0;
    const int nwin = (qstart + 128 - kc0) >> 7;

    const int key_ld = tid >> 2;
    const int seg = tid & 3;
    const __half* src_base[2];
    {
        size_t kvb = ((size_t)(b * NKV + kvh) * SS) * 64;
        src_base[0] = g_kh + kvb;
        src_base[1] = g_vh + kvb;
    }
    auto load_window = [&](int kc, int stg) {
        uint32_t sb = smb + stg * STAGEB + key_ld * 144 + seg * 16;
#pragma unroll
        for (int h = 0; h < 2; h++) {
#pragma unroll
            for (int t = 0; t < 2; t++) {
                const __half* src = src_base[t] + (size_t)(kc + h * 64 + key_ld) * 64 + seg * 8;
                cp16(sb + t * VOFF + h * TILEB, src);
                cp16(sb + t * VOFF + h * TILEB + 64, src + 32);
            }
        }
        cp_commit();
    };

    load_window(kc0, 0);
    if (nwin > 1) load_window(kc0 + 128, 1);

    const uint32_t lane_off = (uint32_t)(((lid >> 4) * 8 + (lid & 7)) * 144 + ((lid >> 3) & 1) * 16);

    auto do_chunk = [&](int kc, uint32_t kbase) {
        const bool active = (kc <= wqmax) && (kc + 63 >= wqmin - WIN);
        if (!active) return;

        bool gok[2];
#pragma unroll
        for (int g = 0; g < 2; g++) {
            int gk0 = kc + g * 32;
            gok[g] = (gk0 <= wqmax) && (gk0 + 31 >= wqmin - WIN);
        }

        float S[8][4];
#pragma unroll
        for (int i = 0; i < 8; i++)
#pragma unroll
            for (int j = 0; j < 4; j++) S[i][j] = 0.f;

#pragma unroll
        for (int ks = 0; ks < 4; ks++) {
#pragma unroll
            for (int g = 0; g < 2; g++) {
                if (!gok[g]) continue;
                uint32_t kh[2][4];
#pragma unroll
                for (int j = 0; j < 2; j++) {
                    int nfp = g * 2 + j;
                    LDMX4(kh[j][0], kh[j][1], kh[j][2], kh[j][3],
                          kbase + nfp * 2304 + ks * 32 + lane_off);
                }
#pragma unroll
                for (int j = 0; j < 2; j++) {
                    int nf = (g * 2 + j) * 2;
                    MMA_F16(S[nf][0], S[nf][1], S[nf][2], S[nf][3],
                            Qh[ks][0], Qh[ks][1], Qh[ks][2], Qh[ks][3], kh[j][0], kh[j][1]);
                    MMA_F16(S[nf+1][0], S[nf+1][1], S[nf+1][2], S[nf+1][3],
                            Qh[ks][0], Qh[ks][1], Qh[ks][2], Qh[ks][3], kh[j][2], kh[j][3]);
                }
            }
        }

#pragma unroll
        for (int nf = 0; nf < 8; nf++) {
            if (!gok[nf >> 2]) continue;
            int rel0 = kc + nf * 8 + c2 - qpos0;
            int rel2 = rel0 - 8;
            S[nf][0] = (rel0     <= 0 && rel0     >= -WIN) ? fmaf(slope, (float)rel0,     S[nf][0]) : -INFINITY;
            S[nf][1] = (rel0 + 1 <= 0 && rel0 + 1 >= -WIN) ? fmaf(slope, (float)(rel0+1), S[nf][1]) : -INFINITY;
            S[nf][2] = (rel2     <= 0 && rel2     >= -WIN) ? fmaf(slope, (float)rel2,     S[nf][2]) : -INFINITY;
            S[nf][3] = (rel2 + 1 <= 0 && rel2 + 1 >= -WIN) ? fmaf(slope, (float)(rel2+1), S[nf][3]) : -INFINITY;
        }

        float mx0 = -INFINITY, mx1 = -INFINITY;
#pragma unroll
        for (int nf = 0; nf < 8; nf++) {
            if (!gok[nf >> 2]) continue;
            mx0 = fmaxf(mx0, fmaxf(S[nf][0], S[nf][1]));
            mx1 = fmaxf(mx1, fmaxf(S[nf][2], S[nf][3]));
        }
        mx0 = fmaxf(mx0, __shfl_xor_sync(0xffffffffu, mx0, 1));
        mx0 = fmaxf(mx0, __shfl_xor_sync(0xffffffffu, mx0, 2));
        mx1 = fmaxf(mx1, __shfl_xor_sync(0xffffffffu, mx1, 1));
        mx1 = fmaxf(mx1, __shfl_xor_sync(0xffffffffu, mx1, 2));

        float mn0 = fmaxf(fmaxf(m0, mx0), -1e30f);
        float mn1 = fmaxf(fmaxf(m1, mx1), -1e30f);
        float a0 = ex2(m0 - mn0);
        float a1 = ex2(m1 - mn1);
        m0 = mn0; m1 = mn1;
        l0 *= a0; l1 *= a1;
#pragma unroll
        for (int nf = 0; nf < 8; nf++) {
            O[nf][0] *= a0; O[nf][1] *= a0;
            O[nf][2] *= a1; O[nf][3] *= a1;
        }
#pragma unroll
        for (int nf = 0; nf < 8; nf++) {
            if (!gok[nf >> 2]) {
                S[nf][0] = 0.f; S[nf][1] = 0.f; S[nf][2] = 0.f; S[nf][3] = 0.f;
                continue;
            }
            S[nf][0] = ex2(S[nf][0] - m0);
            S[nf][1] = ex2(S[nf][1] - m0);
            S[nf][2] = ex2(S[nf][2] - m1);
            S[nf][3] = ex2(S[nf][3] - m1);
            l0 += S[nf][0] + S[nf][1];
            l1 += S[nf][2] + S[nf][3];
        }

#pragma unroll
        for (int ks = 0; ks < 4; ks++) {
            int kk0 = kc + ks * 16;
            if (kk0 > wqmax || kk0 + 15 < wqmin - WIN) continue;
            uint32_t ph0 = packh(S[2*ks][0],   S[2*ks][1]);
            uint32_t ph1 = packh(S[2*ks][2],   S[2*ks][3]);
            uint32_t ph2 = packh(S[2*ks+1][0], S[2*ks+1][1]);
            uint32_t ph3 = packh(S[2*ks+1][2], S[2*ks+1][3]);
#pragma unroll
            for (int g = 0; g < 2; g++) {
                uint32_t v[2][4];
#pragma unroll
                for (int j = 0; j < 2; j++) {
                    int nfp = g * 2 + j;
                    LDMX4T(v[j][0], v[j][1], v[j][2], v[j][3],
                           kbase + VOFF + ks * 2304 + nfp * 32 + lane_off);
                }
#pragma unroll
                for (int j = 0; j < 2; j++) {
                    int nf = (g * 2 + j) * 2;
                    MMA_F16(O[nf][0], O[nf][1], O[nf][2], O[nf][3],
                            ph0, ph1, ph2, ph3, v[j][0], v[j][2]);
                    MMA_F16(O[nf+1][0], O[nf+1][1], O[nf+1][2], O[nf+1][3],
                            ph0, ph1, ph2, ph3, v[j][1], v[j][3]);
                }
            }
        }
    };

    for (int w = 0; w < nwin; w++) {
        if (w < nwin - 1) cp_wait<1>(); else cp_wait<0>();
        __syncthreads();

        const uint32_t sb = smb + (w & 1) * STAGEB;
        const int kc = kc0 + w * 128;

        do_chunk(kc, sb);
        do_chunk(kc + 64, sb + TILEB);

        __syncthreads();
        if (w + 2 < nwin) load_window(kc0 + (w + 2) * 128, w & 1);
    }

    // ---- epilogue: write y as fp16 ----
    l0 += __shfl_xor_sync(0xffffffffu, l0, 1);
    l0 += __shfl_xor_sync(0xffffffffu, l0, 2);
    l1 += __shfl_xor_sync(0xffffffffu, l1, 1);
    l1 += __shfl_xor_sync(0xffffffffu, l1, 2);
    float inv0 = 1.f / l0, inv1 = 1.f / l1;

    size_t out0 = ((size_t)(b * SS + qpos0) * DIM) + head * 64;
    size_t out1 = out0 + (size_t)8 * DIM;
#pragma unroll
    for (int nf = 0; nf < 8; nf++) {
        float y0 = O[nf][0] * inv0, y1 = O[nf][1] * inv0;
        float y2 = O[nf][2] * inv1, y3 = O[nf][3] * inv1;
        int col = nf * 8 + c2;
        *(uint32_t*)(g_ah + out0 + col) = packh(y0, y1);
        *(uint32_t*)(g_ah + out1 + col) = packh(y2, y3);
    }
}

// ---------------- launch ----------------
extern "C" void kernel_launch(void* const* d_in, const int* in_sizes, int n_in,
                              void* d_out, int out_size)
{
    const float* x  = (const float*)d_in[0];
    const float* wq = (const float*)d_in[1];
    const float* wk = (const float*)d_in[2];
    const float* wv = (const float*)d_in[3];
    const float* wo = (const float*)d_in[4];
    const float* qw = (const float*)d_in[5];
    const float* kw = (const float*)d_in[6];
    float* out = (float*)d_out;

    float* xqkv = nullptr;
    __half *ah = nullptr, *wh = nullptr;
    cudaGetSymbolAddress((void**)&xqkv, g_xqkv);
    cudaGetSymbolAddress((void**)&ah, g_ah);
    cudaGetSymbolAddress((void**)&wh, g_wh);

    static bool attr_done = false;
    if (!attr_done) {
        cudaFuncSetAttribute(hmma_gemm, cudaFuncAttributeMaxDynamicSharedMemorySize, GEMM_SMEM);
        cudaFuncSetAttribute(attn_tc, cudaFuncAttributeMaxDynamicSharedMemorySize, ATT_SMEM);
        attr_done = true;
    }

    split_all<<<(1048576 + 655360) / 256, 256>>>(x, wq, wk, wv, wo);
    hmma_gemm<<<dim3(QKVW / 128, TT / 128), 256, GEMM_SMEM>>>(ah, wh, xqkv, QKVW, 0);
    prep_qkv<<<TT, 256>>>(qw, kw);
    attn_tc<<<dim3(SS / 128, NH, BB), 256, ATT_SMEM>>>();
    hmma_gemm<<<dim3(DIM / 128, TT / 128), 256, GEMM_SMEM>>>(
        ah, wh + (size_t)WO_ROW * DIM, out, DIM, 0);
}

// round 16
// speedup vs baseline: 2.4912x; 1.0543x over previous
#include <cuda_runtime.h>
#include <cuda_fp16.h>
#include <math.h>
#include <stdint.h>

#define DIM   1024
#define NH    16
#define NKV   4
#define HD    64
#define WIN   512
#define BB    2
#define SS    2048
#define TT    (BB*SS)
#define QKVW  1536   // 1024 q | 256 k | 256 v per token
#define GK    1024   // K dim of every GEMM
#define LOG2E 1.4426950408889634f

// ---------------- scratch (no allocs allowed) ----------------
__device__ __half g_qkvh[(size_t)TT * QKVW];       // fp16 qkv projections
__device__ __half g_ah[(size_t)TT * DIM];          // activation fp16 (x, then attn out)
__device__ __half g_wh[(size_t)2560 * DIM];        // weights fp16: wq|wk|wv|wo
__device__ __half g_qh[(size_t)TT * DIM];          // per-head Q fp16 [(b*NH+h)*SS+s][64]
__device__ __half g_kh[(size_t)TT * 256];          // per-kvhead K fp16
__device__ __half g_vh[(size_t)TT * 256];          // per-kvhead V fp16
#define WO_ROW 1536

// ---------------- small PTX helpers ----------------
__device__ __forceinline__ uint32_t smem_u32(const void* p) {
    uint32_t a;
    asm("{ .reg .u64 t; cvta.to.shared.u64 t, %1; cvt.u32.u64 %0, t; }" : "=r"(a) : "l"(p));
    return a;
}
__device__ __forceinline__ void cp16(uint32_t s, const void* g) {
    asm volatile("{ .reg .u64 gg; cvta.to.global.u64 gg, %1; cp.async.cg.shared.global [%0], [gg], 16; }"
                 :: "r"(s), "l"(g) : "memory");
}
__device__ __forceinline__ void cp_commit() { asm volatile("cp.async.commit_group;" ::: "memory"); }
template <int N>
__device__ __forceinline__ void cp_wait() { asm volatile("cp.async.wait_group %0;" :: "n"(N) : "memory"); }

__device__ __forceinline__ uint32_t packh(float lo, float hi) {
    uint32_t r;
    asm("cvt.rn.f16x2.f32 %0, %1, %2;" : "=r"(r) : "f"(hi), "f"(lo));
    return r;
}
__device__ __forceinline__ float ex2(float x) {
    float y;
    asm("ex2.approx.ftz.f32 %0, %1;" : "=f"(y) : "f"(x));
    return y;
}

#define MMA_F16(c0,c1,c2,c3, a0,a1,a2,a3, b0,b1) \
    asm volatile("mma.sync.aligned.m16n8k16.row.col.f32.f16.f16.f32 " \
                 "{%0,%1,%2,%3}, {%4,%5,%6,%7}, {%8,%9}, {%0,%1,%2,%3};" \
                 : "+f"(c0), "+f"(c1), "+f"(c2), "+f"(c3) \
                 : "r"(a0), "r"(a1), "r"(a2), "r"(a3), "r"(b0), "r"(b1))

#define LDMX4(r0,r1,r2,r3, addr) \
    asm volatile("ldmatrix.sync.aligned.m8n8.x4.shared.b16 {%0,%1,%2,%3}, [%4];" \
                 : "=r"(r0), "=r"(r1), "=r"(r2), "=r"(r3) : "r"(addr))
#define LDMX4T(r0,r1,r2,r3, addr) \
    asm volatile("ldmatrix.sync.aligned.m8n8.x4.trans.shared.b16 {%0,%1,%2,%3}, [%4];" \
                 : "=r"(r0), "=r"(r1), "=r"(r2), "=r"(r3) : "r"(addr))

// ---------------- fused splits: x -> fp16, all weights -> fp16 ----------------
__global__ __launch_bounds__(256) void split_all(
    const float* __restrict__ x,
    const float* __restrict__ wq, const float* __restrict__ wk,
    const float* __restrict__ wv, const float* __restrict__ wo)
{
    int i = blockIdx.x * 256 + threadIdx.x;
    if (i < 1048576) {
        float4 v = ((const float4*)x)[i];
        union { __half b[4]; uint2 u; } H;
        H.b[0] = __float2half(v.x); H.b[1] = __float2half(v.y);
        H.b[2] = __float2half(v.z); H.b[3] = __float2half(v.w);
        ((uint2*)g_ah)[i] = H.u;
    } else {
        int j = i - 1048576;
        const float* src;
        int local;
        if (j < 262144)      { src = wq; local = j; }
        else if (j < 327680) { src = wk; local = j - 262144; }
        else if (j < 393216) { src = wv; local = j - 327680; }
        else                 { src = wo; local = j - 393216; }
        float4 v = ((const float4*)src)[local];
        union { __half b[4]; uint2 u; } H;
        H.b[0] = __float2half(v.x); H.b[1] = __float2half(v.y);
        H.b[2] = __float2half(v.z); H.b[3] = __float2half(v.w);
        ((uint2*)g_wh)[j] = H.u;
    }
}

// ---------------- HMMA fp16 1-pass GEMM: C = Ah*Bh, BK=64, 2-stage cp.async ----------------
// out_half=1: write fp16 (QKV). out_half=0: write fp32 (O-projection -> harness out).
#define BKC 64
#define NCHG (GK / BKC)          // 16
#define SROWG 72                 // halves per row (64 data + 8 pad -> 144B)
#define TILEG (128 * SROWG)      // halves per tile
#define STAGEG (2 * TILEG)       // Ah, Bh
#define GEMM_SMEM (2 * STAGEG * 2)   // 73728 bytes

__global__ __launch_bounds__(256, 2) void hmma_gemm(
    const __half* __restrict__ ah, const __half* __restrict__ bh,
    void* __restrict__ Cout, int ldc, int coff, int out_half)
{
    extern __shared__ char smraw[];
    const uint32_t smb = smem_u32(smraw);

    const int tid = threadIdx.x;
    const int wid = tid >> 5;
    const int lid = tid & 31;
    const int wm = wid & 1;
    const int wn = wid >> 1;
    const int m0 = blockIdx.y * 128;
    const int n0 = blockIdx.x * 128;

    const __half* gbase[2];
    gbase[0] = ah + (size_t)m0 * GK;
    gbase[1] = bh + (size_t)n0 * GK;

    auto load_stage = [&](int kc, int stg) {
        const uint32_t base = smb + (uint32_t)stg * (STAGEG * 2);
#pragma unroll
        for (int i = 0; i < 4; i++) {
            int id = tid + 256 * i;
            int row = id >> 3, seg = id & 7;
            uint32_t soff = (uint32_t)(row * SROWG + seg * 8) * 2;
#pragma unroll
            for (int t = 0; t < 2; t++) {
                const __half* src = gbase[t] + (size_t)row * GK + kc + seg * 8;
                cp16(base + (uint32_t)t * (TILEG * 2) + soff, src);
            }
        }
        cp_commit();
    };

    float acc[4][4][4];
#pragma unroll
    for (int i = 0; i < 4; i++)
#pragma unroll
        for (int j = 0; j < 4; j++)
#pragma unroll
            for (int k = 0; k < 4; k++) acc[i][j][k] = 0.f;

    const uint32_t frag_off =
        (uint32_t)((((lid & 7) + ((lid >> 3) & 1) * 8) * SROWG + (lid >> 4) * 8) * 2);

    load_stage(0, 0);
    load_stage(BKC, 1);

    for (int c = 0; c < NCHG; c++) {
        if (c < NCHG - 1) cp_wait<1>(); else cp_wait<0>();
        __syncthreads();

        const uint32_t sbase = smb + (uint32_t)(c & 1) * (STAGEG * 2);

#pragma unroll
        for (int ks = 0; ks < 4; ks++) {
            uint32_t Ah[4][4], Bh[2][4];
#pragma unroll
            for (int mf = 0; mf < 4; mf++) {
                uint32_t aaddr = sbase +
                    (uint32_t)(((wm * 64 + mf * 16) * SROWG + ks * 16) * 2) + frag_off;
                LDMX4(Ah[mf][0], Ah[mf][1], Ah[mf][2], Ah[mf][3], aaddr);
            }
#pragma unroll
            for (int nfp = 0; nfp < 2; nfp++) {
                uint32_t baddr = sbase + (TILEG * 2) +
                    (uint32_t)(((wn * 32 + nfp * 16) * SROWG + ks * 16) * 2) + frag_off;
                LDMX4(Bh[nfp][0], Bh[nfp][1], Bh[nfp][2], Bh[nfp][3], baddr);
            }

#pragma unroll
            for (int nfp = 0; nfp < 2; nfp++)
#pragma unroll
                for (int mf = 0; mf < 4; mf++) {
                    MMA_F16(acc[mf][2*nfp][0], acc[mf][2*nfp][1], acc[mf][2*nfp][2], acc[mf][2*nfp][3],
                            Ah[mf][0], Ah[mf][1], Ah[mf][2], Ah[mf][3], Bh[nfp][0], Bh[nfp][2]);
                    MMA_F16(acc[mf][2*nfp+1][0], acc[mf][2*nfp+1][1], acc[mf][2*nfp+1][2], acc[mf][2*nfp+1][3],
                            Ah[mf][0], Ah[mf][1], Ah[mf][2], Ah[mf][3], Bh[nfp][1], Bh[nfp][3]);
                }
        }

        __syncthreads();
        if (c + 2 < NCHG) load_stage((c + 2) * BKC, c & 1);
    }

    const int r2 = lid >> 2;
    const int c2 = (lid & 3) * 2;
    if (out_half) {
        __half* C = (__half*)Cout;
#pragma unroll
        for (int mf = 0; mf < 4; mf++) {
            const int row = m0 + wm * 64 + mf * 16 + r2;
#pragma unroll
            for (int nf = 0; nf < 4; nf++) {
                __half* cp0 = C + (size_t)row * ldc + coff + n0 + wn * 32 + nf * 8 + c2;
                *(uint32_t*)cp0 = packh(acc[mf][nf][0], acc[mf][nf][1]);
                *(uint32_t*)(cp0 + 8 * (size_t)ldc) = packh(acc[mf][nf][2], acc[mf][nf][3]);
            }
        }
    } else {
        float* C = (float*)Cout;
#pragma unroll
        for (int mf = 0; mf < 4; mf++) {
            const int row = m0 + wm * 64 + mf * 16 + r2;
#pragma unroll
            for (int nf = 0; nf < 4; nf++) {
                float* cp0 = C + (size_t)row * ldc + coff + n0 + wn * 32 + nf * 8 + c2;
                *(float2*)cp0 = make_float2(acc[mf][nf][0], acc[mf][nf][1]);
                *(float2*)(cp0 + 8 * (size_t)ldc) = make_float2(acc[mf][nf][2], acc[mf][nf][3]);
            }
        }
    }
}

// ---------------- fused q-rms + k-rms + v relayout (fp16 input) ----------------
__global__ __launch_bounds__(256) void prep_qkv(
    const float* __restrict__ qw, const float* __restrict__ kw)
{
    const int t = blockIdx.x;
    const int b = t >> 11, s = t & (SS - 1);
    const __half* row = g_qkvh + (size_t)t * QKVW;
    const int tid = threadIdx.x;

    // q: 4 halves per thread
    uint2 qu = *(const uint2*)(row + tid * 4);
    __half2 qh01 = *(__half2*)&qu.x;
    __half2 qh23 = *(__half2*)&qu.y;
    float2 q01 = __half22float2(qh01);
    float2 q23 = __half22float2(qh23);
    float ssq = q01.x * q01.x;
    ssq = fmaf(q01.y, q01.y, ssq);
    ssq = fmaf(q23.x, q23.x, ssq);
    ssq = fmaf(q23.y, q23.y, ssq);

    float2 k01 = make_float2(0.f, 0.f), k23 = make_float2(0.f, 0.f);
    uint2 vu = make_uint2(0u, 0u);
    float ssk = 0.f;
    if (tid < 64) {
        uint2 ku = *(const uint2*)(row + 1024 + tid * 4);
        k01 = __half22float2(*(__half2*)&ku.x);
        k23 = __half22float2(*(__half2*)&ku.y);
        ssk = k01.x * k01.x;
        ssk = fmaf(k01.y, k01.y, ssk);
        ssk = fmaf(k23.x, k23.x, ssk);
        ssk = fmaf(k23.y, k23.y, ssk);
    } else if (tid < 128) {
        vu = *(const uint2*)(row + 1280 + (tid - 64) * 4);
    }

#pragma unroll
    for (int o = 16; o > 0; o >>= 1) {
        ssq += __shfl_xor_sync(0xffffffffu, ssq, o);
        ssk += __shfl_xor_sync(0xffffffffu, ssk, o);
    }

    __shared__ float redq[8], redk[8];
    __shared__ float sclq_s, sclk_s;
    if ((tid & 31) == 0) { redq[tid >> 5] = ssq; redk[tid >> 5] = ssk; }
    __syncthreads();
    if (tid == 0) {
        float tq = 0.f, tk = 0.f;
#pragma unroll
        for (int i = 0; i < 8; i++) { tq += redq[i]; tk += redk[i]; }
        sclq_s = rsqrtf(tq * (1.f / 1024.f) + 1e-6f) * (0.125f * LOG2E);
        sclk_s = rsqrtf(tk * (1.f / 256.f) + 1e-6f);
    }
    __syncthreads();
    const float sclq = sclq_s, sclk = sclk_s;

    {
        float4 qwv = *(const float4*)(qw + tid * 4);
        float v0 = q01.x * sclq * qwv.x;
        float v1 = q01.y * sclq * qwv.y;
        float v2 = q23.x * sclq * qwv.z;
        float v3 = q23.y * sclq * qwv.w;
        int idx = tid * 4;
        int head = idx >> 6, d = idx & 63;
        size_t off = ((size_t)(b * NH + head) * SS + s) * 64 + d;
        *(uint2*)(g_qh + off) = make_uint2(packh(v0, v1), packh(v2, v3));
    }

    if (tid < 64) {
        int idx = tid * 4;
        int kv = idx >> 6, d = idx & 63;
        float4 kwv = *(const float4*)(kw + idx);
        float v0 = k01.x * sclk * kwv.x;
        float v1 = k01.y * sclk * kwv.y;
        float v2 = k23.x * sclk * kwv.z;
        float v3 = k23.y * sclk * kwv.w;
        size_t off = ((size_t)(b * NKV + kv) * SS + s) * 64 + d;
        *(uint2*)(g_kh + off) = make_uint2(packh(v0, v1), packh(v2, v3));
    } else if (tid < 128) {
        int idx = (tid - 64) * 4;
        int kv = idx >> 6, d = idx & 63;
        size_t off = ((size_t)(b * NKV + kv) * SS + s) * 64 + d;
        *(uint2*)(g_vh + off) = vu;   // already fp16, pure relayout
    }
}

// ---------------- tensor-core attention: 128-key windows, interior fast path ----------------
#define TILEB 9216
#define VOFF  18432
#define STAGEB 36864
#define ATT_SMEM (2 * STAGEB)

__global__ __launch_bounds__(256, 2) void attn_tc()
{
    extern __shared__ char asm_[];
    const uint32_t smb = smem_u32(asm_);

    const int tid = threadIdx.x;
    const int wid = tid >> 5;
    const int lid = tid & 31;
    const int qstart = blockIdx.x * 128;
    const int head = blockIdx.y;
    const int b = blockIdx.z;
    const int kvh = head >> 2;

    const int r = lid >> 2;
    const int c2 = (lid & 3) * 2;
    const int qpos0 = qstart + wid * 16 + r;
    const int wqmin = qstart + wid * 16;
    const int wqmax = wqmin + 15;
    const float slope = exp2f(-0.5f * (float)(head + 1)) * LOG2E;

    const __half* qbh = g_qh + ((size_t)(b * NH + head) * SS + qstart + wid * 16) * 64;
    uint32_t Qh[4][4];
#pragma unroll
    for (int ks = 0; ks < 4; ks++) {
        Qh[ks][0] = *(const uint32_t*)(qbh + r * 64 + ks * 16 + c2);
        Qh[ks][1] = *(const uint32_t*)(qbh + (r + 8) * 64 + ks * 16 + c2);
        Qh[ks][2] = *(const uint32_t*)(qbh + r * 64 + ks * 16 + 8 + c2);
        Qh[ks][3] = *(const uint32_t*)(qbh + (r + 8) * 64 + ks * 16 + 8 + c2);
    }

    float O[8][4];
#pragma unroll
    for (int i = 0; i < 8; i++)
#pragma unroll
        for (int j = 0; j < 4; j++) O[i][j] = 0.f;
    float m0 = -INFINITY, m1 = -INFINITY, l0 = 0.f, l1 = 0.f;

    const int kc0 = (qstart >= WIN) ? qstart - WIN : 0;
    const int nwin = (qstart + 128 - kc0) >> 7;

    const int key_ld = tid >> 2;
    const int seg = tid & 3;
    const __half* src_base[2];
    {
        size_t kvb = ((size_t)(b * NKV + kvh) * SS) * 64;
        src_base[0] = g_kh + kvb;
        src_base[1] = g_vh + kvb;
    }
    auto load_window = [&](int kc, int stg) {
        uint32_t sb = smb + stg * STAGEB + key_ld * 144 + seg * 16;
#pragma unroll
        for (int h = 0; h < 2; h++) {
#pragma unroll
            for (int t = 0; t < 2; t++) {
                const __half* src = src_base[t] + (size_t)(kc + h * 64 + key_ld) * 64 + seg * 8;
                cp16(sb + t * VOFF + h * TILEB, src);
                cp16(sb + t * VOFF + h * TILEB + 64, src + 32);
            }
        }
        cp_commit();
    };

    load_window(kc0, 0);
    if (nwin > 1) load_window(kc0 + 128, 1);

    const uint32_t lane_off = (uint32_t)(((lid >> 4) * 8 + (lid & 7)) * 144 + ((lid >> 3) & 1) * 16);

    auto do_chunk = [&](int kc, uint32_t kbase) {
        const bool active = (kc <= wqmax) && (kc + 63 >= wqmin - WIN);
        if (!active) return;
        // interior: every (q,k) pair in this warp-chunk is unmasked
        const bool interior = (kc + 63 <= wqmin) && (kc >= wqmax - WIN);

        bool gok[2];
#pragma unroll
        for (int g = 0; g < 2; g++) {
            int gk0 = kc + g * 32;
            gok[g] = interior || ((gk0 <= wqmax) && (gk0 + 31 >= wqmin - WIN));
        }

        float S[8][4];
#pragma unroll
        for (int i = 0; i < 8; i++)
#pragma unroll
            for (int j = 0; j < 4; j++) S[i][j] = 0.f;

#pragma unroll
        for (int ks = 0; ks < 4; ks++) {
#pragma unroll
            for (int g = 0; g < 2; g++) {
                if (!gok[g]) continue;
                uint32_t kh[2][4];
#pragma unroll
                for (int j = 0; j < 2; j++) {
                    int nfp = g * 2 + j;
                    LDMX4(kh[j][0], kh[j][1], kh[j][2], kh[j][3],
                          kbase + nfp * 2304 + ks * 32 + lane_off);
                }
#pragma unroll
                for (int j = 0; j < 2; j++) {
                    int nf = (g * 2 + j) * 2;
                    MMA_F16(S[nf][0], S[nf][1], S[nf][2], S[nf][3],
                            Qh[ks][0], Qh[ks][1], Qh[ks][2], Qh[ks][3], kh[j][0], kh[j][1]);
                    MMA_F16(S[nf+1][0], S[nf+1][1], S[nf+1][2], S[nf+1][3],
                            Qh[ks][0], Qh[ks][1], Qh[ks][2], Qh[ks][3], kh[j][2], kh[j][3]);
                }
            }
        }

        if (interior) {
            // no masking needed: bias only
#pragma unroll
            for (int nf = 0; nf < 8; nf++) {
                float rel0 = (float)(kc + nf * 8 + c2 - qpos0);
                S[nf][0] = fmaf(slope, rel0,       S[nf][0]);
                S[nf][1] = fmaf(slope, rel0 + 1.f, S[nf][1]);
                S[nf][2] = fmaf(slope, rel0 - 8.f, S[nf][2]);
                S[nf][3] = fmaf(slope, rel0 - 7.f, S[nf][3]);
            }
        } else {
#pragma unroll
            for (int nf = 0; nf < 8; nf++) {
                if (!gok[nf >> 2]) continue;
                int rel0 = kc + nf * 8 + c2 - qpos0;
                int rel2 = rel0 - 8;
                S[nf][0] = (rel0     <= 0 && rel0     >= -WIN) ? fmaf(slope, (float)rel0,     S[nf][0]) : -INFINITY;
                S[nf][1] = (rel0 + 1 <= 0 && rel0 + 1 >= -WIN) ? fmaf(slope, (float)(rel0+1), S[nf][1]) : -INFINITY;
                S[nf][2] = (rel2     <= 0 && rel2     >= -WIN) ? fmaf(slope, (float)rel2,     S[nf][2]) : -INFINITY;
                S[nf][3] = (rel2 + 1 <= 0 && rel2 + 1 >= -WIN) ? fmaf(slope, (float)(rel2+1), S[nf][3]) : -INFINITY;
            }
        }

        float mx0 = -INFINITY, mx1 = -INFINITY;
#pragma unroll
        for (int nf = 0; nf < 8; nf++) {
            if (!gok[nf >> 2]) continue;
            mx0 = fmaxf(mx0, fmaxf(S[nf][0], S[nf][1]));
            mx1 = fmaxf(mx1, fmaxf(S[nf][2], S[nf][3]));
        }
        mx0 = fmaxf(mx0, __shfl_xor_sync(0xffffffffu, mx0, 1));
        mx0 = fmaxf(mx0, __shfl_xor_sync(0xffffffffu, mx0, 2));
        mx1 = fmaxf(mx1, __shfl_xor_sync(0xffffffffu, mx1, 1));
        mx1 = fmaxf(mx1, __shfl_xor_sync(0xffffffffu, mx1, 2));

        float mn0 = fmaxf(fmaxf(m0, mx0), -1e30f);
        float mn1 = fmaxf(fmaxf(m1, mx1), -1e30f);
        float a0 = ex2(m0 - mn0);
        float a1 = ex2(m1 - mn1);
        m0 = mn0; m1 = mn1;
        l0 *= a0; l1 *= a1;
#pragma unroll
        for (int nf = 0; nf < 8; nf++) {
            O[nf][0] *= a0; O[nf][1] *= a0;
            O[nf][2] *= a1; O[nf][3] *= a1;
        }
        if (interior) {
#pragma unroll
            for (int nf = 0; nf < 8; nf++) {
                S[nf][0] = ex2(S[nf][0] - m0);
                S[nf][1] = ex2(S[nf][1] - m0);
                S[nf][2] = ex2(S[nf][2] - m1);
                S[nf][3] = ex2(S[nf][3] - m1);
                l0 += S[nf][0] + S[nf][1];
                l1 += S[nf][2] + S[nf][3];
            }
        } else {
#pragma unroll
            for (int nf = 0; nf < 8; nf++) {
                if (!gok[nf >> 2]) {
                    S[nf][0] = 0.f; S[nf][1] = 0.f; S[nf][2] = 0.f; S[nf][3] = 0.f;
                    continue;
                }
                S[nf][0] = ex2(S[nf][0] - m0);
                S[nf][1] = ex2(S[nf][1] - m0);
                S[nf][2] = ex2(S[nf][2] - m1);
                S[nf][3] = ex2(S[nf][3] - m1);
                l0 += S[nf][0] + S[nf][1];
                l1 += S[nf][2] + S[nf][3];
            }
        }

#pragma unroll
        for (int ks = 0; ks < 4; ks++) {
            int kk0 = kc + ks * 16;
            if (!interior && (kk0 > wqmax || kk0 + 15 < wqmin - WIN)) continue;
            uint32_t ph0 = packh(S[2*ks][0],   S[2*ks][1]);
            uint32_t ph1 = packh(S[2*ks][2],   S[2*ks][3]);
            uint32_t ph2 = packh(S[2*ks+1][0], S[2*ks+1][1]);
            uint32_t ph3 = packh(S[2*ks+1][2], S[2*ks+1][3]);
#pragma unroll
            for (int g = 0; g < 2; g++) {
                uint32_t v[2][4];
#pragma unroll
                for (int j = 0; j < 2; j++) {
                    int nfp = g * 2 + j;
                    LDMX4T(v[j][0], v[j][1], v[j][2], v[j][3],
                           kbase + VOFF + ks * 2304 + nfp * 32 + lane_off);
                }
#pragma unroll
                for (int j = 0; j < 2; j++) {
                    int nf = (g * 2 + j) * 2;
                    MMA_F16(O[nf][0], O[nf][1], O[nf][2], O[nf][3],
                            ph0, ph1, ph2, ph3, v[j][0], v[j][2]);
                    MMA_F16(O[nf+1][0], O[nf+1][1], O[nf+1][2], O[nf+1][3],
                            ph0, ph1, ph2, ph3, v[j][1], v[j][3]);
                }
            }
        }
    };

    for (int w = 0; w < nwin; w++) {
        if (w < nwin - 1) cp_wait<1>(); else cp_wait<0>();
        __syncthreads();

        const uint32_t sb = smb + (w & 1) * STAGEB;
        const int kc = kc0 + w * 128;

        do_chunk(kc, sb);
        do_chunk(kc + 64, sb + TILEB);

        __syncthreads();
        if (w + 2 < nwin) load_window(kc0 + (w + 2) * 128, w & 1);
    }

    // ---- epilogue ----
    l0 += __shfl_xor_sync(0xffffffffu, l0, 1);
    l0 += __shfl_xor_sync(0xffffffffu, l0, 2);
    l1 += __shfl_xor_sync(0xffffffffu, l1, 1);
    l1 += __shfl_xor_sync(0xffffffffu, l1, 2);
    float inv0 = 1.f / l0, inv1 = 1.f / l1;

    size_t out0 = ((size_t)(b * SS + qpos0) * DIM) + head * 64;
    size_t out1 = out0 + (size_t)8 * DIM;
#pragma unroll
    for (int nf = 0; nf < 8; nf++) {
        float y0 = O[nf][0] * inv0, y1 = O[nf][1] * inv0;
        float y2 = O[nf][2] * inv1, y3 = O[nf][3] * inv1;
        int col = nf * 8 + c2;
        *(uint32_t*)(g_ah + out0 + col) = packh(y0, y1);
        *(uint32_t*)(g_ah + out1 + col) = packh(y2, y3);
    }
}

// ---------------- launch ----------------
extern "C" void kernel_launch(void* const* d_in, const int* in_sizes, int n_in,
                              void* d_out, int out_size)
{
    const float* x  = (const float*)d_in[0];
    const float* wq = (const float*)d_in[1];
    const float* wk = (const float*)d_in[2];
    const float* wv = (const float*)d_in[3];
    const float* wo = (const float*)d_in[4];
    const float* qw = (const float*)d_in[5];
    const float* kw = (const float*)d_in[6];
    float* out = (float*)d_out;

    __half *qkvh = nullptr, *ah = nullptr, *wh = nullptr;
    cudaGetSymbolAddress((void**)&qkvh, g_qkvh);
    cudaGetSymbolAddress((void**)&ah, g_ah);
    cudaGetSymbolAddress((void**)&wh, g_wh);

    static bool attr_done = false;
    if (!attr_done) {
        cudaFuncSetAttribute(hmma_gemm, cudaFuncAttributeMaxDynamicSharedMemorySize, GEMM_SMEM);
        cudaFuncSetAttribute(attn_tc, cudaFuncAttributeMaxDynamicSharedMemorySize, ATT_SMEM);
        attr_done = true;
    }

    split_all<<<(1048576 + 655360) / 256, 256>>>(x, wq, wk, wv, wo);
    hmma_gemm<<<dim3(QKVW / 128, TT / 128), 256, GEMM_SMEM>>>(ah, wh, qkvh, QKVW, 0, 1);
    prep_qkv<<<TT, 256>>>(qw, kw);
    attn_tc<<<dim3(SS / 128, NH, BB), 256, ATT_SMEM>>>();
    hmma_gemm<<<dim3(DIM / 128, TT / 128), 256, GEMM_SMEM>>>(
        ah, wh + (size_t)WO_ROW * DIM, out, DIM, 0, 0);
}